// round 1
// baseline (speedup 1.0000x reference)
#include <cuda_runtime.h>
#include <math.h>

#define B_ 8
#define S_ 1024
#define D_ 768
#define H_ 3072
#define T_ (B_*S_)   // 8192 tokens

// ---------------- scratch (static device globals; no runtime allocation) ----
static __device__ float g_pe[S_*D_];
static __device__ float g_y [T_*D_];
static __device__ float g_q [T_*H_];
static __device__ float g_k [T_*H_];
static __device__ float g_v [T_*H_];
static __device__ float g_s [B_*S_*S_];
static __device__ float g_av[T_*H_];
static __device__ float g_ao[T_*D_];
static __device__ float g_y1[T_*D_];
static __device__ float g_h1[T_*H_];
static __device__ float g_f [T_*D_];

// ---------------- positional encoding table ---------------------------------
__global__ void pe_kernel(float* __restrict__ pe) {
    int i = blockIdx.x * blockDim.x + threadIdx.x;
    if (i >= S_ * D_) return;
    int s = i / D_, d = i % D_;
    // ang = s / 10000^(d/D)  computed in double, reduced mod 2pi for accuracy
    double ang = (double)s * exp(-9.210340371976184 * ((double)d / (double)D_));
    float a = (float)fmod(ang, 6.283185307179586);
    pe[i] = (d & 1) ? cosf(a) : sinf(a);
}

// ---------------- embedding gather + PE add ---------------------------------
__global__ void embed_kernel(const int* __restrict__ x, const float* __restrict__ emb,
                             const float* __restrict__ pe, float* __restrict__ y) {
    int t = blockIdx.x;            // token 0..8191
    int s = t & (S_ - 1);
    long long row = x[t];
    const float* er = emb + row * (long long)D_;
    const float* pr = pe + (long long)s * D_;
    float* yr = y + (long long)t * D_;
    for (int d = threadIdx.x; d < D_; d += blockDim.x)
        yr[d] = er[d] + pr[d];
}

// ---------------- GEMM: C = A@B (+bias)(+gelu); optional B^T; batched -------
__device__ __forceinline__ float gelu_exact(float v) {
    return 0.5f * v * (1.0f + erff(v * 0.70710678118654752f));
}

// 128x128x8 tile, 256 threads, 8x8 per thread (4+4 split), As/Bs padded to 132
template<int TB, int BIAS, int GELU>
__global__ void __launch_bounds__(256)
sgemm(const float* __restrict__ A, const float* __restrict__ B,
      const float* __restrict__ bias, float* __restrict__ C,
      int M, int N, int K,
      long long sA, long long sB, long long sC) {
    A += (long long)blockIdx.z * sA;
    B += (long long)blockIdx.z * sB;
    C += (long long)blockIdx.z * sC;

    const int tid = threadIdx.x;
    const int bm = blockIdx.y << 7, bn = blockIdx.x << 7;

    __shared__ float As[8][132];
    __shared__ float Bs[8][132];

    const int lr = tid >> 1, lk = (tid & 1) << 2;   // A / B^T loaders
    const int kr = tid >> 5, nc = (tid & 31) << 2;  // B (NN) loaders
    const int tx = tid & 15, ty = tid >> 4;

    const float* Ap = A + (long long)(bm + lr) * K + lk;
    const float* Bp = TB ? (B + (long long)(bn + lr) * K + lk)
                         : (B + (long long)kr * N + bn + nc);

    float4 a4 = *(const float4*)Ap;
    float4 b4 = *(const float4*)Bp;

    float acc[8][8];
#pragma unroll
    for (int i = 0; i < 8; i++)
#pragma unroll
        for (int j = 0; j < 8; j++) acc[i][j] = 0.0f;

    for (int k0 = 0; k0 < K; k0 += 8) {
        // stage current tile
        As[lk + 0][lr] = a4.x; As[lk + 1][lr] = a4.y;
        As[lk + 2][lr] = a4.z; As[lk + 3][lr] = a4.w;
        if (TB) {
            Bs[lk + 0][lr] = b4.x; Bs[lk + 1][lr] = b4.y;
            Bs[lk + 2][lr] = b4.z; Bs[lk + 3][lr] = b4.w;
        } else {
            *(float4*)&Bs[kr][nc] = b4;
        }
        __syncthreads();

        // prefetch next tile into registers (overlaps with compute)
        if (k0 + 8 < K) {
            Ap += 8; a4 = *(const float4*)Ap;
            if (TB) { Bp += 8; } else { Bp += (long long)8 * N; }
            b4 = *(const float4*)Bp;
        }

#pragma unroll
        for (int kk = 0; kk < 8; kk++) {
            float af[8], bf[8];
            *(float4*)(af)     = *(const float4*)&As[kk][(ty << 2)];
            *(float4*)(af + 4) = *(const float4*)&As[kk][64 + (ty << 2)];
            *(float4*)(bf)     = *(const float4*)&Bs[kk][(tx << 2)];
            *(float4*)(bf + 4) = *(const float4*)&Bs[kk][64 + (tx << 2)];
#pragma unroll
            for (int i = 0; i < 8; i++)
#pragma unroll
                for (int j = 0; j < 8; j++)
                    acc[i][j] = fmaf(af[i], bf[j], acc[i][j]);
        }
        __syncthreads();
    }

    // epilogue
#pragma unroll
    for (int i = 0; i < 8; i++) {
        int row = bm + ((i < 4) ? (ty << 2) + i : 64 + (ty << 2) + (i - 4));
#pragma unroll
        for (int jh = 0; jh < 2; jh++) {
            int col = bn + jh * 64 + (tx << 2);
            float4 r = make_float4(acc[i][jh * 4 + 0], acc[i][jh * 4 + 1],
                                   acc[i][jh * 4 + 2], acc[i][jh * 4 + 3]);
            if (BIAS) {
                float4 bb = *(const float4*)&bias[col];
                r.x += bb.x; r.y += bb.y; r.z += bb.z; r.w += bb.w;
            }
            if (GELU) {
                r.x = gelu_exact(r.x); r.y = gelu_exact(r.y);
                r.z = gelu_exact(r.z); r.w = gelu_exact(r.w);
            }
            *(float4*)&C[(long long)row * N + col] = r;
        }
    }
}

// ---------------- row softmax (rows of length 1024) --------------------------
__global__ void softmax_kernel(float* __restrict__ s) {
    float* p = s + (long long)blockIdx.x * S_;
    __shared__ float red[256];
    int tid = threadIdx.x;

    float m = -1e30f;
    for (int i = tid; i < S_; i += 256) m = fmaxf(m, p[i]);
    red[tid] = m; __syncthreads();
    for (int o = 128; o > 0; o >>= 1) {
        if (tid < o) red[tid] = fmaxf(red[tid], red[tid + o]);
        __syncthreads();
    }
    m = red[0]; __syncthreads();

    float sum = 0.f;
    for (int i = tid; i < S_; i += 256) {
        float e = expf(p[i] - m);
        p[i] = e; sum += e;
    }
    red[tid] = sum; __syncthreads();
    for (int o = 128; o > 0; o >>= 1) {
        if (tid < o) red[tid] += red[tid + o];
        __syncthreads();
    }
    float inv = 1.0f / red[0];
    for (int i = tid; i < S_; i += 256) p[i] *= inv;
}

// ---------------- layernorm over each batch's whole [S,D] slab --------------
__global__ void ln_kernel(const float* __restrict__ a, const float* __restrict__ r,
                          const float* __restrict__ w, const float* __restrict__ bb,
                          float* __restrict__ out) {
    const long long off = (long long)blockIdx.x * (S_ * D_);
    const int tid = threadIdx.x;
    const int NTH = 1024;
    const int NEL = S_ * D_;

    double s = 0.0, s2 = 0.0;
    for (int i = tid; i < NEL; i += NTH) {
        float v = a[off + i] + r[off + i];
        s += (double)v; s2 += (double)v * (double)v;
    }
    __shared__ double sm1[1024];
    __shared__ double sm2[1024];
    sm1[tid] = s; sm2[tid] = s2; __syncthreads();
    for (int o = 512; o > 0; o >>= 1) {
        if (tid < o) { sm1[tid] += sm1[tid + o]; sm2[tid] += sm2[tid + o]; }
        __syncthreads();
    }
    double mean = sm1[0] / NEL;
    double var  = sm2[0] / NEL - mean * mean;
    float mf = (float)mean;
    float sc = (float)(1.0 / sqrt(var + 1e-5));

    for (int i = tid; i < NEL; i += NTH) {
        float v = a[off + i] + r[off + i];
        out[off + i] = (v - mf) * sc * w[i] + bb[i];
    }
}

// ---------------- launch ------------------------------------------------------
extern "C" void kernel_launch(void* const* d_in, const int* in_sizes, int n_in,
                              void* d_out, int out_size) {
    const int*   x    = (const int*)  d_in[0];
    const float* emb  = (const float*)d_in[1];
    const float* Wq   = (const float*)d_in[2];
    const float* bq   = (const float*)d_in[3];
    const float* Wk   = (const float*)d_in[4];
    const float* bk   = (const float*)d_in[5];
    const float* Wv   = (const float*)d_in[6];
    const float* bv   = (const float*)d_in[7];
    const float* Wo   = (const float*)d_in[8];
    const float* bo   = (const float*)d_in[9];
    const float* W1   = (const float*)d_in[10];
    const float* b1   = (const float*)d_in[11];
    const float* W2   = (const float*)d_in[12];
    const float* b2   = (const float*)d_in[13];
    const float* ln1w = (const float*)d_in[14];
    const float* ln1b = (const float*)d_in[15];
    const float* ln2w = (const float*)d_in[16];
    const float* ln2b = (const float*)d_in[17];
    float* out = (float*)d_out;

    float *pe, *y, *q, *k, *v, *s, *av, *ao, *y1, *h1, *f;
    cudaGetSymbolAddress((void**)&pe, g_pe);
    cudaGetSymbolAddress((void**)&y,  g_y);
    cudaGetSymbolAddress((void**)&q,  g_q);
    cudaGetSymbolAddress((void**)&k,  g_k);
    cudaGetSymbolAddress((void**)&v,  g_v);
    cudaGetSymbolAddress((void**)&s,  g_s);
    cudaGetSymbolAddress((void**)&av, g_av);
    cudaGetSymbolAddress((void**)&ao, g_ao);
    cudaGetSymbolAddress((void**)&y1, g_y1);
    cudaGetSymbolAddress((void**)&h1, g_h1);
    cudaGetSymbolAddress((void**)&f,  g_f);

    // 1. positional table + embedding
    pe_kernel<<<(S_*D_ + 255) / 256, 256>>>(pe);
    embed_kernel<<<T_, 256>>>(x, emb, pe, y);

    // 2. q,k,v projections  [8192,768]@[768,3072]
    dim3 gProj(H_/128, T_/128);
    sgemm<0,1,0><<<gProj, 256>>>(y, Wq, bq, q, T_, H_, D_, 0, 0, 0);
    sgemm<0,1,0><<<gProj, 256>>>(y, Wk, bk, k, T_, H_, D_, 0, 0, 0);
    sgemm<0,1,0><<<gProj, 256>>>(y, Wv, bv, v, T_, H_, D_, 0, 0, 0);

    // 3. scores = q @ k^T per batch   [1024,3072]x[1024,3072]^T
    dim3 gScore(S_/128, S_/128, B_);
    sgemm<1,0,0><<<gScore, 256>>>(q, k, nullptr, s, S_, S_, H_,
                                  (long long)S_*H_, (long long)S_*H_, (long long)S_*S_);

    // 4. softmax rows
    softmax_kernel<<<B_*S_, 256>>>(s);

    // 5. av = attn @ v per batch   [1024,1024]@[1024,3072]
    dim3 gAV(H_/128, S_/128, B_);
    sgemm<0,0,0><<<gAV, 256>>>(s, v, nullptr, av, S_, H_, S_,
                               (long long)S_*S_, (long long)S_*H_, (long long)S_*H_);

    // 6. attn out projection  [8192,3072]@[3072,768] + bo
    dim3 gOut(D_/128, T_/128);
    sgemm<0,1,0><<<gOut, 256>>>(av, Wo, bo, ao, T_, D_, H_, 0, 0, 0);

    // 7. LN1 over (y + ao) per batch slab
    ln_kernel<<<B_, 1024>>>(y, ao, ln1w, ln1b, y1);

    // 8. FFN: h1 = y1@W1+b1 ; f = gelu(h1@W2+b2)
    sgemm<0,1,0><<<gProj, 256>>>(y1, W1, b1, h1, T_, H_, D_, 0, 0, 0);
    sgemm<0,1,1><<<gOut,  256>>>(h1, W2, b2, f,  T_, D_, H_, 0, 0, 0);

    // 9. LN2 over (y1 + f) -> output
    ln_kernel<<<B_, 1024>>>(y1, f, ln2w, ln2b, out);
}

// round 3
// speedup vs baseline: 1.4357x; 1.4357x over previous
#include <cuda_runtime.h>
#include <math.h>
#include <cstdint>

#define B_ 8
#define S_ 1024
#define D_ 768
#define H_ 3072
#define T_ (B_*S_)

// ---------------------------------------------------------------- scratch ---
static __device__ float g_pe [S_*D_];
static __device__ float g_y  [T_*D_];
static __device__ float g_q  [T_*H_];
static __device__ float g_k  [T_*H_];
static __device__ float g_vT [B_*H_*S_];   // [B][H][S]
static __device__ float g_s  [B_*S_*S_];
static __device__ float g_av [T_*H_];
static __device__ float g_ao [T_*D_];
static __device__ float g_y1 [T_*D_];
static __device__ float g_h1 [T_*H_];
static __device__ float g_f  [T_*D_];
static __device__ float g_wqt[H_*D_];
static __device__ float g_wkt[H_*D_];
static __device__ float g_wvt[H_*D_];
static __device__ float g_wot[D_*H_];
static __device__ float g_w1t[H_*D_];
static __device__ float g_w2t[D_*H_];
static __device__ double g_part[B_*128*2];
static __device__ double g_stats[B_*2];

// ------------------------------------------------------------- helpers ------
__device__ __forceinline__ uint32_t smem_u32(const void* p) {
    uint32_t a;
    asm("{ .reg .u64 t; cvta.to.shared.u64 t, %1; cvt.u32.u64 %0, t; }" : "=r"(a) : "l"(p));
    return a;
}

#define CP16(dst, src) \
    asm volatile("cp.async.cg.shared.global [%0], [%1], 16;" :: "r"(dst), "l"(src) : "memory")
#define CP_COMMIT() asm volatile("cp.async.commit_group;" ::: "memory")
#define CP_WAIT1()  asm volatile("cp.async.wait_group 1;" ::: "memory")
#define CP_WAIT0()  asm volatile("cp.async.wait_group 0;" ::: "memory")

__device__ __forceinline__ void split2(float x, uint32_t& hi, uint32_t& lo) {
    uint32_t h;
    asm("cvt.rna.tf32.f32 %0, %1;" : "=r"(h) : "f"(x));
    float lf = x - __uint_as_float(h);
    uint32_t l;
    asm("cvt.rna.tf32.f32 %0, %1;" : "=r"(l) : "f"(lf));
    hi = h; lo = l;
}

__device__ __forceinline__ void mma_tf32(float* c, const uint32_t* a, const uint32_t* b) {
    asm volatile(
        "mma.sync.aligned.m16n8k8.row.col.f32.tf32.tf32.f32 "
        "{%0,%1,%2,%3}, {%4,%5,%6,%7}, {%8,%9}, {%0,%1,%2,%3};"
        : "+f"(c[0]), "+f"(c[1]), "+f"(c[2]), "+f"(c[3])
        : "r"(a[0]), "r"(a[1]), "r"(a[2]), "r"(a[3]), "r"(b[0]), "r"(b[1]));
}

__device__ __forceinline__ float gelu_exact(float v) {
    return 0.5f * v * (1.0f + erff(v * 0.70710678118654752f));
}

// smem: per buffer A[128][36] then B[128][36] fp32 (row pad 36 -> conflict-free)
#define ROWP     36
#define A_FLTS   (128 * ROWP)          // 4608 floats = 18432 B
#define BUF_FLTS (2 * A_FLTS)          // 9216 floats = 36864 B
#define SMEM_SZ  (2 * BUF_FLTS * 4)    // 73728 B

// ---------------------------------------------------------------------------
// 3xTF32 mma.sync GEMM: C[M,N] = A[M,K] * B[N,K]^T, 128x128 tile, Kstage=32
// grid = (N/128, M/128, batch). BIASMODE: 0 none, 1 col bias[n], 2 row bias[m]
// ---------------------------------------------------------------------------
template<int BIASMODE, int GELU>
__global__ void __launch_bounds__(256)
mmagemm(const float* __restrict__ A, const float* __restrict__ B,
        const float* __restrict__ bias, float* __restrict__ C,
        int N_, int K_, long long sA, long long sB, long long sC) {
    extern __shared__ float sm[];
    A += (long long)blockIdx.z * sA;
    B += (long long)blockIdx.z * sB;
    C += (long long)blockIdx.z * sC;

    const int tid = threadIdx.x, lane = tid & 31, wid = tid >> 5;
    const int wm = wid >> 2, wn = wid & 3;          // warps: 2 (m) x 4 (n)
    const int bm = blockIdx.y << 7, bn = blockIdx.x << 7;
    const uint32_t sbase = smem_u32(sm);

    float acc[4][4][4];
#pragma unroll
    for (int mt = 0; mt < 4; mt++)
#pragma unroll
        for (int nt = 0; nt < 4; nt++)
#pragma unroll
            for (int r = 0; r < 4; r++) acc[mt][nt][r] = 0.0f;

    // loader geometry: i = tid + j*256 in [0,1024): row = i>>3, 16B-chunk = i&7
    int lrow[4], lc4[4];
#pragma unroll
    for (int j = 0; j < 4; j++) { int i = tid + (j << 8); lrow[j] = i >> 3; lc4[j] = i & 7; }

    const int nst = K_ >> 5;

    // prologue: stage 0
#pragma unroll
    for (int j = 0; j < 4; j++) {
        const float* ga = A + (size_t)(bm + lrow[j]) * K_ + (lc4[j] << 2);
        const float* gb = B + (size_t)(bn + lrow[j]) * K_ + (lc4[j] << 2);
        uint32_t so = sbase + lrow[j] * (ROWP * 4) + (lc4[j] << 4);
        CP16(so, ga);
        CP16(so + A_FLTS * 4, gb);
    }
    CP_COMMIT();

    for (int s = 0; s < nst; s++) {
        if (s + 1 < nst) {
            const int k0 = (s + 1) << 5;
            const uint32_t boff = ((s + 1) & 1) * (BUF_FLTS * 4);
#pragma unroll
            for (int j = 0; j < 4; j++) {
                const float* ga = A + (size_t)(bm + lrow[j]) * K_ + k0 + (lc4[j] << 2);
                const float* gb = B + (size_t)(bn + lrow[j]) * K_ + k0 + (lc4[j] << 2);
                uint32_t so = sbase + boff + lrow[j] * (ROWP * 4) + (lc4[j] << 4);
                CP16(so, ga);
                CP16(so + A_FLTS * 4, gb);
            }
            CP_COMMIT();
            CP_WAIT1();
        } else {
            CP_WAIT0();
        }
        __syncthreads();

        const float* As = sm + (s & 1) * BUF_FLTS;
        const float* Bs = As + A_FLTS;

#pragma unroll
        for (int kc = 0; kc < 4; kc++) {
            const int cA = (kc << 3) + (lane & 3);
            uint32_t ah[4][4], al[4][4], bh[4][2], bl[4][2];
#pragma unroll
            for (int mt = 0; mt < 4; mt++) {
                const int r0 = wm * 64 + mt * 16 + (lane >> 2);
                float f0 = As[r0 * ROWP + cA];
                float f1 = As[(r0 + 8) * ROWP + cA];
                float f2 = As[r0 * ROWP + cA + 4];
                float f3 = As[(r0 + 8) * ROWP + cA + 4];
                split2(f0, ah[mt][0], al[mt][0]);
                split2(f1, ah[mt][1], al[mt][1]);
                split2(f2, ah[mt][2], al[mt][2]);
                split2(f3, ah[mt][3], al[mt][3]);
            }
#pragma unroll
            for (int nt = 0; nt < 4; nt++) {
                const int n0 = wn * 32 + nt * 8 + (lane >> 2);
                float f0 = Bs[n0 * ROWP + cA];
                float f1 = Bs[n0 * ROWP + cA + 4];
                split2(f0, bh[nt][0], bl[nt][0]);
                split2(f1, bh[nt][1], bl[nt][1]);
            }
            // small terms first, then hi*hi
#pragma unroll
            for (int mt = 0; mt < 4; mt++)
#pragma unroll
                for (int nt = 0; nt < 4; nt++) mma_tf32(acc[mt][nt], al[mt], bh[nt]);
#pragma unroll
            for (int mt = 0; mt < 4; mt++)
#pragma unroll
                for (int nt = 0; nt < 4; nt++) mma_tf32(acc[mt][nt], ah[mt], bl[nt]);
#pragma unroll
            for (int mt = 0; mt < 4; mt++)
#pragma unroll
                for (int nt = 0; nt < 4; nt++) mma_tf32(acc[mt][nt], ah[mt], bh[nt]);
        }
        __syncthreads();
    }

    // epilogue
#pragma unroll
    for (int mt = 0; mt < 4; mt++) {
        const int m0 = bm + wm * 64 + mt * 16 + (lane >> 2);
#pragma unroll
        for (int nt = 0; nt < 4; nt++) {
            const int n0 = bn + wn * 32 + nt * 8 + ((lane & 3) << 1);
            float v00 = acc[mt][nt][0], v01 = acc[mt][nt][1];
            float v10 = acc[mt][nt][2], v11 = acc[mt][nt][3];
            if (BIASMODE == 1) {
                float2 bb = *(const float2*)&bias[n0];
                v00 += bb.x; v01 += bb.y; v10 += bb.x; v11 += bb.y;
            } else if (BIASMODE == 2) {
                float r0 = bias[m0], r1 = bias[m0 + 8];
                v00 += r0; v01 += r0; v10 += r1; v11 += r1;
            }
            if (GELU) {
                v00 = gelu_exact(v00); v01 = gelu_exact(v01);
                v10 = gelu_exact(v10); v11 = gelu_exact(v11);
            }
            float2 o0 = make_float2(v00, v01);
            float2 o1 = make_float2(v10, v11);
            *(float2*)&C[(size_t)m0 * N_ + n0] = o0;
            *(float2*)&C[(size_t)(m0 + 8) * N_ + n0] = o1;
        }
    }
}

// ------------------------------------------------------------- aux kernels --
__global__ void pe_kernel(float* __restrict__ pe) {
    int i = blockIdx.x * blockDim.x + threadIdx.x;
    if (i >= S_ * D_) return;
    int s = i / D_, d = i % D_;
    double ang = (double)s * exp(-9.210340371976184 * ((double)d / (double)D_));
    float a = (float)fmod(ang, 6.283185307179586);
    pe[i] = (d & 1) ? cosf(a) : sinf(a);
}

__global__ void embed_kernel(const int* __restrict__ x, const float* __restrict__ emb,
                             const float* __restrict__ pe, float* __restrict__ y) {
    int t = blockIdx.x;
    int s = t & (S_ - 1);
    long long row = x[t];
    const float* er = emb + row * (long long)D_;
    const float* pr = pe + (long long)s * D_;
    float* yr = y + (long long)t * D_;
    for (int d = threadIdx.x; d < D_; d += blockDim.x)
        yr[d] = er[d] + pr[d];
}

__global__ void transpose_k(const float* __restrict__ in, float* __restrict__ out,
                            int R, int C) {
    __shared__ float t[32][33];
    int rb = blockIdx.y * 32, cb = blockIdx.x * 32;
#pragma unroll
    for (int i = 0; i < 32; i += 8)
        t[threadIdx.y + i][threadIdx.x] = in[(size_t)(rb + threadIdx.y + i) * C + cb + threadIdx.x];
    __syncthreads();
#pragma unroll
    for (int i = 0; i < 32; i += 8)
        out[(size_t)(cb + threadIdx.y + i) * R + rb + threadIdx.x] = t[threadIdx.x][threadIdx.y + i];
}

__global__ void softmax_kernel(float* __restrict__ s) {
    float* p = s + (long long)blockIdx.x * S_;
    __shared__ float red[256];
    int tid = threadIdx.x;
    float m = -1e30f;
    for (int i = tid; i < S_; i += 256) m = fmaxf(m, p[i]);
    red[tid] = m; __syncthreads();
    for (int o = 128; o > 0; o >>= 1) { if (tid < o) red[tid] = fmaxf(red[tid], red[tid + o]); __syncthreads(); }
    m = red[0]; __syncthreads();
    float sum = 0.f;
    for (int i = tid; i < S_; i += 256) { float e = expf(p[i] - m); p[i] = e; sum += e; }
    red[tid] = sum; __syncthreads();
    for (int o = 128; o > 0; o >>= 1) { if (tid < o) red[tid] += red[tid + o]; __syncthreads(); }
    float inv = 1.0f / red[0];
    for (int i = tid; i < S_; i += 256) p[i] *= inv;
}

// LN split into part/stats/apply (deterministic, full-chip)
#define LN_CH (S_*D_/128)   // 6144
__global__ void ln_part(const float* __restrict__ a, const float* __restrict__ r,
                        double* __restrict__ part) {
    int b = blockIdx.y, c = blockIdx.x, tid = threadIdx.x;
    size_t base = (size_t)b * (S_*D_) + (size_t)c * LN_CH;
    double s = 0.0, s2 = 0.0;
    for (int i = tid; i < LN_CH; i += 256) {
        float v = a[base + i] + r[base + i];
        s += v; s2 += (double)v * v;
    }
    __shared__ double m1[256], m2[256];
    m1[tid] = s; m2[tid] = s2; __syncthreads();
    for (int o = 128; o > 0; o >>= 1) {
        if (tid < o) { m1[tid] += m1[tid + o]; m2[tid] += m2[tid + o]; }
        __syncthreads();
    }
    if (tid == 0) { part[(b * 128 + c) * 2] = m1[0]; part[(b * 128 + c) * 2 + 1] = m2[0]; }
}
__global__ void ln_stats(const double* __restrict__ part, double* __restrict__ stats) {
    int b = blockIdx.x, tid = threadIdx.x;
    __shared__ double m1[128], m2[128];
    m1[tid] = part[(b * 128 + tid) * 2];
    m2[tid] = part[(b * 128 + tid) * 2 + 1];
    __syncthreads();
    for (int o = 64; o > 0; o >>= 1) {
        if (tid < o) { m1[tid] += m1[tid + o]; m2[tid] += m2[tid + o]; }
        __syncthreads();
    }
    if (tid == 0) {
        double mean = m1[0] / (S_*D_);
        double var  = m2[0] / (S_*D_) - mean * mean;
        stats[b * 2] = mean;
        stats[b * 2 + 1] = 1.0 / sqrt(var + 1e-5);
    }
}
__global__ void ln_apply(const float* __restrict__ a, const float* __restrict__ r,
                         const float* __restrict__ w, const float* __restrict__ bb,
                         const double* __restrict__ stats, float* __restrict__ out) {
    int b = blockIdx.y, c = blockIdx.x, tid = threadIdx.x;
    size_t base = (size_t)b * (S_*D_) + (size_t)c * LN_CH;
    size_t sl = (size_t)c * LN_CH;
    float mean = (float)stats[b * 2];
    float rstd = (float)stats[b * 2 + 1];
    for (int i = tid; i < LN_CH; i += 256) {
        float v = a[base + i] + r[base + i];
        out[base + i] = (v - mean) * rstd * w[sl + i] + bb[sl + i];
    }
}

// ------------------------------------------------------------------ launch --
extern "C" void kernel_launch(void* const* d_in, const int* in_sizes, int n_in,
                              void* d_out, int out_size) {
    const int*   x    = (const int*)  d_in[0];
    const float* emb  = (const float*)d_in[1];
    const float* Wq   = (const float*)d_in[2];
    const float* bq   = (const float*)d_in[3];
    const float* Wk   = (const float*)d_in[4];
    const float* bk   = (const float*)d_in[5];
    const float* Wv   = (const float*)d_in[6];
    const float* bv   = (const float*)d_in[7];
    const float* Wo   = (const float*)d_in[8];
    const float* bo   = (const float*)d_in[9];
    const float* W1   = (const float*)d_in[10];
    const float* b1   = (const float*)d_in[11];
    const float* W2   = (const float*)d_in[12];
    const float* b2   = (const float*)d_in[13];
    const float* ln1w = (const float*)d_in[14];
    const float* ln1b = (const float*)d_in[15];
    const float* ln2w = (const float*)d_in[16];
    const float* ln2b = (const float*)d_in[17];
    float* out = (float*)d_out;

    float *pe, *y, *q, *k, *vT, *s, *av, *ao, *y1, *h1, *f;
    float *wqt, *wkt, *wvt, *wot, *w1t, *w2t;
    double *part, *stats;
    cudaGetSymbolAddress((void**)&pe,  g_pe);
    cudaGetSymbolAddress((void**)&y,   g_y);
    cudaGetSymbolAddress((void**)&q,   g_q);
    cudaGetSymbolAddress((void**)&k,   g_k);
    cudaGetSymbolAddress((void**)&vT,  g_vT);
    cudaGetSymbolAddress((void**)&s,   g_s);
    cudaGetSymbolAddress((void**)&av,  g_av);
    cudaGetSymbolAddress((void**)&ao,  g_ao);
    cudaGetSymbolAddress((void**)&y1,  g_y1);
    cudaGetSymbolAddress((void**)&h1,  g_h1);
    cudaGetSymbolAddress((void**)&f,   g_f);
    cudaGetSymbolAddress((void**)&wqt, g_wqt);
    cudaGetSymbolAddress((void**)&wkt, g_wkt);
    cudaGetSymbolAddress((void**)&wvt, g_wvt);
    cudaGetSymbolAddress((void**)&wot, g_wot);
    cudaGetSymbolAddress((void**)&w1t, g_w1t);
    cudaGetSymbolAddress((void**)&w2t, g_w2t);
    cudaGetSymbolAddress((void**)&part,  g_part);
    cudaGetSymbolAddress((void**)&stats, g_stats);

    cudaFuncSetAttribute(mmagemm<0,0>, cudaFuncAttributeMaxDynamicSharedMemorySize, SMEM_SZ);
    cudaFuncSetAttribute(mmagemm<1,0>, cudaFuncAttributeMaxDynamicSharedMemorySize, SMEM_SZ);
    cudaFuncSetAttribute(mmagemm<2,0>, cudaFuncAttributeMaxDynamicSharedMemorySize, SMEM_SZ);
    cudaFuncSetAttribute(mmagemm<1,1>, cudaFuncAttributeMaxDynamicSharedMemorySize, SMEM_SZ);

    // 0. transposed weights (in [R,C] -> out [C,R])
    transpose_k<<<dim3(H_/32, D_/32), dim3(32,8)>>>(Wq, wqt, D_, H_);
    transpose_k<<<dim3(H_/32, D_/32), dim3(32,8)>>>(Wk, wkt, D_, H_);
    transpose_k<<<dim3(H_/32, D_/32), dim3(32,8)>>>(Wv, wvt, D_, H_);
    transpose_k<<<dim3(D_/32, H_/32), dim3(32,8)>>>(Wo, wot, H_, D_);
    transpose_k<<<dim3(H_/32, D_/32), dim3(32,8)>>>(W1, w1t, D_, H_);
    transpose_k<<<dim3(D_/32, H_/32), dim3(32,8)>>>(W2, w2t, H_, D_);

    // 1. embedding + PE
    pe_kernel<<<(S_*D_ + 255)/256, 256>>>(pe);
    embed_kernel<<<T_, 256>>>(x, emb, pe, y);

    // 2. q = y @ wqt^T + bq ; k likewise  (M=T_, N=H_, K=D_)
    mmagemm<1,0><<<dim3(H_/128, T_/128), 256, SMEM_SZ>>>(y, wqt, bq, q, H_, D_, 0, 0, 0);
    mmagemm<1,0><<<dim3(H_/128, T_/128), 256, SMEM_SZ>>>(y, wkt, bk, k, H_, D_, 0, 0, 0);

    // 3. vT_b = wvt @ y_b^T + bv (row)   (M=H_, N=S_, K=D_)
    mmagemm<2,0><<<dim3(S_/128, H_/128, B_), 256, SMEM_SZ>>>(
        wvt, y, bv, vT, S_, D_, 0, (long long)S_*D_, (long long)H_*S_);

    // 4. scores_b = q_b @ k_b^T  (M=N=S_, K=H_)
    mmagemm<0,0><<<dim3(S_/128, S_/128, B_), 256, SMEM_SZ>>>(
        q, k, nullptr, s, S_, H_, (long long)S_*H_, (long long)S_*H_, (long long)S_*S_);

    // 5. softmax
    softmax_kernel<<<B_*S_, 256>>>(s);

    // 6. av_b = attn_b @ vT_b^T  (M=S_, N=H_, K=S_)
    mmagemm<0,0><<<dim3(H_/128, S_/128, B_), 256, SMEM_SZ>>>(
        s, vT, nullptr, av, H_, S_, (long long)S_*S_, (long long)H_*S_, (long long)S_*H_);

    // 7. ao = av @ wot^T + bo  (M=T_, N=D_, K=H_)
    mmagemm<1,0><<<dim3(D_/128, T_/128), 256, SMEM_SZ>>>(av, wot, bo, ao, D_, H_, 0, 0, 0);

    // 8. LN1: y1 = LN(y + ao)
    ln_part <<<dim3(128, B_), 256>>>(y, ao, part);
    ln_stats<<<B_, 128>>>(part, stats);
    ln_apply<<<dim3(128, B_), 256>>>(y, ao, ln1w, ln1b, stats, y1);

    // 9. FFN
    mmagemm<1,0><<<dim3(H_/128, T_/128), 256, SMEM_SZ>>>(y1, w1t, b1, h1, H_, D_, 0, 0, 0);
    mmagemm<1,1><<<dim3(D_/128, T_/128), 256, SMEM_SZ>>>(h1, w2t, b2, f, D_, H_, 0, 0, 0);

    // 10. LN2 -> out
    ln_part <<<dim3(128, B_), 256>>>(y1, f, part);
    ln_stats<<<B_, 128>>>(part, stats);
    ln_apply<<<dim3(128, B_), 256>>>(y1, f, ln2w, ln2b, stats, out);
}

// round 4
// speedup vs baseline: 2.1394x; 1.4902x over previous
#include <cuda_runtime.h>
#include <cuda_fp16.h>
#include <math.h>
#include <cstdint>

#define B_ 8
#define S_ 1024
#define D_ 768
#define H_ 3072
#define T_ (B_*S_)

typedef long long ll;

// ---------------- scratch: split-pair (uint2 = {half2 hi, half2 lo} / 2 elems)
static __device__ uint2 g_ysp  [T_*D_/2];
static __device__ uint2 g_y1sp [T_*D_/2];
static __device__ uint2 g_qsp  [T_*H_/2];
static __device__ uint2 g_ksp  [T_*H_/2];
static __device__ uint2 g_vTsp [B_*H_*S_/2];
static __device__ uint2 g_ssp  [B_*S_*S_/2];
static __device__ uint2 g_avsp [T_*H_/2];
static __device__ uint2 g_h1sp [T_*H_/2];
static __device__ uint2 g_wqt  [H_*D_/2];
static __device__ uint2 g_wkt  [H_*D_/2];
static __device__ uint2 g_wvt  [H_*D_/2];
static __device__ uint2 g_wot  [D_*H_/2];
static __device__ uint2 g_w1t  [H_*D_/2];
static __device__ uint2 g_w2t  [D_*H_/2];
// fp32 scratch
static __device__ float g_pe [S_*D_];
static __device__ float g_y  [T_*D_];
static __device__ float g_s  [B_*S_*S_];
static __device__ float g_ao [T_*D_];
static __device__ float g_y1 [T_*D_];
static __device__ float g_f  [T_*D_];
static __device__ double g_part[B_*128*2];
static __device__ double g_stats[B_*2];

// ------------------------------------------------------------- helpers ------
__device__ __forceinline__ uint32_t smem_u32(const void* p) {
    uint32_t a;
    asm("{ .reg .u64 t; cvta.to.shared.u64 t, %1; cvt.u32.u64 %0, t; }" : "=r"(a) : "l"(p));
    return a;
}
#define CP16(dst, src) \
    asm volatile("cp.async.cg.shared.global [%0], [%1], 16;" :: "r"(dst), "l"(src) : "memory")
#define CP_COMMIT() asm volatile("cp.async.commit_group;" ::: "memory")
#define CP_WAIT1()  asm volatile("cp.async.wait_group 1;" ::: "memory")
#define CP_WAIT0()  asm volatile("cp.async.wait_group 0;" ::: "memory")

__device__ __forceinline__ uint2 split_pair(float2 v) {
    __half2 h = __float22half2_rn(v);
    float2 hf = __half22float2(h);
    __half2 l = __float22half2_rn(make_float2(v.x - hf.x, v.y - hf.y));
    uint2 o;
    o.x = *reinterpret_cast<uint32_t*>(&h);
    o.y = *reinterpret_cast<uint32_t*>(&l);
    return o;
}

__device__ __forceinline__ void mma_f16(float* c, const uint32_t* a, const uint32_t* b) {
    asm volatile(
        "mma.sync.aligned.m16n8k16.row.col.f32.f16.f16.f32 "
        "{%0,%1,%2,%3}, {%4,%5,%6,%7}, {%8,%9}, {%0,%1,%2,%3};"
        : "+f"(c[0]), "+f"(c[1]), "+f"(c[2]), "+f"(c[3])
        : "r"(a[0]), "r"(a[1]), "r"(a[2]), "r"(a[3]), "r"(b[0]), "r"(b[1]));
}

__device__ __forceinline__ float gelu_exact(float v) {
    return 0.5f * v * (1.0f + erff(v * 0.70710678118654752f));
}

// smem tile: 128 rows x 16 uint2 (32 elems), padded row stride 20 uint2 = 160B
#define RSTR_B   160
#define TILE_B   (128 * RSTR_B)          // 20480
#define BUF_B    (2 * TILE_B)            // 40960 (A + B)
#define SMEM_SZ  (2 * BUF_B)             // 81920

// ---------------------------------------------------------------------------
// fp16-split GEMM: C[M,N] = A[M,K]*B[N,K]^T, inputs in split-pair format.
// 128x128 tile, Kstage=32, 256 thr (warps 2m x 4n), 3 HMMA passes (hh, hl, lh)
// BIASMODE: 0 none, 1 col bias[n], 2 row bias[m]. OUTSPLIT: C split-pair else f32
// ---------------------------------------------------------------------------
template<int BIASMODE, int OUTSPLIT, int GELU>
__global__ void __launch_bounds__(256)
hgemm(const uint2* __restrict__ A, const uint2* __restrict__ B,
      const float* __restrict__ bias, void* __restrict__ Cout,
      int N_, int K_, ll sA, ll sB, ll sC) {
    extern __shared__ char smraw[];
    A += (ll)blockIdx.z * sA;
    B += (ll)blockIdx.z * sB;
    float* Cf = (float*)Cout + (OUTSPLIT ? 0 : (ll)blockIdx.z * sC);
    uint2* Cs = (uint2*)Cout + (OUTSPLIT ? (ll)blockIdx.z * sC : 0);

    const int tid = threadIdx.x, lane = tid & 31, wid = tid >> 5;
    const int wm = wid >> 2, wn = wid & 3;
    const int bm = blockIdx.y << 7, bn = blockIdx.x << 7;
    const int Kp = K_ >> 1;
    const uint32_t sbase = smem_u32(smraw);

    float acc[4][4][4];
#pragma unroll
    for (int mt = 0; mt < 4; mt++)
#pragma unroll
        for (int nt = 0; nt < 4; nt++)
#pragma unroll
            for (int r = 0; r < 4; r++) acc[mt][nt][r] = 0.0f;

    // loaders: i = tid + j*256 in [0,1024): row=i>>3, chunk=i&7 (16B = 2 uint2)
    int lrow[4], lc[4];
#pragma unroll
    for (int j = 0; j < 4; j++) { int i = tid + (j << 8); lrow[j] = i >> 3; lc[j] = i & 7; }

    const int nst = K_ >> 5;

#pragma unroll
    for (int j = 0; j < 4; j++) {
        const uint2* ga = A + (size_t)(bm + lrow[j]) * Kp + (lc[j] << 1);
        const uint2* gb = B + (size_t)(bn + lrow[j]) * Kp + (lc[j] << 1);
        uint32_t so = sbase + lrow[j] * RSTR_B + (lc[j] << 4);
        CP16(so, ga);
        CP16(so + TILE_B, gb);
    }
    CP_COMMIT();

    for (int s = 0; s < nst; s++) {
        if (s + 1 < nst) {
            const int kp0 = (s + 1) << 4;                 // pair offset of next stage
            const uint32_t boff = ((s + 1) & 1) * BUF_B;
#pragma unroll
            for (int j = 0; j < 4; j++) {
                const uint2* ga = A + (size_t)(bm + lrow[j]) * Kp + kp0 + (lc[j] << 1);
                const uint2* gb = B + (size_t)(bn + lrow[j]) * Kp + kp0 + (lc[j] << 1);
                uint32_t so = sbase + boff + lrow[j] * RSTR_B + (lc[j] << 4);
                CP16(so, ga);
                CP16(so + TILE_B, gb);
            }
            CP_COMMIT();
            CP_WAIT1();
        } else {
            CP_WAIT0();
        }
        __syncthreads();

        const uint32_t Asm = sbase + (s & 1) * BUF_B;
        const uint32_t Bsm = Asm + TILE_B;
        const int poff = (lane & 3) << 3;                 // pair byte offset in row

#pragma unroll
        for (int kc = 0; kc < 2; kc++) {
            const uint32_t kb = (kc << 6) + poff;         // kc*8 pairs * 8B
            uint32_t bh[4][2], bl[4][2];
#pragma unroll
            for (int nt = 0; nt < 4; nt++) {
                uint32_t ba = Bsm + (wn * 32 + nt * 8 + (lane >> 2)) * RSTR_B + kb;
                asm volatile("ld.shared.v2.b32 {%0,%1}, [%2];" : "=r"(bh[nt][0]), "=r"(bl[nt][0]) : "r"(ba));
                asm volatile("ld.shared.v2.b32 {%0,%1}, [%2];" : "=r"(bh[nt][1]), "=r"(bl[nt][1]) : "r"(ba + 32));
            }
#pragma unroll
            for (int mt = 0; mt < 4; mt++) {
                uint32_t aa = Asm + (wm * 64 + mt * 16 + (lane >> 2)) * RSTR_B + kb;
                uint32_t ah[4], al[4];
                asm volatile("ld.shared.v2.b32 {%0,%1}, [%2];" : "=r"(ah[0]), "=r"(al[0]) : "r"(aa));
                asm volatile("ld.shared.v2.b32 {%0,%1}, [%2];" : "=r"(ah[1]), "=r"(al[1]) : "r"(aa + 8 * RSTR_B));
                asm volatile("ld.shared.v2.b32 {%0,%1}, [%2];" : "=r"(ah[2]), "=r"(al[2]) : "r"(aa + 32));
                asm volatile("ld.shared.v2.b32 {%0,%1}, [%2];" : "=r"(ah[3]), "=r"(al[3]) : "r"(aa + 8 * RSTR_B + 32));
#pragma unroll
                for (int nt = 0; nt < 4; nt++) {
                    mma_f16(acc[mt][nt], ah, bl[nt]);
                    mma_f16(acc[mt][nt], al, bh[nt]);
                    mma_f16(acc[mt][nt], ah, bh[nt]);
                }
            }
        }
        __syncthreads();
    }

    // epilogue
#pragma unroll
    for (int mt = 0; mt < 4; mt++) {
        const int m0 = bm + wm * 64 + mt * 16 + (lane >> 2);
#pragma unroll
        for (int nt = 0; nt < 4; nt++) {
            const int n0 = bn + wn * 32 + nt * 8 + ((lane & 3) << 1);
            float v00 = acc[mt][nt][0], v01 = acc[mt][nt][1];
            float v10 = acc[mt][nt][2], v11 = acc[mt][nt][3];
            if (BIASMODE == 1) {
                float2 bb = *(const float2*)&bias[n0];
                v00 += bb.x; v01 += bb.y; v10 += bb.x; v11 += bb.y;
            } else if (BIASMODE == 2) {
                float r0 = bias[m0], r1 = bias[m0 + 8];
                v00 += r0; v01 += r0; v10 += r1; v11 += r1;
            }
            if (GELU) {
                v00 = gelu_exact(v00); v01 = gelu_exact(v01);
                v10 = gelu_exact(v10); v11 = gelu_exact(v11);
            }
            if (OUTSPLIT) {
                Cs[((size_t)m0 * N_ + n0) >> 1]       = split_pair(make_float2(v00, v01));
                Cs[((size_t)(m0 + 8) * N_ + n0) >> 1] = split_pair(make_float2(v10, v11));
            } else {
                *(float2*)&Cf[(size_t)m0 * N_ + n0]       = make_float2(v00, v01);
                *(float2*)&Cf[(size_t)(m0 + 8) * N_ + n0] = make_float2(v10, v11);
            }
        }
    }
}

// ------------------------------------------------------------- aux kernels --
__global__ void pe_kernel(float* __restrict__ pe) {
    int i = blockIdx.x * blockDim.x + threadIdx.x;
    if (i >= S_ * D_) return;
    int s = i / D_, d = i % D_;
    double ang = (double)s * exp(-9.210340371976184 * ((double)d / (double)D_));
    float a = (float)fmod(ang, 6.283185307179586);
    pe[i] = (d & 1) ? cosf(a) : sinf(a);
}

__global__ void embed_kernel(const int* __restrict__ x, const float* __restrict__ emb,
                             const float* __restrict__ pe,
                             float* __restrict__ y, uint2* __restrict__ ysp) {
    int t = blockIdx.x;
    int s = t & (S_ - 1);
    ll row = x[t];
    const float* er = emb + row * (ll)D_;
    const float* pr = pe + (ll)s * D_;
    float* yr = y + (ll)t * D_;
    uint2* yp = ysp + (ll)t * (D_ / 2);
    for (int p = threadIdx.x; p < D_ / 2; p += blockDim.x) {
        float2 e = *(const float2*)(er + 2 * p);
        float2 q = *(const float2*)(pr + 2 * p);
        float2 v = make_float2(e.x + q.x, e.y + q.y);
        *(float2*)(yr + 2 * p) = v;
        yp[p] = split_pair(v);
    }
}

// transpose [R][C] fp32 -> [C][R] split-pair
__global__ void transpose_split(const float* __restrict__ in, uint2* __restrict__ out,
                                int R, int C) {
    __shared__ float t[32][33];
    int rb = blockIdx.y * 32, cb = blockIdx.x * 32;
#pragma unroll
    for (int i = 0; i < 32; i += 8)
        t[threadIdx.y + i][threadIdx.x] = in[(size_t)(rb + threadIdx.y + i) * C + cb + threadIdx.x];
    __syncthreads();
    int tid = threadIdx.y * 32 + threadIdx.x;
#pragma unroll
    for (int j = 0; j < 2; j++) {
        int pidx = tid + j * 256;           // [0,512): c = pidx>>4, pr = pidx&15
        int c = pidx >> 4, pr = pidx & 15;
        float2 v = make_float2(t[2 * pr][c], t[2 * pr + 1][c]);
        out[(size_t)(cb + c) * (R >> 1) + (rb >> 1) + pr] = split_pair(v);
    }
}

__global__ void softmax_split(float* __restrict__ s, uint2* __restrict__ sp) {
    float* p = s + (ll)blockIdx.x * S_;
    uint2* o = sp + (ll)blockIdx.x * (S_ / 2);
    __shared__ float red[256];
    int tid = threadIdx.x;
    float m = -1e30f;
    for (int i = tid; i < S_ / 2; i += 256) {
        float2 v = *(const float2*)(p + 2 * i);
        m = fmaxf(m, fmaxf(v.x, v.y));
    }
    red[tid] = m; __syncthreads();
    for (int off = 128; off > 0; off >>= 1) { if (tid < off) red[tid] = fmaxf(red[tid], red[tid + off]); __syncthreads(); }
    m = red[0]; __syncthreads();
    float sum = 0.f;
    for (int i = tid; i < S_ / 2; i += 256) {
        float2 v = *(const float2*)(p + 2 * i);
        v.x = expf(v.x - m); v.y = expf(v.y - m);
        *(float2*)(p + 2 * i) = v;
        sum += v.x + v.y;
    }
    red[tid] = sum; __syncthreads();
    for (int off = 128; off > 0; off >>= 1) { if (tid < off) red[tid] += red[tid + off]; __syncthreads(); }
    float inv = 1.0f / red[0];
    for (int i = tid; i < S_ / 2; i += 256) {
        float2 v = *(const float2*)(p + 2 * i);
        o[i] = split_pair(make_float2(v.x * inv, v.y * inv));
    }
}

#define LN_CH (S_*D_/128)   // 6144
__global__ void ln_part(const float* __restrict__ a, const float* __restrict__ r,
                        double* __restrict__ part) {
    int b = blockIdx.y, c = blockIdx.x, tid = threadIdx.x;
    size_t base = (size_t)b * (S_*D_) + (size_t)c * LN_CH;
    double s = 0.0, s2 = 0.0;
    for (int i = tid; i < LN_CH; i += 256) {
        float v = a[base + i] + r[base + i];
        s += v; s2 += (double)v * v;
    }
    __shared__ double m1[256], m2[256];
    m1[tid] = s; m2[tid] = s2; __syncthreads();
    for (int o = 128; o > 0; o >>= 1) {
        if (tid < o) { m1[tid] += m1[tid + o]; m2[tid] += m2[tid + o]; }
        __syncthreads();
    }
    if (tid == 0) { part[(b * 128 + c) * 2] = m1[0]; part[(b * 128 + c) * 2 + 1] = m2[0]; }
}
__global__ void ln_stats(const double* __restrict__ part, double* __restrict__ stats) {
    int b = blockIdx.x, tid = threadIdx.x;
    __shared__ double m1[128], m2[128];
    m1[tid] = part[(b * 128 + tid) * 2];
    m2[tid] = part[(b * 128 + tid) * 2 + 1];
    __syncthreads();
    for (int o = 64; o > 0; o >>= 1) {
        if (tid < o) { m1[tid] += m1[tid + o]; m2[tid] += m2[tid + o]; }
        __syncthreads();
    }
    if (tid == 0) {
        double mean = m1[0] / (S_*D_);
        double var  = m2[0] / (S_*D_) - mean * mean;
        stats[b * 2] = mean;
        stats[b * 2 + 1] = 1.0 / sqrt(var + 1e-5);
    }
}
template<int SPLIT>
__global__ void ln_apply(const float* __restrict__ a, const float* __restrict__ r,
                         const float* __restrict__ w, const float* __restrict__ bb,
                         const double* __restrict__ stats,
                         float* __restrict__ out, uint2* __restrict__ osp) {
    int b = blockIdx.y, c = blockIdx.x, tid = threadIdx.x;
    size_t base = (size_t)b * (S_*D_) + (size_t)c * LN_CH;
    size_t sl = (size_t)c * LN_CH;
    float mean = (float)stats[b * 2];
    float rstd = (float)stats[b * 2 + 1];
    for (int i = tid; i < LN_CH / 2; i += 256) {
        float2 av_ = *(const float2*)(a + base + 2 * i);
        float2 rv  = *(const float2*)(r + base + 2 * i);
        float2 wv  = *(const float2*)(w + sl + 2 * i);
        float2 bv  = *(const float2*)(bb + sl + 2 * i);
        float2 v;
        v.x = (av_.x + rv.x - mean) * rstd * wv.x + bv.x;
        v.y = (av_.y + rv.y - mean) * rstd * wv.y + bv.y;
        *(float2*)(out + base + 2 * i) = v;
        if (SPLIT) osp[(base >> 1) + i] = split_pair(v);
    }
}

// ------------------------------------------------------------------ launch --
extern "C" void kernel_launch(void* const* d_in, const int* in_sizes, int n_in,
                              void* d_out, int out_size) {
    const int*   x    = (const int*)  d_in[0];
    const float* emb  = (const float*)d_in[1];
    const float* Wq   = (const float*)d_in[2];
    const float* bq   = (const float*)d_in[3];
    const float* Wk   = (const float*)d_in[4];
    const float* bk   = (const float*)d_in[5];
    const float* Wv   = (const float*)d_in[6];
    const float* bv   = (const float*)d_in[7];
    const float* Wo   = (const float*)d_in[8];
    const float* bo   = (const float*)d_in[9];
    const float* W1   = (const float*)d_in[10];
    const float* b1   = (const float*)d_in[11];
    const float* W2   = (const float*)d_in[12];
    const float* b2   = (const float*)d_in[13];
    const float* ln1w = (const float*)d_in[14];
    const float* ln1b = (const float*)d_in[15];
    const float* ln2w = (const float*)d_in[16];
    const float* ln2b = (const float*)d_in[17];
    float* out = (float*)d_out;

    float *pe, *y, *s, *ao, *y1, *f;
    uint2 *ysp, *y1sp, *qsp, *ksp, *vTsp, *ssp, *avsp, *h1sp;
    uint2 *wqt, *wkt, *wvt, *wot, *w1t, *w2t;
    double *part, *stats;
    cudaGetSymbolAddress((void**)&pe,   g_pe);
    cudaGetSymbolAddress((void**)&y,    g_y);
    cudaGetSymbolAddress((void**)&s,    g_s);
    cudaGetSymbolAddress((void**)&ao,   g_ao);
    cudaGetSymbolAddress((void**)&y1,   g_y1);
    cudaGetSymbolAddress((void**)&f,    g_f);
    cudaGetSymbolAddress((void**)&ysp,  g_ysp);
    cudaGetSymbolAddress((void**)&y1sp, g_y1sp);
    cudaGetSymbolAddress((void**)&qsp,  g_qsp);
    cudaGetSymbolAddress((void**)&ksp,  g_ksp);
    cudaGetSymbolAddress((void**)&vTsp, g_vTsp);
    cudaGetSymbolAddress((void**)&ssp,  g_ssp);
    cudaGetSymbolAddress((void**)&avsp, g_avsp);
    cudaGetSymbolAddress((void**)&h1sp, g_h1sp);
    cudaGetSymbolAddress((void**)&wqt,  g_wqt);
    cudaGetSymbolAddress((void**)&wkt,  g_wkt);
    cudaGetSymbolAddress((void**)&wvt,  g_wvt);
    cudaGetSymbolAddress((void**)&wot,  g_wot);
    cudaGetSymbolAddress((void**)&w1t,  g_w1t);
    cudaGetSymbolAddress((void**)&w2t,  g_w2t);
    cudaGetSymbolAddress((void**)&part,  g_part);
    cudaGetSymbolAddress((void**)&stats, g_stats);

    cudaFuncSetAttribute(hgemm<1,1,0>, cudaFuncAttributeMaxDynamicSharedMemorySize, SMEM_SZ);
    cudaFuncSetAttribute(hgemm<2,1,0>, cudaFuncAttributeMaxDynamicSharedMemorySize, SMEM_SZ);
    cudaFuncSetAttribute(hgemm<0,0,0>, cudaFuncAttributeMaxDynamicSharedMemorySize, SMEM_SZ);
    cudaFuncSetAttribute(hgemm<0,1,0>, cudaFuncAttributeMaxDynamicSharedMemorySize, SMEM_SZ);
    cudaFuncSetAttribute(hgemm<1,0,0>, cudaFuncAttributeMaxDynamicSharedMemorySize, SMEM_SZ);
    cudaFuncSetAttribute(hgemm<1,0,1>, cudaFuncAttributeMaxDynamicSharedMemorySize, SMEM_SZ);

    // 0. weights -> transposed split-pair
    transpose_split<<<dim3(H_/32, D_/32), dim3(32,8)>>>(Wq, wqt, D_, H_);
    transpose_split<<<dim3(H_/32, D_/32), dim3(32,8)>>>(Wk, wkt, D_, H_);
    transpose_split<<<dim3(H_/32, D_/32), dim3(32,8)>>>(Wv, wvt, D_, H_);
    transpose_split<<<dim3(D_/32, H_/32), dim3(32,8)>>>(Wo, wot, H_, D_);
    transpose_split<<<dim3(H_/32, D_/32), dim3(32,8)>>>(W1, w1t, D_, H_);
    transpose_split<<<dim3(D_/32, H_/32), dim3(32,8)>>>(W2, w2t, H_, D_);

    // 1. embedding + PE (fp32 + split)
    pe_kernel<<<(S_*D_ + 255)/256, 256>>>(pe);
    embed_kernel<<<T_, 256>>>(x, emb, pe, y, ysp);

    // 2. q,k  (M=T, N=H, K=D) split out, col bias
    hgemm<1,1,0><<<dim3(H_/128, T_/128), 256, SMEM_SZ>>>(ysp, wqt, bq, qsp, H_, D_, 0, 0, 0);
    hgemm<1,1,0><<<dim3(H_/128, T_/128), 256, SMEM_SZ>>>(ysp, wkt, bk, ksp, H_, D_, 0, 0, 0);

    // 3. vT_b = wvt @ y_b^T + bv(row)  (M=H, N=S, K=D) split out
    hgemm<2,1,0><<<dim3(S_/128, H_/128, B_), 256, SMEM_SZ>>>(
        wvt, ysp, bv, vTsp, S_, D_, 0, (ll)S_*D_/2, (ll)H_*S_/2);

    // 4. scores_b = q_b @ k_b^T  (M=N=S, K=H) fp32 out
    hgemm<0,0,0><<<dim3(S_/128, S_/128, B_), 256, SMEM_SZ>>>(
        qsp, ksp, nullptr, s, S_, H_, (ll)S_*H_/2, (ll)S_*H_/2, (ll)S_*S_);

    // 5. softmax -> split probs
    softmax_split<<<B_*S_, 256>>>(s, ssp);

    // 6. av_b = attn_b @ vT_b^T  (M=S, N=H, K=S) split out
    hgemm<0,1,0><<<dim3(H_/128, S_/128, B_), 256, SMEM_SZ>>>(
        ssp, vTsp, nullptr, avsp, H_, S_, (ll)S_*S_/2, (ll)H_*S_/2, (ll)S_*H_/2);

    // 7. ao = av @ wot^T + bo  (M=T, N=D, K=H) fp32 out
    hgemm<1,0,0><<<dim3(D_/128, T_/128), 256, SMEM_SZ>>>(avsp, wot, bo, ao, D_, H_, 0, 0, 0);

    // 8. LN1: y1 = LN(y + ao)  (fp32 + split)
    ln_part <<<dim3(128, B_), 256>>>(y, ao, part);
    ln_stats<<<B_, 128>>>(part, stats);
    ln_apply<1><<<dim3(128, B_), 256>>>(y, ao, ln1w, ln1b, stats, y1, y1sp);

    // 9. FFN: h1 = y1@W1+b1 (split);  f = gelu(h1@W2+b2) (fp32)
    hgemm<1,1,0><<<dim3(H_/128, T_/128), 256, SMEM_SZ>>>(y1sp, w1t, b1, h1sp, H_, D_, 0, 0, 0);
    hgemm<1,0,1><<<dim3(D_/128, T_/128), 256, SMEM_SZ>>>(h1sp, w2t, b2, f, D_, H_, 0, 0, 0);

    // 10. LN2 -> out (fp32 only)
    ln_part <<<dim3(128, B_), 256>>>(y1, f, part);
    ln_stats<<<B_, 128>>>(part, stats);
    ln_apply<0><<<dim3(128, B_), 256>>>(y1, f, ln2w, ln2b, stats, out, nullptr);
}

// round 5
// speedup vs baseline: 2.7772x; 1.2981x over previous
#include <cuda_runtime.h>
#include <cuda_fp16.h>
#include <math.h>
#include <cstdint>

#define B_ 8
#define S_ 1024
#define D_ 768
#define H_ 3072
#define T_ (B_*S_)

typedef long long ll;

// ---------------- scratch: split-pair (uint2 = {half2 hi, half2 lo} / 2 elems)
static __device__ uint2 g_ysp  [T_*D_/2];
static __device__ uint2 g_y1sp [T_*D_/2];
static __device__ uint2 g_qsp  [T_*H_/2];
static __device__ uint2 g_ksp  [T_*H_/2];
static __device__ uint2 g_vTsp [B_*H_*S_/2];
static __device__ uint2 g_ssp  [B_*S_*S_/2];
static __device__ uint2 g_avsp [T_*H_/2];
static __device__ uint2 g_h1sp [T_*H_/2];
static __device__ uint2 g_wqt  [H_*D_/2];
static __device__ uint2 g_wkt  [H_*D_/2];
static __device__ uint2 g_wvt  [H_*D_/2];
static __device__ uint2 g_wot  [D_*H_/2];
static __device__ uint2 g_w1t  [H_*D_/2];
static __device__ uint2 g_w2t  [D_*H_/2];
// fp32 scratch
static __device__ float g_pe [S_*D_];
static __device__ float g_y  [T_*D_];
static __device__ float g_s  [B_*S_*S_];
static __device__ float g_ao [T_*D_];
static __device__ float g_y1 [T_*D_];
static __device__ float g_f  [T_*D_];
static __device__ double g_part[B_*128*2];
static __device__ double g_stats[B_*2];

// ------------------------------------------------------------- helpers ------
__device__ __forceinline__ uint32_t smem_u32(const void* p) {
    uint32_t a;
    asm("{ .reg .u64 t; cvta.to.shared.u64 t, %1; cvt.u32.u64 %0, t; }" : "=r"(a) : "l"(p));
    return a;
}
#define CP16(dst, src) \
    asm volatile("cp.async.cg.shared.global [%0], [%1], 16;" :: "r"(dst), "l"(src) : "memory")
#define CP_COMMIT() asm volatile("cp.async.commit_group;" ::: "memory")
#define CP_WAIT1()  asm volatile("cp.async.wait_group 1;" ::: "memory")
#define CP_WAIT0()  asm volatile("cp.async.wait_group 0;" ::: "memory")

__device__ __forceinline__ uint2 split_pair(float2 v) {
    __half2 h = __float22half2_rn(v);
    float2 hf = __half22float2(h);
    __half2 l = __float22half2_rn(make_float2(v.x - hf.x, v.y - hf.y));
    uint2 o;
    o.x = *reinterpret_cast<uint32_t*>(&h);
    o.y = *reinterpret_cast<uint32_t*>(&l);
    return o;
}

__device__ __forceinline__ void mma_f16(float* c, const uint32_t* a, const uint32_t* b) {
    asm volatile(
        "mma.sync.aligned.m16n8k16.row.col.f32.f16.f16.f32 "
        "{%0,%1,%2,%3}, {%4,%5,%6,%7}, {%8,%9}, {%0,%1,%2,%3};"
        : "+f"(c[0]), "+f"(c[1]), "+f"(c[2]), "+f"(c[3])
        : "r"(a[0]), "r"(a[1]), "r"(a[2]), "r"(a[3]), "r"(b[0]), "r"(b[1]));
}

__device__ __forceinline__ float gelu_exact(float v) {
    return 0.5f * v * (1.0f + erff(v * 0.70710678118654752f));
}

// smem tile: 128 rows x 16 uint2 (32 elems), padded row stride 20 uint2 = 160B
#define RSTR_B   160
#define TILE_B   (128 * RSTR_B)          // 20480
#define BUF_B    (2 * TILE_B)            // 40960 (A + B)
#define SMEM_SZ  (2 * BUF_B)             // 81920

// ---------------------------------------------------------------------------
// fp16-split GEMM: C[M,N] = A[M,K]*B[N,K]^T, inputs in split-pair format.
// 128x128 tile, Kstage=32, 256 thr (warps 2m x 4n).
// PASSES: 3 = ah*bl + al*bh + ah*bh (full),  2 = ah*bl + ah*bh,  1 = ah*bh
// BIASMODE: 0 none, 1 col bias[n], 2 row bias[m]. OUTSPLIT: C split-pair else f32
// ---------------------------------------------------------------------------
template<int PASSES, int BIASMODE, int OUTSPLIT, int GELU>
__global__ void __launch_bounds__(256, 2)
hgemm(const uint2* __restrict__ A, const uint2* __restrict__ B,
      const float* __restrict__ bias, void* __restrict__ Cout,
      int N_, int K_, ll sA, ll sB, ll sC) {
    extern __shared__ char smraw[];
    A += (ll)blockIdx.z * sA;
    B += (ll)blockIdx.z * sB;
    float* Cf = (float*)Cout + (OUTSPLIT ? 0 : (ll)blockIdx.z * sC);
    uint2* Cs = (uint2*)Cout + (OUTSPLIT ? (ll)blockIdx.z * sC : 0);

    const int tid = threadIdx.x, lane = tid & 31, wid = tid >> 5;
    const int wm = wid >> 2, wn = wid & 3;
    const int bm = blockIdx.y << 7, bn = blockIdx.x << 7;
    const int Kp = K_ >> 1;
    const uint32_t sbase = smem_u32(smraw);

    float acc[4][4][4];
#pragma unroll
    for (int mt = 0; mt < 4; mt++)
#pragma unroll
        for (int nt = 0; nt < 4; nt++)
#pragma unroll
            for (int r = 0; r < 4; r++) acc[mt][nt][r] = 0.0f;

    // loaders: i = tid + j*256 in [0,1024): row=i>>3, chunk=i&7 (16B = 2 uint2)
    int lrow[4], lc[4];
#pragma unroll
    for (int j = 0; j < 4; j++) { int i = tid + (j << 8); lrow[j] = i >> 3; lc[j] = i & 7; }

    const int nst = K_ >> 5;

#pragma unroll
    for (int j = 0; j < 4; j++) {
        const uint2* ga = A + (size_t)(bm + lrow[j]) * Kp + (lc[j] << 1);
        const uint2* gb = B + (size_t)(bn + lrow[j]) * Kp + (lc[j] << 1);
        uint32_t so = sbase + lrow[j] * RSTR_B + (lc[j] << 4);
        CP16(so, ga);
        CP16(so + TILE_B, gb);
    }
    CP_COMMIT();

    for (int s = 0; s < nst; s++) {
        if (s + 1 < nst) {
            const int kp0 = (s + 1) << 4;
            const uint32_t boff = ((s + 1) & 1) * BUF_B;
#pragma unroll
            for (int j = 0; j < 4; j++) {
                const uint2* ga = A + (size_t)(bm + lrow[j]) * Kp + kp0 + (lc[j] << 1);
                const uint2* gb = B + (size_t)(bn + lrow[j]) * Kp + kp0 + (lc[j] << 1);
                uint32_t so = sbase + boff + lrow[j] * RSTR_B + (lc[j] << 4);
                CP16(so, ga);
                CP16(so + TILE_B, gb);
            }
            CP_COMMIT();
            CP_WAIT1();
        } else {
            CP_WAIT0();
        }
        __syncthreads();

        const uint32_t Asm = sbase + (s & 1) * BUF_B;
        const uint32_t Bsm = Asm + TILE_B;
        const int poff = (lane & 3) << 3;

#pragma unroll
        for (int kc = 0; kc < 2; kc++) {
            const uint32_t kb = (kc << 6) + poff;
            uint32_t bh[4][2], bl[4][2];
#pragma unroll
            for (int nt = 0; nt < 4; nt++) {
                uint32_t ba = Bsm + (wn * 32 + nt * 8 + (lane >> 2)) * RSTR_B + kb;
                asm volatile("ld.shared.v2.b32 {%0,%1}, [%2];" : "=r"(bh[nt][0]), "=r"(bl[nt][0]) : "r"(ba));
                asm volatile("ld.shared.v2.b32 {%0,%1}, [%2];" : "=r"(bh[nt][1]), "=r"(bl[nt][1]) : "r"(ba + 32));
            }
#pragma unroll
            for (int mt = 0; mt < 4; mt++) {
                uint32_t aa = Asm + (wm * 64 + mt * 16 + (lane >> 2)) * RSTR_B + kb;
                uint32_t ah[4], al[4];
                asm volatile("ld.shared.v2.b32 {%0,%1}, [%2];" : "=r"(ah[0]), "=r"(al[0]) : "r"(aa));
                asm volatile("ld.shared.v2.b32 {%0,%1}, [%2];" : "=r"(ah[1]), "=r"(al[1]) : "r"(aa + 8 * RSTR_B));
                asm volatile("ld.shared.v2.b32 {%0,%1}, [%2];" : "=r"(ah[2]), "=r"(al[2]) : "r"(aa + 32));
                asm volatile("ld.shared.v2.b32 {%0,%1}, [%2];" : "=r"(ah[3]), "=r"(al[3]) : "r"(aa + 8 * RSTR_B + 32));
#pragma unroll
                for (int nt = 0; nt < 4; nt++) {
                    if (PASSES >= 2) mma_f16(acc[mt][nt], ah, bl[nt]);
                    if (PASSES >= 3) mma_f16(acc[mt][nt], al, bh[nt]);
                    mma_f16(acc[mt][nt], ah, bh[nt]);
                }
            }
        }
        __syncthreads();
    }

    // epilogue
#pragma unroll
    for (int mt = 0; mt < 4; mt++) {
        const int m0 = bm + wm * 64 + mt * 16 + (lane >> 2);
#pragma unroll
        for (int nt = 0; nt < 4; nt++) {
            const int n0 = bn + wn * 32 + nt * 8 + ((lane & 3) << 1);
            float v00 = acc[mt][nt][0], v01 = acc[mt][nt][1];
            float v10 = acc[mt][nt][2], v11 = acc[mt][nt][3];
            if (BIASMODE == 1) {
                float2 bb = *(const float2*)&bias[n0];
                v00 += bb.x; v01 += bb.y; v10 += bb.x; v11 += bb.y;
            } else if (BIASMODE == 2) {
                float r0 = bias[m0], r1 = bias[m0 + 8];
                v00 += r0; v01 += r0; v10 += r1; v11 += r1;
            }
            if (GELU) {
                v00 = gelu_exact(v00); v01 = gelu_exact(v01);
                v10 = gelu_exact(v10); v11 = gelu_exact(v11);
            }
            if (OUTSPLIT) {
                Cs[((size_t)m0 * N_ + n0) >> 1]       = split_pair(make_float2(v00, v01));
                Cs[((size_t)(m0 + 8) * N_ + n0) >> 1] = split_pair(make_float2(v10, v11));
            } else {
                *(float2*)&Cf[(size_t)m0 * N_ + n0]       = make_float2(v00, v01);
                *(float2*)&Cf[(size_t)(m0 + 8) * N_ + n0] = make_float2(v10, v11);
            }
        }
    }
}

// ------------------------------------------------------------- aux kernels --
__global__ void pe_kernel(float* __restrict__ pe) {
    int i = blockIdx.x * blockDim.x + threadIdx.x;
    if (i >= S_ * D_) return;
    int s = i / D_, d = i % D_;
    double ang = (double)s * exp(-9.210340371976184 * ((double)d / (double)D_));
    float a = (float)fmod(ang, 6.283185307179586);
    pe[i] = (d & 1) ? cosf(a) : sinf(a);
}

__global__ void embed_kernel(const int* __restrict__ x, const float* __restrict__ emb,
                             const float* __restrict__ pe,
                             float* __restrict__ y, uint2* __restrict__ ysp) {
    int t = blockIdx.x;
    int s = t & (S_ - 1);
    ll row = x[t];
    const float* er = emb + row * (ll)D_;
    const float* pr = pe + (ll)s * D_;
    float* yr = y + (ll)t * D_;
    uint2* yp = ysp + (ll)t * (D_ / 2);
    for (int p = threadIdx.x; p < D_ / 2; p += blockDim.x) {
        float2 e = *(const float2*)(er + 2 * p);
        float2 q = *(const float2*)(pr + 2 * p);
        float2 v = make_float2(e.x + q.x, e.y + q.y);
        *(float2*)(yr + 2 * p) = v;
        yp[p] = split_pair(v);
    }
}

// transpose [R][C] fp32 -> [C][R] split-pair
__global__ void transpose_split(const float* __restrict__ in, uint2* __restrict__ out,
                                int R, int C) {
    __shared__ float t[32][33];
    int rb = blockIdx.y * 32, cb = blockIdx.x * 32;
#pragma unroll
    for (int i = 0; i < 32; i += 8)
        t[threadIdx.y + i][threadIdx.x] = in[(size_t)(rb + threadIdx.y + i) * C + cb + threadIdx.x];
    __syncthreads();
    int tid = threadIdx.y * 32 + threadIdx.x;
#pragma unroll
    for (int j = 0; j < 2; j++) {
        int pidx = tid + j * 256;
        int c = pidx >> 4, pr = pidx & 15;
        float2 v = make_float2(t[2 * pr][c], t[2 * pr + 1][c]);
        out[(size_t)(cb + c) * (R >> 1) + (rb >> 1) + pr] = split_pair(v);
    }
}

__global__ void softmax_split(float* __restrict__ s, uint2* __restrict__ sp) {
    float* p = s + (ll)blockIdx.x * S_;
    uint2* o = sp + (ll)blockIdx.x * (S_ / 2);
    __shared__ float red[256];
    int tid = threadIdx.x;
    float m = -1e30f;
    for (int i = tid; i < S_ / 2; i += 256) {
        float2 v = *(const float2*)(p + 2 * i);
        m = fmaxf(m, fmaxf(v.x, v.y));
    }
    red[tid] = m; __syncthreads();
    for (int off = 128; off > 0; off >>= 1) { if (tid < off) red[tid] = fmaxf(red[tid], red[tid + off]); __syncthreads(); }
    m = red[0]; __syncthreads();
    float sum = 0.f;
    for (int i = tid; i < S_ / 2; i += 256) {
        float2 v = *(const float2*)(p + 2 * i);
        v.x = expf(v.x - m); v.y = expf(v.y - m);
        *(float2*)(p + 2 * i) = v;
        sum += v.x + v.y;
    }
    red[tid] = sum; __syncthreads();
    for (int off = 128; off > 0; off >>= 1) { if (tid < off) red[tid] += red[tid + off]; __syncthreads(); }
    float inv = 1.0f / red[0];
    for (int i = tid; i < S_ / 2; i += 256) {
        float2 v = *(const float2*)(p + 2 * i);
        o[i] = split_pair(make_float2(v.x * inv, v.y * inv));
    }
}

#define LN_CH (S_*D_/128)   // 6144
__global__ void ln_part(const float* __restrict__ a, const float* __restrict__ r,
                        double* __restrict__ part) {
    int b = blockIdx.y, c = blockIdx.x, tid = threadIdx.x;
    size_t base = (size_t)b * (S_*D_) + (size_t)c * LN_CH;
    double s = 0.0, s2 = 0.0;
    for (int i = tid; i < LN_CH; i += 256) {
        float v = a[base + i] + r[base + i];
        s += v; s2 += (double)v * v;
    }
    __shared__ double m1[256], m2[256];
    m1[tid] = s; m2[tid] = s2; __syncthreads();
    for (int o = 128; o > 0; o >>= 1) {
        if (tid < o) { m1[tid] += m1[tid + o]; m2[tid] += m2[tid + o]; }
        __syncthreads();
    }
    if (tid == 0) { part[(b * 128 + c) * 2] = m1[0]; part[(b * 128 + c) * 2 + 1] = m2[0]; }
}
__global__ void ln_stats(const double* __restrict__ part, double* __restrict__ stats) {
    int b = blockIdx.x, tid = threadIdx.x;
    __shared__ double m1[128], m2[128];
    m1[tid] = part[(b * 128 + tid) * 2];
    m2[tid] = part[(b * 128 + tid) * 2 + 1];
    __syncthreads();
    for (int o = 64; o > 0; o >>= 1) {
        if (tid < o) { m1[tid] += m1[tid + o]; m2[tid] += m2[tid + o]; }
        __syncthreads();
    }
    if (tid == 0) {
        double mean = m1[0] / (S_*D_);
        double var  = m2[0] / (S_*D_) - mean * mean;
        stats[b * 2] = mean;
        stats[b * 2 + 1] = 1.0 / sqrt(var + 1e-5);
    }
}
template<int SPLIT>
__global__ void ln_apply(const float* __restrict__ a, const float* __restrict__ r,
                         const float* __restrict__ w, const float* __restrict__ bb,
                         const double* __restrict__ stats,
                         float* __restrict__ out, uint2* __restrict__ osp) {
    int b = blockIdx.y, c = blockIdx.x, tid = threadIdx.x;
    size_t base = (size_t)b * (S_*D_) + (size_t)c * LN_CH;
    size_t sl = (size_t)c * LN_CH;
    float mean = (float)stats[b * 2];
    float rstd = (float)stats[b * 2 + 1];
    for (int i = tid; i < LN_CH / 2; i += 256) {
        float2 av_ = *(const float2*)(a + base + 2 * i);
        float2 rv  = *(const float2*)(r + base + 2 * i);
        float2 wv  = *(const float2*)(w + sl + 2 * i);
        float2 bv  = *(const float2*)(bb + sl + 2 * i);
        float2 v;
        v.x = (av_.x + rv.x - mean) * rstd * wv.x + bv.x;
        v.y = (av_.y + rv.y - mean) * rstd * wv.y + bv.y;
        *(float2*)(out + base + 2 * i) = v;
        if (SPLIT) osp[(base >> 1) + i] = split_pair(v);
    }
}

// ------------------------------------------------------------------ launch --
extern "C" void kernel_launch(void* const* d_in, const int* in_sizes, int n_in,
                              void* d_out, int out_size) {
    const int*   x    = (const int*)  d_in[0];
    const float* emb  = (const float*)d_in[1];
    const float* Wq   = (const float*)d_in[2];
    const float* bq   = (const float*)d_in[3];
    const float* Wk   = (const float*)d_in[4];
    const float* bk   = (const float*)d_in[5];
    const float* Wv   = (const float*)d_in[6];
    const float* bv   = (const float*)d_in[7];
    const float* Wo   = (const float*)d_in[8];
    const float* bo   = (const float*)d_in[9];
    const float* W1   = (const float*)d_in[10];
    const float* b1   = (const float*)d_in[11];
    const float* W2   = (const float*)d_in[12];
    const float* b2   = (const float*)d_in[13];
    const float* ln1w = (const float*)d_in[14];
    const float* ln1b = (const float*)d_in[15];
    const float* ln2w = (const float*)d_in[16];
    const float* ln2b = (const float*)d_in[17];
    float* out = (float*)d_out;

    float *pe, *y, *s, *ao, *y1, *f;
    uint2 *ysp, *y1sp, *qsp, *ksp, *vTsp, *ssp, *avsp, *h1sp;
    uint2 *wqt, *wkt, *wvt, *wot, *w1t, *w2t;
    double *part, *stats;
    cudaGetSymbolAddress((void**)&pe,   g_pe);
    cudaGetSymbolAddress((void**)&y,    g_y);
    cudaGetSymbolAddress((void**)&s,    g_s);
    cudaGetSymbolAddress((void**)&ao,   g_ao);
    cudaGetSymbolAddress((void**)&y1,   g_y1);
    cudaGetSymbolAddress((void**)&f,    g_f);
    cudaGetSymbolAddress((void**)&ysp,  g_ysp);
    cudaGetSymbolAddress((void**)&y1sp, g_y1sp);
    cudaGetSymbolAddress((void**)&qsp,  g_qsp);
    cudaGetSymbolAddress((void**)&ksp,  g_ksp);
    cudaGetSymbolAddress((void**)&vTsp, g_vTsp);
    cudaGetSymbolAddress((void**)&ssp,  g_ssp);
    cudaGetSymbolAddress((void**)&avsp, g_avsp);
    cudaGetSymbolAddress((void**)&h1sp, g_h1sp);
    cudaGetSymbolAddress((void**)&wqt,  g_wqt);
    cudaGetSymbolAddress((void**)&wkt,  g_wkt);
    cudaGetSymbolAddress((void**)&wvt,  g_wvt);
    cudaGetSymbolAddress((void**)&wot,  g_wot);
    cudaGetSymbolAddress((void**)&w1t,  g_w1t);
    cudaGetSymbolAddress((void**)&w2t,  g_w2t);
    cudaGetSymbolAddress((void**)&part,  g_part);
    cudaGetSymbolAddress((void**)&stats, g_stats);

    cudaFuncSetAttribute(hgemm<3,1,1,0>, cudaFuncAttributeMaxDynamicSharedMemorySize, SMEM_SZ);
    cudaFuncSetAttribute(hgemm<3,2,1,0>, cudaFuncAttributeMaxDynamicSharedMemorySize, SMEM_SZ);
    cudaFuncSetAttribute(hgemm<1,0,0,0>, cudaFuncAttributeMaxDynamicSharedMemorySize, SMEM_SZ);
    cudaFuncSetAttribute(hgemm<2,0,1,0>, cudaFuncAttributeMaxDynamicSharedMemorySize, SMEM_SZ);
    cudaFuncSetAttribute(hgemm<3,1,0,0>, cudaFuncAttributeMaxDynamicSharedMemorySize, SMEM_SZ);
    cudaFuncSetAttribute(hgemm<3,1,0,1>, cudaFuncAttributeMaxDynamicSharedMemorySize, SMEM_SZ);

    // 0. weights -> transposed split-pair
    transpose_split<<<dim3(H_/32, D_/32), dim3(32,8)>>>(Wq, wqt, D_, H_);
    transpose_split<<<dim3(H_/32, D_/32), dim3(32,8)>>>(Wk, wkt, D_, H_);
    transpose_split<<<dim3(H_/32, D_/32), dim3(32,8)>>>(Wv, wvt, D_, H_);
    transpose_split<<<dim3(D_/32, H_/32), dim3(32,8)>>>(Wo, wot, H_, D_);
    transpose_split<<<dim3(H_/32, D_/32), dim3(32,8)>>>(W1, w1t, D_, H_);
    transpose_split<<<dim3(D_/32, H_/32), dim3(32,8)>>>(W2, w2t, H_, D_);

    // 1. embedding + PE (fp32 + split)
    pe_kernel<<<(S_*D_ + 255)/256, 256>>>(pe);
    embed_kernel<<<T_, 256>>>(x, emb, pe, y, ysp);

    // 2. q,k  (M=T, N=H, K=D) 3-pass, split out, col bias
    hgemm<3,1,1,0><<<dim3(H_/128, T_/128), 256, SMEM_SZ>>>(ysp, wqt, bq, qsp, H_, D_, 0, 0, 0);
    hgemm<3,1,1,0><<<dim3(H_/128, T_/128), 256, SMEM_SZ>>>(ysp, wkt, bk, ksp, H_, D_, 0, 0, 0);

    // 3. vT_b = wvt @ y_b^T + bv(row)  (M=H, N=S, K=D) 3-pass, split out
    hgemm<3,2,1,0><<<dim3(S_/128, H_/128, B_), 256, SMEM_SZ>>>(
        wvt, ysp, bv, vTsp, S_, D_, 0, (ll)S_*D_/2, (ll)H_*S_/2);

    // 4. scores_b = q_b @ k_b^T  (M=N=S, K=H) 1-pass (abs score err ~1e-6), f32 out
    hgemm<1,0,0,0><<<dim3(S_/128, S_/128, B_), 256, SMEM_SZ>>>(
        qsp, ksp, nullptr, s, S_, H_, (ll)S_*H_/2, (ll)S_*H_/2, (ll)S_*S_);

    // 5. softmax -> split probs
    softmax_split<<<B_*S_, 256>>>(s, ssp);

    // 6. av_b = attn_b @ vT_b^T  (M=S, N=H, K=S) 2-pass, split out
    hgemm<2,0,1,0><<<dim3(H_/128, S_/128, B_), 256, SMEM_SZ>>>(
        ssp, vTsp, nullptr, avsp, H_, S_, (ll)S_*S_/2, (ll)H_*S_/2, (ll)S_*H_/2);

    // 7. ao = av @ wot^T + bo  (M=T, N=D, K=H) 3-pass, f32 out
    hgemm<3,1,0,0><<<dim3(D_/128, T_/128), 256, SMEM_SZ>>>(avsp, wot, bo, ao, D_, H_, 0, 0, 0);

    // 8. LN1: y1 = LN(y + ao)  (fp32 + split)
    ln_part <<<dim3(128, B_), 256>>>(y, ao, part);
    ln_stats<<<B_, 128>>>(part, stats);
    ln_apply<1><<<dim3(128, B_), 256>>>(y, ao, ln1w, ln1b, stats, y1, y1sp);

    // 9. FFN: h1 = y1@W1+b1 (split);  f = gelu(h1@W2+b2) (fp32)
    hgemm<3,1,1,0><<<dim3(H_/128, T_/128), 256, SMEM_SZ>>>(y1sp, w1t, b1, h1sp, H_, D_, 0, 0, 0);
    hgemm<3,1,0,1><<<dim3(D_/128, T_/128), 256, SMEM_SZ>>>(h1sp, w2t, b2, f, D_, H_, 0, 0, 0);

    // 10. LN2 -> out (fp32 only)
    ln_part <<<dim3(128, B_), 256>>>(y1, f, part);
    ln_stats<<<B_, 128>>>(part, stats);
    ln_apply<0><<<dim3(128, B_), 256>>>(y1, f, ln2w, ln2b, stats, out, nullptr);
}

// round 6
// speedup vs baseline: 3.3463x; 1.2049x over previous
#include <cuda_runtime.h>
#include <cuda_fp16.h>
#include <math.h>
#include <cstdint>

#define B_ 8
#define S_ 1024
#define D_ 768
#define H_ 3072
#define T_ (B_*S_)

typedef long long ll;

// ---------------- scratch: split-pair (uint2 = {half2 hi, half2 lo} / 2 elems)
static __device__ uint2 g_ysp  [T_*D_/2];
static __device__ uint2 g_y1sp [T_*D_/2];
static __device__ uint2 g_qsp  [T_*H_/2];
static __device__ uint2 g_ksp  [T_*H_/2];
static __device__ uint2 g_vTsp [B_*H_*S_/2];
static __device__ uint2 g_ssp  [B_*S_*S_/2];
static __device__ uint2 g_avsp [T_*H_/2];
static __device__ uint2 g_h1sp [T_*H_/2];
static __device__ uint2 g_wqt  [H_*D_/2];
static __device__ uint2 g_wkt  [H_*D_/2];
static __device__ uint2 g_wvt  [H_*D_/2];
static __device__ uint2 g_wot  [D_*H_/2];
static __device__ uint2 g_w1t  [H_*D_/2];
static __device__ uint2 g_w2t  [D_*H_/2];
// fp32 scratch
static __device__ float g_pe [S_*D_];
static __device__ float g_y  [T_*D_];
static __device__ float g_s  [B_*S_*S_];
static __device__ float g_ao [T_*D_];
static __device__ float g_y1 [T_*D_];
static __device__ float g_f  [T_*D_];
static __device__ double g_part[B_*128*2];
static __device__ double g_stats[B_*2];

// ------------------------------------------------------------- helpers ------
__device__ __forceinline__ uint32_t smem_u32(const void* p) {
    uint32_t a;
    asm("{ .reg .u64 t; cvta.to.shared.u64 t, %1; cvt.u32.u64 %0, t; }" : "=r"(a) : "l"(p));
    return a;
}
#define CP16(dst, src) \
    asm volatile("cp.async.cg.shared.global [%0], [%1], 16;" :: "r"(dst), "l"(src) : "memory")
#define CP_COMMIT() asm volatile("cp.async.commit_group;" ::: "memory")
#define CP_WAIT0()  asm volatile("cp.async.wait_group 0;" ::: "memory")

__device__ __forceinline__ uint2 split_pair(float2 v) {
    __half2 h = __float22half2_rn(v);
    float2 hf = __half22float2(h);
    __half2 l = __float22half2_rn(make_float2(v.x - hf.x, v.y - hf.y));
    uint2 o;
    o.x = *reinterpret_cast<uint32_t*>(&h);
    o.y = *reinterpret_cast<uint32_t*>(&l);
    return o;
}

__device__ __forceinline__ void mma_f16(float* c, const uint32_t* a, const uint32_t* b) {
    asm volatile(
        "mma.sync.aligned.m16n8k16.row.col.f32.f16.f16.f32 "
        "{%0,%1,%2,%3}, {%4,%5,%6,%7}, {%8,%9}, {%0,%1,%2,%3};"
        : "+f"(c[0]), "+f"(c[1]), "+f"(c[2]), "+f"(c[3])
        : "r"(a[0]), "r"(a[1]), "r"(a[2]), "r"(a[3]), "r"(b[0]), "r"(b[1]));
}

__device__ __forceinline__ float gelu_exact(float v) {
    return 0.5f * v * (1.0f + erff(v * 0.70710678118654752f));
}

// smem tile: 128 rows x 16 uint2 (32 elems), padded row stride 20 uint2 = 160B
#define RSTR_B   160
#define TILE_B   (128 * RSTR_B)          // 20480
#define BUF_B    (2 * TILE_B)            // 40960 (A + B)
#define SMEM_SZ  (2 * BUF_B)             // 81920

// ---------------------------------------------------------------------------
// fp16-split GEMM: C[M,N] = A[M,K]*B[N,K]^T, inputs in split-pair format.
// 128x128 tile, Kstage=32, 256 thr (warps 2m x 4n), single-sync double buffer.
// PASSES: 3 = ah*bl + al*bh + ah*bh,  2 = ah*bl + ah*bh,  1 = ah*bh
// BIASMODE: 0 none, 1 col bias[n], 2 row bias[m]. OUTSPLIT: C split-pair else f32
// ---------------------------------------------------------------------------
template<int PASSES, int BIASMODE, int OUTSPLIT, int GELU>
__global__ void __launch_bounds__(256, 2)
hgemm(const uint2* __restrict__ A, const uint2* __restrict__ B,
      const float* __restrict__ bias, void* __restrict__ Cout,
      int N_, int K_, ll sA, ll sB, ll sC) {
    extern __shared__ char smraw[];
    A += (ll)blockIdx.z * sA;
    B += (ll)blockIdx.z * sB;
    float* Cf = (float*)Cout + (OUTSPLIT ? 0 : (ll)blockIdx.z * sC);
    uint2* Cs = (uint2*)Cout + (OUTSPLIT ? (ll)blockIdx.z * sC : 0);

    const int tid = threadIdx.x, lane = tid & 31, wid = tid >> 5;
    const int wm = wid >> 2, wn = wid & 3;
    const int bm = blockIdx.y << 7, bn = blockIdx.x << 7;
    const int Kp = K_ >> 1;
    const uint32_t sbase = smem_u32(smraw);

    float acc[4][4][4];
#pragma unroll
    for (int mt = 0; mt < 4; mt++)
#pragma unroll
        for (int nt = 0; nt < 4; nt++)
#pragma unroll
            for (int r = 0; r < 4; r++) acc[mt][nt][r] = 0.0f;

    // loaders: i = tid + j*256 in [0,1024): row=i>>3, chunk=i&7 (16B = 2 uint2)
    int lrow[4], lc[4];
#pragma unroll
    for (int j = 0; j < 4; j++) { int i = tid + (j << 8); lrow[j] = i >> 3; lc[j] = i & 7; }

    const int nst = K_ >> 5;

    // prologue: stage 0 into buf 0
#pragma unroll
    for (int j = 0; j < 4; j++) {
        const uint2* ga = A + (size_t)(bm + lrow[j]) * Kp + (lc[j] << 1);
        const uint2* gb = B + (size_t)(bn + lrow[j]) * Kp + (lc[j] << 1);
        uint32_t so = sbase + lrow[j] * RSTR_B + (lc[j] << 4);
        CP16(so, ga);
        CP16(so + TILE_B, gb);
    }
    CP_COMMIT();

    for (int s = 0; s < nst; s++) {
        // wait for stage s data; sync also orders prior reads of buf[(s+1)&1]
        CP_WAIT0();
        __syncthreads();

        // issue stage s+1 into the other buffer (overlaps with compute below)
        if (s + 1 < nst) {
            const int kp0 = (s + 1) << 4;
            const uint32_t boff = ((s + 1) & 1) * BUF_B;
#pragma unroll
            for (int j = 0; j < 4; j++) {
                const uint2* ga = A + (size_t)(bm + lrow[j]) * Kp + kp0 + (lc[j] << 1);
                const uint2* gb = B + (size_t)(bn + lrow[j]) * Kp + kp0 + (lc[j] << 1);
                uint32_t so = sbase + boff + lrow[j] * RSTR_B + (lc[j] << 4);
                CP16(so, ga);
                CP16(so + TILE_B, gb);
            }
            CP_COMMIT();
        }

        const uint32_t Asm = sbase + (s & 1) * BUF_B;
        const uint32_t Bsm = Asm + TILE_B;
        const int poff = (lane & 3) << 3;

#pragma unroll
        for (int kc = 0; kc < 2; kc++) {
            const uint32_t kb = (kc << 6) + poff;
            uint32_t bh[4][2], bl[4][2];
#pragma unroll
            for (int nt = 0; nt < 4; nt++) {
                uint32_t ba = Bsm + (wn * 32 + nt * 8 + (lane >> 2)) * RSTR_B + kb;
                asm volatile("ld.shared.v2.b32 {%0,%1}, [%2];" : "=r"(bh[nt][0]), "=r"(bl[nt][0]) : "r"(ba));
                asm volatile("ld.shared.v2.b32 {%0,%1}, [%2];" : "=r"(bh[nt][1]), "=r"(bl[nt][1]) : "r"(ba + 32));
            }
#pragma unroll
            for (int mt = 0; mt < 4; mt++) {
                uint32_t aa = Asm + (wm * 64 + mt * 16 + (lane >> 2)) * RSTR_B + kb;
                uint32_t ah[4], al[4];
                asm volatile("ld.shared.v2.b32 {%0,%1}, [%2];" : "=r"(ah[0]), "=r"(al[0]) : "r"(aa));
                asm volatile("ld.shared.v2.b32 {%0,%1}, [%2];" : "=r"(ah[1]), "=r"(al[1]) : "r"(aa + 8 * RSTR_B));
                asm volatile("ld.shared.v2.b32 {%0,%1}, [%2];" : "=r"(ah[2]), "=r"(al[2]) : "r"(aa + 32));
                asm volatile("ld.shared.v2.b32 {%0,%1}, [%2];" : "=r"(ah[3]), "=r"(al[3]) : "r"(aa + 8 * RSTR_B + 32));
#pragma unroll
                for (int nt = 0; nt < 4; nt++) {
                    if (PASSES >= 2) mma_f16(acc[mt][nt], ah, bl[nt]);
                    if (PASSES >= 3) mma_f16(acc[mt][nt], al, bh[nt]);
                    mma_f16(acc[mt][nt], ah, bh[nt]);
                }
            }
        }
    }

    __syncthreads();   // protect smem before any (unlikely) reuse; cheap, once

    // epilogue
#pragma unroll
    for (int mt = 0; mt < 4; mt++) {
        const int m0 = bm + wm * 64 + mt * 16 + (lane >> 2);
#pragma unroll
        for (int nt = 0; nt < 4; nt++) {
            const int n0 = bn + wn * 32 + nt * 8 + ((lane & 3) << 1);
            float v00 = acc[mt][nt][0], v01 = acc[mt][nt][1];
            float v10 = acc[mt][nt][2], v11 = acc[mt][nt][3];
            if (BIASMODE == 1) {
                float2 bb = *(const float2*)&bias[n0];
                v00 += bb.x; v01 += bb.y; v10 += bb.x; v11 += bb.y;
            } else if (BIASMODE == 2) {
                float r0 = bias[m0], r1 = bias[m0 + 8];
                v00 += r0; v01 += r0; v10 += r1; v11 += r1;
            }
            if (GELU) {
                v00 = gelu_exact(v00); v01 = gelu_exact(v01);
                v10 = gelu_exact(v10); v11 = gelu_exact(v11);
            }
            if (OUTSPLIT) {
                Cs[((size_t)m0 * N_ + n0) >> 1]       = split_pair(make_float2(v00, v01));
                Cs[((size_t)(m0 + 8) * N_ + n0) >> 1] = split_pair(make_float2(v10, v11));
            } else {
                *(float2*)&Cf[(size_t)m0 * N_ + n0]       = make_float2(v00, v01);
                *(float2*)&Cf[(size_t)(m0 + 8) * N_ + n0] = make_float2(v10, v11);
            }
        }
    }
}

// ------------------------------------------------------------- aux kernels --
__global__ void pe_kernel(float* __restrict__ pe) {
    int i = blockIdx.x * blockDim.x + threadIdx.x;
    if (i >= S_ * D_) return;
    int s = i / D_, d = i % D_;
    double ang = (double)s * exp(-9.210340371976184 * ((double)d / (double)D_));
    float a = (float)fmod(ang, 6.283185307179586);
    pe[i] = (d & 1) ? cosf(a) : sinf(a);
}

__global__ void embed_kernel(const int* __restrict__ x, const float* __restrict__ emb,
                             const float* __restrict__ pe,
                             float* __restrict__ y, uint2* __restrict__ ysp) {
    int t = blockIdx.x;
    int s = t & (S_ - 1);
    ll row = x[t];
    const float* er = emb + row * (ll)D_;
    const float* pr = pe + (ll)s * D_;
    float* yr = y + (ll)t * D_;
    uint2* yp = ysp + (ll)t * (D_ / 2);
    for (int p = threadIdx.x; p < D_ / 2; p += blockDim.x) {
        float2 e = *(const float2*)(er + 2 * p);
        float2 q = *(const float2*)(pr + 2 * p);
        float2 v = make_float2(e.x + q.x, e.y + q.y);
        *(float2*)(yr + 2 * p) = v;
        yp[p] = split_pair(v);
    }
}

// transpose [R][C] fp32 -> [C][R] split-pair
__global__ void transpose_split(const float* __restrict__ in, uint2* __restrict__ out,
                                int R, int C) {
    __shared__ float t[32][33];
    int rb = blockIdx.y * 32, cb = blockIdx.x * 32;
#pragma unroll
    for (int i = 0; i < 32; i += 8)
        t[threadIdx.y + i][threadIdx.x] = in[(size_t)(rb + threadIdx.y + i) * C + cb + threadIdx.x];
    __syncthreads();
    int tid = threadIdx.y * 32 + threadIdx.x;
#pragma unroll
    for (int j = 0; j < 2; j++) {
        int pidx = tid + j * 256;
        int c = pidx >> 4, pr = pidx & 15;
        float2 v = make_float2(t[2 * pr][c], t[2 * pr + 1][c]);
        out[(size_t)(cb + c) * (R >> 1) + (rb >> 1) + pr] = split_pair(v);
    }
}

__global__ void softmax_split(float* __restrict__ s, uint2* __restrict__ sp) {
    float* p = s + (ll)blockIdx.x * S_;
    uint2* o = sp + (ll)blockIdx.x * (S_ / 2);
    __shared__ float red[256];
    int tid = threadIdx.x;
    float m = -1e30f;
    for (int i = tid; i < S_ / 2; i += 256) {
        float2 v = *(const float2*)(p + 2 * i);
        m = fmaxf(m, fmaxf(v.x, v.y));
    }
    red[tid] = m; __syncthreads();
    for (int off = 128; off > 0; off >>= 1) { if (tid < off) red[tid] = fmaxf(red[tid], red[tid + off]); __syncthreads(); }
    m = red[0]; __syncthreads();
    float sum = 0.f;
    for (int i = tid; i < S_ / 2; i += 256) {
        float2 v = *(const float2*)(p + 2 * i);
        v.x = expf(v.x - m); v.y = expf(v.y - m);
        *(float2*)(p + 2 * i) = v;
        sum += v.x + v.y;
    }
    red[tid] = sum; __syncthreads();
    for (int off = 128; off > 0; off >>= 1) { if (tid < off) red[tid] += red[tid + off]; __syncthreads(); }
    float inv = 1.0f / red[0];
    for (int i = tid; i < S_ / 2; i += 256) {
        float2 v = *(const float2*)(p + 2 * i);
        o[i] = split_pair(make_float2(v.x * inv, v.y * inv));
    }
}

#define LN_CH (S_*D_/128)   // 6144
__global__ void ln_part(const float* __restrict__ a, const float* __restrict__ r,
                        double* __restrict__ part) {
    int b = blockIdx.y, c = blockIdx.x, tid = threadIdx.x;
    size_t base = (size_t)b * (S_*D_) + (size_t)c * LN_CH;
    double s = 0.0, s2 = 0.0;
    for (int i = tid; i < LN_CH; i += 256) {
        float v = a[base + i] + r[base + i];
        s += v; s2 += (double)v * v;
    }
    __shared__ double m1[256], m2[256];
    m1[tid] = s; m2[tid] = s2; __syncthreads();
    for (int o = 128; o > 0; o >>= 1) {
        if (tid < o) { m1[tid] += m1[tid + o]; m2[tid] += m2[tid + o]; }
        __syncthreads();
    }
    if (tid == 0) { part[(b * 128 + c) * 2] = m1[0]; part[(b * 128 + c) * 2 + 1] = m2[0]; }
}
__global__ void ln_stats(const double* __restrict__ part, double* __restrict__ stats) {
    int b = blockIdx.x, tid = threadIdx.x;
    __shared__ double m1[128], m2[128];
    m1[tid] = part[(b * 128 + tid) * 2];
    m2[tid] = part[(b * 128 + tid) * 2 + 1];
    __syncthreads();
    for (int o = 64; o > 0; o >>= 1) {
        if (tid < o) { m1[tid] += m1[tid + o]; m2[tid] += m2[tid + o]; }
        __syncthreads();
    }
    if (tid == 0) {
        double mean = m1[0] / (S_*D_);
        double var  = m2[0] / (S_*D_) - mean * mean;
        stats[b * 2] = mean;
        stats[b * 2 + 1] = 1.0 / sqrt(var + 1e-5);
    }
}
template<int SPLIT>
__global__ void ln_apply(const float* __restrict__ a, const float* __restrict__ r,
                         const float* __restrict__ w, const float* __restrict__ bb,
                         const double* __restrict__ stats,
                         float* __restrict__ out, uint2* __restrict__ osp) {
    int b = blockIdx.y, c = blockIdx.x, tid = threadIdx.x;
    size_t base = (size_t)b * (S_*D_) + (size_t)c * LN_CH;
    size_t sl = (size_t)c * LN_CH;
    float mean = (float)stats[b * 2];
    float rstd = (float)stats[b * 2 + 1];
    for (int i = tid; i < LN_CH / 2; i += 256) {
        float2 av_ = *(const float2*)(a + base + 2 * i);
        float2 rv  = *(const float2*)(r + base + 2 * i);
        float2 wv  = *(const float2*)(w + sl + 2 * i);
        float2 bv  = *(const float2*)(bb + sl + 2 * i);
        float2 v;
        v.x = (av_.x + rv.x - mean) * rstd * wv.x + bv.x;
        v.y = (av_.y + rv.y - mean) * rstd * wv.y + bv.y;
        *(float2*)(out + base + 2 * i) = v;
        if (SPLIT) osp[(base >> 1) + i] = split_pair(v);
    }
}

// ------------------------------------------------------------------ launch --
extern "C" void kernel_launch(void* const* d_in, const int* in_sizes, int n_in,
                              void* d_out, int out_size) {
    const int*   x    = (const int*)  d_in[0];
    const float* emb  = (const float*)d_in[1];
    const float* Wq   = (const float*)d_in[2];
    const float* bq   = (const float*)d_in[3];
    const float* Wk   = (const float*)d_in[4];
    const float* bk   = (const float*)d_in[5];
    const float* Wv   = (const float*)d_in[6];
    const float* bv   = (const float*)d_in[7];
    const float* Wo   = (const float*)d_in[8];
    const float* bo   = (const float*)d_in[9];
    const float* W1   = (const float*)d_in[10];
    const float* b1   = (const float*)d_in[11];
    const float* W2   = (const float*)d_in[12];
    const float* b2   = (const float*)d_in[13];
    const float* ln1w = (const float*)d_in[14];
    const float* ln1b = (const float*)d_in[15];
    const float* ln2w = (const float*)d_in[16];
    const float* ln2b = (const float*)d_in[17];
    float* out = (float*)d_out;

    float *pe, *y, *s, *ao, *y1, *f;
    uint2 *ysp, *y1sp, *qsp, *ksp, *vTsp, *ssp, *avsp, *h1sp;
    uint2 *wqt, *wkt, *wvt, *wot, *w1t, *w2t;
    double *part, *stats;
    cudaGetSymbolAddress((void**)&pe,   g_pe);
    cudaGetSymbolAddress((void**)&y,    g_y);
    cudaGetSymbolAddress((void**)&s,    g_s);
    cudaGetSymbolAddress((void**)&ao,   g_ao);
    cudaGetSymbolAddress((void**)&y1,   g_y1);
    cudaGetSymbolAddress((void**)&f,    g_f);
    cudaGetSymbolAddress((void**)&ysp,  g_ysp);
    cudaGetSymbolAddress((void**)&y1sp, g_y1sp);
    cudaGetSymbolAddress((void**)&qsp,  g_qsp);
    cudaGetSymbolAddress((void**)&ksp,  g_ksp);
    cudaGetSymbolAddress((void**)&vTsp, g_vTsp);
    cudaGetSymbolAddress((void**)&ssp,  g_ssp);
    cudaGetSymbolAddress((void**)&avsp, g_avsp);
    cudaGetSymbolAddress((void**)&h1sp, g_h1sp);
    cudaGetSymbolAddress((void**)&wqt,  g_wqt);
    cudaGetSymbolAddress((void**)&wkt,  g_wkt);
    cudaGetSymbolAddress((void**)&wvt,  g_wvt);
    cudaGetSymbolAddress((void**)&wot,  g_wot);
    cudaGetSymbolAddress((void**)&w1t,  g_w1t);
    cudaGetSymbolAddress((void**)&w2t,  g_w2t);
    cudaGetSymbolAddress((void**)&part,  g_part);
    cudaGetSymbolAddress((void**)&stats, g_stats);

    cudaFuncSetAttribute(hgemm<2,1,1,0>, cudaFuncAttributeMaxDynamicSharedMemorySize, SMEM_SZ);
    cudaFuncSetAttribute(hgemm<3,2,1,0>, cudaFuncAttributeMaxDynamicSharedMemorySize, SMEM_SZ);
    cudaFuncSetAttribute(hgemm<1,0,0,0>, cudaFuncAttributeMaxDynamicSharedMemorySize, SMEM_SZ);
    cudaFuncSetAttribute(hgemm<2,0,1,0>, cudaFuncAttributeMaxDynamicSharedMemorySize, SMEM_SZ);
    cudaFuncSetAttribute(hgemm<2,1,0,0>, cudaFuncAttributeMaxDynamicSharedMemorySize, SMEM_SZ);
    cudaFuncSetAttribute(hgemm<3,1,0,1>, cudaFuncAttributeMaxDynamicSharedMemorySize, SMEM_SZ);

    // 0. weights -> transposed split-pair
    transpose_split<<<dim3(H_/32, D_/32), dim3(32,8)>>>(Wq, wqt, D_, H_);
    transpose_split<<<dim3(H_/32, D_/32), dim3(32,8)>>>(Wk, wkt, D_, H_);
    transpose_split<<<dim3(H_/32, D_/32), dim3(32,8)>>>(Wv, wvt, D_, H_);
    transpose_split<<<dim3(D_/32, H_/32), dim3(32,8)>>>(Wo, wot, H_, D_);
    transpose_split<<<dim3(H_/32, D_/32), dim3(32,8)>>>(W1, w1t, D_, H_);
    transpose_split<<<dim3(D_/32, H_/32), dim3(32,8)>>>(W2, w2t, H_, D_);

    // 1. embedding + PE (fp32 + split)
    pe_kernel<<<(S_*D_ + 255)/256, 256>>>(pe);
    embed_kernel<<<T_, 256>>>(x, emb, pe, y, ysp);

    // 2. q,k  (M=T, N=H, K=D) 2-pass (feeds 1-pass QK; error below fp16 quant), split out
    hgemm<2,1,1,0><<<dim3(H_/128, T_/128), 256, SMEM_SZ>>>(ysp, wqt, bq, qsp, H_, D_, 0, 0, 0);
    hgemm<2,1,1,0><<<dim3(H_/128, T_/128), 256, SMEM_SZ>>>(ysp, wkt, bk, ksp, H_, D_, 0, 0, 0);

    // 3. vT_b = wvt @ y_b^T + bv(row)  (M=H, N=S, K=D) 3-pass (lo consumed by PV)
    hgemm<3,2,1,0><<<dim3(S_/128, H_/128, B_), 256, SMEM_SZ>>>(
        wvt, ysp, bv, vTsp, S_, D_, 0, (ll)S_*D_/2, (ll)H_*S_/2);

    // 4. scores_b = q_b @ k_b^T  (M=N=S, K=H) 1-pass, f32 out
    hgemm<1,0,0,0><<<dim3(S_/128, S_/128, B_), 256, SMEM_SZ>>>(
        qsp, ksp, nullptr, s, S_, H_, (ll)S_*H_/2, (ll)S_*H_/2, (ll)S_*S_);

    // 5. softmax -> split probs
    softmax_split<<<B_*S_, 256>>>(s, ssp);

    // 6. av_b = attn_b @ vT_b^T  (M=S, N=H, K=S) 2-pass, split out
    hgemm<2,0,1,0><<<dim3(H_/128, S_/128, B_), 256, SMEM_SZ>>>(
        ssp, vTsp, nullptr, avsp, H_, S_, (ll)S_*S_/2, (ll)H_*S_/2, (ll)S_*H_/2);

    // 7. ao = av @ wot^T + bo  (M=T, N=D, K=H) 2-pass (residual-diluted), f32 out
    hgemm<2,1,0,0><<<dim3(D_/128, T_/128), 256, SMEM_SZ>>>(avsp, wot, bo, ao, D_, H_, 0, 0, 0);

    // 8. LN1: y1 = LN(y + ao)  (fp32 + split)
    ln_part <<<dim3(128, B_), 256>>>(y, ao, part);
    ln_stats<<<B_, 128>>>(part, stats);
    ln_apply<1><<<dim3(128, B_), 256>>>(y, ao, ln1w, ln1b, stats, y1, y1sp);

    // 9. FFN: h1 = y1@W1+b1 2-pass (split);  f = gelu(h1@W2+b2) 3-pass (fp32)
    hgemm<2,1,1,0><<<dim3(H_/128, T_/128), 256, SMEM_SZ>>>(y1sp, w1t, b1, h1sp, H_, D_, 0, 0, 0);
    hgemm<3,1,0,1><<<dim3(D_/128, T_/128), 256, SMEM_SZ>>>(h1sp, w2t, b2, f, D_, H_, 0, 0, 0);

    // 10. LN2 -> out (fp32 only)
    ln_part <<<dim3(128, B_), 256>>>(y1, f, part);
    ln_stats<<<B_, 128>>>(part, stats);
    ln_apply<0><<<dim3(128, B_), 256>>>(y1, f, ln2w, ln2b, stats, out, nullptr);
}

// round 7
// speedup vs baseline: 3.6402x; 1.0878x over previous
#include <cuda_runtime.h>
#include <cuda_fp16.h>
#include <math.h>
#include <cstdint>

#define B_ 8
#define S_ 1024
#define D_ 768
#define H_ 3072
#define T_ (B_*S_)

typedef long long ll;

// ---------------- scratch: split-pair (uint2 = {half2 hi, half2 lo} / 2 elems)
static __device__ uint2 g_ysp  [T_*D_/2];
static __device__ uint2 g_y1sp [T_*D_/2];
static __device__ uint2 g_qsp  [T_*H_/2];
static __device__ uint2 g_ksp  [T_*H_/2];
static __device__ uint2 g_vTsp [B_*H_*S_/2];
static __device__ uint2 g_ssp  [B_*S_*S_/2];
static __device__ uint2 g_avsp [T_*H_/2];
static __device__ uint2 g_h1sp [T_*H_/2];
static __device__ uint2 g_wqt  [H_*D_/2];
static __device__ uint2 g_wkt  [H_*D_/2];
static __device__ uint2 g_wvt  [H_*D_/2];
static __device__ uint2 g_wot  [D_*H_/2];
static __device__ uint2 g_w1t  [H_*D_/2];
static __device__ uint2 g_w2t  [D_*H_/2];
// fp32 scratch
static __device__ float g_pe [S_*D_];
static __device__ float g_y  [T_*D_];
static __device__ float g_s  [B_*S_*S_];
static __device__ float g_ao [T_*D_];
static __device__ float g_y1 [T_*D_];
static __device__ float g_f  [T_*D_];
static __device__ double g_part[B_*128*2];
static __device__ double g_stats[B_*2];

// ------------------------------------------------------------- helpers ------
__device__ __forceinline__ uint32_t smem_u32(const void* p) {
    uint32_t a;
    asm("{ .reg .u64 t; cvta.to.shared.u64 t, %1; cvt.u32.u64 %0, t; }" : "=r"(a) : "l"(p));
    return a;
}
#define CP16(dst, src) \
    asm volatile("cp.async.cg.shared.global [%0], [%1], 16;" :: "r"(dst), "l"(src) : "memory")
#define CP_COMMIT() asm volatile("cp.async.commit_group;" ::: "memory")
#define CP_WAIT0()  asm volatile("cp.async.wait_group 0;" ::: "memory")

__device__ __forceinline__ uint2 split_pair(float2 v) {
    __half2 h = __float22half2_rn(v);
    float2 hf = __half22float2(h);
    __half2 l = __float22half2_rn(make_float2(v.x - hf.x, v.y - hf.y));
    uint2 o;
    o.x = *reinterpret_cast<uint32_t*>(&h);
    o.y = *reinterpret_cast<uint32_t*>(&l);
    return o;
}

// f32-accumulator HMMA (main term)
__device__ __forceinline__ void mma_f16(float* c, const uint32_t* a, const uint32_t* b) {
    asm volatile(
        "mma.sync.aligned.m16n8k16.row.col.f32.f16.f16.f32 "
        "{%0,%1,%2,%3}, {%4,%5,%6,%7}, {%8,%9}, {%0,%1,%2,%3};"
        : "+f"(c[0]), "+f"(c[1]), "+f"(c[2]), "+f"(c[3])
        : "r"(a[0]), "r"(a[1]), "r"(a[2]), "r"(a[3]), "r"(b[0]), "r"(b[1]));
}
// f16-accumulator HMMA (small correction term; potentially 2x rate)
__device__ __forceinline__ void mma_f16acc(uint32_t* c, const uint32_t* a, const uint32_t* b) {
    asm volatile(
        "mma.sync.aligned.m16n8k16.row.col.f16.f16.f16.f16 "
        "{%0,%1}, {%2,%3,%4,%5}, {%6,%7}, {%0,%1};"
        : "+r"(c[0]), "+r"(c[1])
        : "r"(a[0]), "r"(a[1]), "r"(a[2]), "r"(a[3]), "r"(b[0]), "r"(b[1]));
}

__device__ __forceinline__ float gelu_exact(float v) {
    return 0.5f * v * (1.0f + erff(v * 0.70710678118654752f));
}

// smem tile: 128 rows x 16 uint2 (32 elems), padded row stride 20 uint2 = 160B
#define RSTR_B   160
#define TILE_B   (128 * RSTR_B)          // 20480
#define BUF_B    (2 * TILE_B)            // 40960 (A + B)
#define SMEM_SZ  (2 * BUF_B)             // 81920

// ---------------------------------------------------------------------------
// fp16-split GEMM: C[M,N] = A[M,K]*B[N,K]^T, inputs in split-pair format.
// 128x128 tile, Kstage=32, 256 thr (warps 2m x 4n), single-sync double buffer.
// PASSES: 2 = ah*bl (f16 acc) + ah*bh (f32 acc),  1 = ah*bh only
// BIASMODE: 0 none, 1 col bias[n], 2 row bias[m]. OUTSPLIT: C split-pair else f32
// ---------------------------------------------------------------------------
template<int PASSES, int BIASMODE, int OUTSPLIT, int GELU>
__global__ void __launch_bounds__(256, 2)
hgemm(const uint2* __restrict__ A, const uint2* __restrict__ B,
      const float* __restrict__ bias, void* __restrict__ Cout,
      int N_, int K_, ll sA, ll sB, ll sC) {
    extern __shared__ char smraw[];
    A += (ll)blockIdx.z * sA;
    B += (ll)blockIdx.z * sB;
    float* Cf = (float*)Cout + (OUTSPLIT ? 0 : (ll)blockIdx.z * sC);
    uint2* Cs = (uint2*)Cout + (OUTSPLIT ? (ll)blockIdx.z * sC : 0);

    const int tid = threadIdx.x, lane = tid & 31, wid = tid >> 5;
    const int wm = wid >> 2, wn = wid & 3;
    const int bm = blockIdx.y << 7, bn = blockIdx.x << 7;
    const int Kp = K_ >> 1;
    const uint32_t sbase = smem_u32(smraw);

    float acc[4][4][4];
    uint32_t accC[4][4][2];
#pragma unroll
    for (int mt = 0; mt < 4; mt++)
#pragma unroll
        for (int nt = 0; nt < 4; nt++) {
#pragma unroll
            for (int r = 0; r < 4; r++) acc[mt][nt][r] = 0.0f;
            accC[mt][nt][0] = 0u; accC[mt][nt][1] = 0u;
        }

    // loaders: i = tid + j*256 in [0,1024): row=i>>3, chunk=i&7 (16B = 2 uint2)
    int lrow[4], lc[4];
#pragma unroll
    for (int j = 0; j < 4; j++) { int i = tid + (j << 8); lrow[j] = i >> 3; lc[j] = i & 7; }

    const int nst = K_ >> 5;

    // prologue: stage 0 into buf 0
#pragma unroll
    for (int j = 0; j < 4; j++) {
        const uint2* ga = A + (size_t)(bm + lrow[j]) * Kp + (lc[j] << 1);
        const uint2* gb = B + (size_t)(bn + lrow[j]) * Kp + (lc[j] << 1);
        uint32_t so = sbase + lrow[j] * RSTR_B + (lc[j] << 4);
        CP16(so, ga);
        CP16(so + TILE_B, gb);
    }
    CP_COMMIT();

    for (int s = 0; s < nst; s++) {
        CP_WAIT0();
        __syncthreads();

        if (s + 1 < nst) {
            const int kp0 = (s + 1) << 4;
            const uint32_t boff = ((s + 1) & 1) * BUF_B;
#pragma unroll
            for (int j = 0; j < 4; j++) {
                const uint2* ga = A + (size_t)(bm + lrow[j]) * Kp + kp0 + (lc[j] << 1);
                const uint2* gb = B + (size_t)(bn + lrow[j]) * Kp + kp0 + (lc[j] << 1);
                uint32_t so = sbase + boff + lrow[j] * RSTR_B + (lc[j] << 4);
                CP16(so, ga);
                CP16(so + TILE_B, gb);
            }
            CP_COMMIT();
        }

        const uint32_t Asm = sbase + (s & 1) * BUF_B;
        const uint32_t Bsm = Asm + TILE_B;
        const int poff = (lane & 3) << 3;

#pragma unroll
        for (int kc = 0; kc < 2; kc++) {
            const uint32_t kb = (kc << 6) + poff;
            uint32_t bh[4][2], bl[4][2];
#pragma unroll
            for (int nt = 0; nt < 4; nt++) {
                uint32_t ba = Bsm + (wn * 32 + nt * 8 + (lane >> 2)) * RSTR_B + kb;
                asm volatile("ld.shared.v2.b32 {%0,%1}, [%2];" : "=r"(bh[nt][0]), "=r"(bl[nt][0]) : "r"(ba));
                asm volatile("ld.shared.v2.b32 {%0,%1}, [%2];" : "=r"(bh[nt][1]), "=r"(bl[nt][1]) : "r"(ba + 32));
            }
#pragma unroll
            for (int mt = 0; mt < 4; mt++) {
                uint32_t aa = Asm + (wm * 64 + mt * 16 + (lane >> 2)) * RSTR_B + kb;
                uint32_t ah[4], al[4];
                asm volatile("ld.shared.v2.b32 {%0,%1}, [%2];" : "=r"(ah[0]), "=r"(al[0]) : "r"(aa));
                asm volatile("ld.shared.v2.b32 {%0,%1}, [%2];" : "=r"(ah[1]), "=r"(al[1]) : "r"(aa + 8 * RSTR_B));
                asm volatile("ld.shared.v2.b32 {%0,%1}, [%2];" : "=r"(ah[2]), "=r"(al[2]) : "r"(aa + 32));
                asm volatile("ld.shared.v2.b32 {%0,%1}, [%2];" : "=r"(ah[3]), "=r"(al[3]) : "r"(aa + 8 * RSTR_B + 32));
#pragma unroll
                for (int nt = 0; nt < 4; nt++) {
                    if (PASSES >= 2) mma_f16acc(accC[mt][nt], ah, bl[nt]);
                    mma_f16(acc[mt][nt], ah, bh[nt]);
                }
            }
        }
    }

    __syncthreads();

    // epilogue: fold f16 corrections into f32 acc, then bias/gelu/store
#pragma unroll
    for (int mt = 0; mt < 4; mt++) {
        const int m0 = bm + wm * 64 + mt * 16 + (lane >> 2);
#pragma unroll
        for (int nt = 0; nt < 4; nt++) {
            float v00 = acc[mt][nt][0], v01 = acc[mt][nt][1];
            float v10 = acc[mt][nt][2], v11 = acc[mt][nt][3];
            if (PASSES >= 2) {
                __half2 c0 = *reinterpret_cast<__half2*>(&accC[mt][nt][0]);
                __half2 c1 = *reinterpret_cast<__half2*>(&accC[mt][nt][1]);
                float2 f0 = __half22float2(c0);
                float2 f1 = __half22float2(c1);
                v00 += f0.x; v01 += f0.y; v10 += f1.x; v11 += f1.y;
            }
            const int n0 = bn + wn * 32 + nt * 8 + ((lane & 3) << 1);
            if (BIASMODE == 1) {
                float2 bb = *(const float2*)&bias[n0];
                v00 += bb.x; v01 += bb.y; v10 += bb.x; v11 += bb.y;
            } else if (BIASMODE == 2) {
                float r0 = bias[m0], r1 = bias[m0 + 8];
                v00 += r0; v01 += r0; v10 += r1; v11 += r1;
            }
            if (GELU) {
                v00 = gelu_exact(v00); v01 = gelu_exact(v01);
                v10 = gelu_exact(v10); v11 = gelu_exact(v11);
            }
            if (OUTSPLIT) {
                Cs[((size_t)m0 * N_ + n0) >> 1]       = split_pair(make_float2(v00, v01));
                Cs[((size_t)(m0 + 8) * N_ + n0) >> 1] = split_pair(make_float2(v10, v11));
            } else {
                *(float2*)&Cf[(size_t)m0 * N_ + n0]       = make_float2(v00, v01);
                *(float2*)&Cf[(size_t)(m0 + 8) * N_ + n0] = make_float2(v10, v11);
            }
        }
    }
}

// ------------------------------------------------------------- aux kernels --
__global__ void pe_kernel(float* __restrict__ pe) {
    int i = blockIdx.x * blockDim.x + threadIdx.x;
    if (i >= S_ * D_) return;
    int s = i / D_, d = i % D_;
    double ang = (double)s * exp(-9.210340371976184 * ((double)d / (double)D_));
    float a = (float)fmod(ang, 6.283185307179586);
    pe[i] = (d & 1) ? cosf(a) : sinf(a);
}

__global__ void embed_kernel(const int* __restrict__ x, const float* __restrict__ emb,
                             const float* __restrict__ pe,
                             float* __restrict__ y, uint2* __restrict__ ysp) {
    int t = blockIdx.x;
    int s = t & (S_ - 1);
    ll row = x[t];
    const float* er = emb + row * (ll)D_;
    const float* pr = pe + (ll)s * D_;
    float* yr = y + (ll)t * D_;
    uint2* yp = ysp + (ll)t * (D_ / 2);
    for (int p = threadIdx.x; p < D_ / 2; p += blockDim.x) {
        float2 e = *(const float2*)(er + 2 * p);
        float2 q = *(const float2*)(pr + 2 * p);
        float2 v = make_float2(e.x + q.x, e.y + q.y);
        *(float2*)(yr + 2 * p) = v;
        yp[p] = split_pair(v);
    }
}

// transpose [R][C] fp32 -> [C][R] split-pair
__global__ void transpose_split(const float* __restrict__ in, uint2* __restrict__ out,
                                int R, int C) {
    __shared__ float t[32][33];
    int rb = blockIdx.y * 32, cb = blockIdx.x * 32;
#pragma unroll
    for (int i = 0; i < 32; i += 8)
        t[threadIdx.y + i][threadIdx.x] = in[(size_t)(rb + threadIdx.y + i) * C + cb + threadIdx.x];
    __syncthreads();
    int tid = threadIdx.y * 32 + threadIdx.x;
#pragma unroll
    for (int j = 0; j < 2; j++) {
        int pidx = tid + j * 256;
        int c = pidx >> 4, pr = pidx & 15;
        float2 v = make_float2(t[2 * pr][c], t[2 * pr + 1][c]);
        out[(size_t)(cb + c) * (R >> 1) + (rb >> 1) + pr] = split_pair(v);
    }
}

__global__ void softmax_split(float* __restrict__ s, uint2* __restrict__ sp) {
    float* p = s + (ll)blockIdx.x * S_;
    uint2* o = sp + (ll)blockIdx.x * (S_ / 2);
    __shared__ float red[256];
    int tid = threadIdx.x;
    float m = -1e30f;
    for (int i = tid; i < S_ / 2; i += 256) {
        float2 v = *(const float2*)(p + 2 * i);
        m = fmaxf(m, fmaxf(v.x, v.y));
    }
    red[tid] = m; __syncthreads();
    for (int off = 128; off > 0; off >>= 1) { if (tid < off) red[tid] = fmaxf(red[tid], red[tid + off]); __syncthreads(); }
    m = red[0]; __syncthreads();
    float sum = 0.f;
    for (int i = tid; i < S_ / 2; i += 256) {
        float2 v = *(const float2*)(p + 2 * i);
        v.x = expf(v.x - m); v.y = expf(v.y - m);
        *(float2*)(p + 2 * i) = v;
        sum += v.x + v.y;
    }
    red[tid] = sum; __syncthreads();
    for (int off = 128; off > 0; off >>= 1) { if (tid < off) red[tid] += red[tid + off]; __syncthreads(); }
    float inv = 1.0f / red[0];
    for (int i = tid; i < S_ / 2; i += 256) {
        float2 v = *(const float2*)(p + 2 * i);
        o[i] = split_pair(make_float2(v.x * inv, v.y * inv));
    }
}

#define LN_CH (S_*D_/128)   // 6144
__global__ void ln_part(const float* __restrict__ a, const float* __restrict__ r,
                        double* __restrict__ part) {
    int b = blockIdx.y, c = blockIdx.x, tid = threadIdx.x;
    size_t base = (size_t)b * (S_*D_) + (size_t)c * LN_CH;
    double s = 0.0, s2 = 0.0;
    for (int i = tid; i < LN_CH; i += 256) {
        float v = a[base + i] + r[base + i];
        s += v; s2 += (double)v * v;
    }
    __shared__ double m1[256], m2[256];
    m1[tid] = s; m2[tid] = s2; __syncthreads();
    for (int o = 128; o > 0; o >>= 1) {
        if (tid < o) { m1[tid] += m1[tid + o]; m2[tid] += m2[tid + o]; }
        __syncthreads();
    }
    if (tid == 0) { part[(b * 128 + c) * 2] = m1[0]; part[(b * 128 + c) * 2 + 1] = m2[0]; }
}
__global__ void ln_stats(const double* __restrict__ part, double* __restrict__ stats) {
    int b = blockIdx.x, tid = threadIdx.x;
    __shared__ double m1[128], m2[128];
    m1[tid] = part[(b * 128 + tid) * 2];
    m2[tid] = part[(b * 128 + tid) * 2 + 1];
    __syncthreads();
    for (int o = 64; o > 0; o >>= 1) {
        if (tid < o) { m1[tid] += m1[tid + o]; m2[tid] += m2[tid + o]; }
        __syncthreads();
    }
    if (tid == 0) {
        double mean = m1[0] / (S_*D_);
        double var  = m2[0] / (S_*D_) - mean * mean;
        stats[b * 2] = mean;
        stats[b * 2 + 1] = 1.0 / sqrt(var + 1e-5);
    }
}
template<int SPLIT>
__global__ void ln_apply(const float* __restrict__ a, const float* __restrict__ r,
                         const float* __restrict__ w, const float* __restrict__ bb,
                         const double* __restrict__ stats,
                         float* __restrict__ out, uint2* __restrict__ osp) {
    int b = blockIdx.y, c = blockIdx.x, tid = threadIdx.x;
    size_t base = (size_t)b * (S_*D_) + (size_t)c * LN_CH;
    size_t sl = (size_t)c * LN_CH;
    float mean = (float)stats[b * 2];
    float rstd = (float)stats[b * 2 + 1];
    for (int i = tid; i < LN_CH / 2; i += 256) {
        float2 av_ = *(const float2*)(a + base + 2 * i);
        float2 rv  = *(const float2*)(r + base + 2 * i);
        float2 wv  = *(const float2*)(w + sl + 2 * i);
        float2 bv  = *(const float2*)(bb + sl + 2 * i);
        float2 v;
        v.x = (av_.x + rv.x - mean) * rstd * wv.x + bv.x;
        v.y = (av_.y + rv.y - mean) * rstd * wv.y + bv.y;
        *(float2*)(out + base + 2 * i) = v;
        if (SPLIT) osp[(base >> 1) + i] = split_pair(v);
    }
}

// ------------------------------------------------------------------ launch --
extern "C" void kernel_launch(void* const* d_in, const int* in_sizes, int n_in,
                              void* d_out, int out_size) {
    const int*   x    = (const int*)  d_in[0];
    const float* emb  = (const float*)d_in[1];
    const float* Wq   = (const float*)d_in[2];
    const float* bq   = (const float*)d_in[3];
    const float* Wk   = (const float*)d_in[4];
    const float* bk   = (const float*)d_in[5];
    const float* Wv   = (const float*)d_in[6];
    const float* bv   = (const float*)d_in[7];
    const float* Wo   = (const float*)d_in[8];
    const float* bo   = (const float*)d_in[9];
    const float* W1   = (const float*)d_in[10];
    const float* b1   = (const float*)d_in[11];
    const float* W2   = (const float*)d_in[12];
    const float* b2   = (const float*)d_in[13];
    const float* ln1w = (const float*)d_in[14];
    const float* ln1b = (const float*)d_in[15];
    const float* ln2w = (const float*)d_in[16];
    const float* ln2b = (const float*)d_in[17];
    float* out = (float*)d_out;

    float *pe, *y, *s, *ao, *y1, *f;
    uint2 *ysp, *y1sp, *qsp, *ksp, *vTsp, *ssp, *avsp, *h1sp;
    uint2 *wqt, *wkt, *wvt, *wot, *w1t, *w2t;
    double *part, *stats;
    cudaGetSymbolAddress((void**)&pe,   g_pe);
    cudaGetSymbolAddress((void**)&y,    g_y);
    cudaGetSymbolAddress((void**)&s,    g_s);
    cudaGetSymbolAddress((void**)&ao,   g_ao);
    cudaGetSymbolAddress((void**)&y1,   g_y1);
    cudaGetSymbolAddress((void**)&f,    g_f);
    cudaGetSymbolAddress((void**)&ysp,  g_ysp);
    cudaGetSymbolAddress((void**)&y1sp, g_y1sp);
    cudaGetSymbolAddress((void**)&qsp,  g_qsp);
    cudaGetSymbolAddress((void**)&ksp,  g_ksp);
    cudaGetSymbolAddress((void**)&vTsp, g_vTsp);
    cudaGetSymbolAddress((void**)&ssp,  g_ssp);
    cudaGetSymbolAddress((void**)&avsp, g_avsp);
    cudaGetSymbolAddress((void**)&h1sp, g_h1sp);
    cudaGetSymbolAddress((void**)&wqt,  g_wqt);
    cudaGetSymbolAddress((void**)&wkt,  g_wkt);
    cudaGetSymbolAddress((void**)&wvt,  g_wvt);
    cudaGetSymbolAddress((void**)&wot,  g_wot);
    cudaGetSymbolAddress((void**)&w1t,  g_w1t);
    cudaGetSymbolAddress((void**)&w2t,  g_w2t);
    cudaGetSymbolAddress((void**)&part,  g_part);
    cudaGetSymbolAddress((void**)&stats, g_stats);

    cudaFuncSetAttribute(hgemm<2,1,1,0>, cudaFuncAttributeMaxDynamicSharedMemorySize, SMEM_SZ);
    cudaFuncSetAttribute(hgemm<2,2,1,0>, cudaFuncAttributeMaxDynamicSharedMemorySize, SMEM_SZ);
    cudaFuncSetAttribute(hgemm<1,0,0,0>, cudaFuncAttributeMaxDynamicSharedMemorySize, SMEM_SZ);
    cudaFuncSetAttribute(hgemm<2,0,1,0>, cudaFuncAttributeMaxDynamicSharedMemorySize, SMEM_SZ);
    cudaFuncSetAttribute(hgemm<2,1,0,0>, cudaFuncAttributeMaxDynamicSharedMemorySize, SMEM_SZ);
    cudaFuncSetAttribute(hgemm<2,1,0,1>, cudaFuncAttributeMaxDynamicSharedMemorySize, SMEM_SZ);

    // 0. weights -> transposed split-pair
    transpose_split<<<dim3(H_/32, D_/32), dim3(32,8)>>>(Wq, wqt, D_, H_);
    transpose_split<<<dim3(H_/32, D_/32), dim3(32,8)>>>(Wk, wkt, D_, H_);
    transpose_split<<<dim3(H_/32, D_/32), dim3(32,8)>>>(Wv, wvt, D_, H_);
    transpose_split<<<dim3(D_/32, H_/32), dim3(32,8)>>>(Wo, wot, H_, D_);
    transpose_split<<<dim3(H_/32, D_/32), dim3(32,8)>>>(W1, w1t, D_, H_);
    transpose_split<<<dim3(D_/32, H_/32), dim3(32,8)>>>(W2, w2t, H_, D_);

    // 1. embedding + PE (fp32 + split)
    pe_kernel<<<(S_*D_ + 255)/256, 256>>>(pe);
    embed_kernel<<<T_, 256>>>(x, emb, pe, y, ysp);

    // 2. q,k  (M=T, N=H, K=D) 2-pass, split out
    hgemm<2,1,1,0><<<dim3(H_/128, T_/128), 256, SMEM_SZ>>>(ysp, wqt, bq, qsp, H_, D_, 0, 0, 0);
    hgemm<2,1,1,0><<<dim3(H_/128, T_/128), 256, SMEM_SZ>>>(ysp, wkt, bk, ksp, H_, D_, 0, 0, 0);

    // 3. vT_b = wvt @ y_b^T + bv(row)  (M=H, N=S, K=D) 2-pass, split out
    hgemm<2,2,1,0><<<dim3(S_/128, H_/128, B_), 256, SMEM_SZ>>>(
        wvt, ysp, bv, vTsp, S_, D_, 0, (ll)S_*D_/2, (ll)H_*S_/2);

    // 4. scores_b = q_b @ k_b^T  (M=N=S, K=H) 1-pass, f32 out
    hgemm<1,0,0,0><<<dim3(S_/128, S_/128, B_), 256, SMEM_SZ>>>(
        qsp, ksp, nullptr, s, S_, H_, (ll)S_*H_/2, (ll)S_*H_/2, (ll)S_*S_);

    // 5. softmax -> split probs
    softmax_split<<<B_*S_, 256>>>(s, ssp);

    // 6. av_b = attn_b @ vT_b^T  (M=S, N=H, K=S) 2-pass, split out
    hgemm<2,0,1,0><<<dim3(H_/128, S_/128, B_), 256, SMEM_SZ>>>(
        ssp, vTsp, nullptr, avsp, H_, S_, (ll)S_*S_/2, (ll)H_*S_/2, (ll)S_*H_/2);

    // 7. ao = av @ wot^T + bo  (M=T, N=D, K=H) 2-pass, f32 out
    hgemm<2,1,0,0><<<dim3(D_/128, T_/128), 256, SMEM_SZ>>>(avsp, wot, bo, ao, D_, H_, 0, 0, 0);

    // 8. LN1: y1 = LN(y + ao)  (fp32 + split)
    ln_part <<<dim3(128, B_), 256>>>(y, ao, part);
    ln_stats<<<B_, 128>>>(part, stats);
    ln_apply<1><<<dim3(128, B_), 256>>>(y, ao, ln1w, ln1b, stats, y1, y1sp);

    // 9. FFN: h1 = y1@W1+b1 2-pass (split);  f = gelu(h1@W2+b2) 2-pass (fp32)
    hgemm<2,1,1,0><<<dim3(H_/128, T_/128), 256, SMEM_SZ>>>(y1sp, w1t, b1, h1sp, H_, D_, 0, 0, 0);
    hgemm<2,1,0,1><<<dim3(D_/128, T_/128), 256, SMEM_SZ>>>(h1sp, w2t, b2, f, D_, H_, 0, 0, 0);

    // 10. LN2 -> out (fp32 only)
    ln_part <<<dim3(128, B_), 256>>>(y1, f, part);
    ln_stats<<<B_, 128>>>(part, stats);
    ln_apply<0><<<dim3(128, B_), 256>>>(y1, f, ln2w, ln2b, stats, out, nullptr);
}

// round 8
// speedup vs baseline: 4.2507x; 1.1677x over previous
#include <cuda_runtime.h>
#include <cuda_fp16.h>
#include <math.h>
#include <cstdint>

#define B_ 8
#define S_ 1024
#define D_ 768
#define H_ 3072
#define T_ (B_*S_)

typedef long long ll;

// ---------------- scratch: split-pair (uint2 = {half2 hi, half2 lo} / 2 elems)
static __device__ uint2 g_ysp  [T_*D_/2];
static __device__ uint2 g_y1sp [T_*D_/2];
static __device__ uint2 g_qsp  [T_*H_/2];
static __device__ uint2 g_ksp  [T_*H_/2];
static __device__ uint2 g_vTsp [B_*H_*S_/2];
static __device__ uint2 g_ssp  [B_*S_*S_/2];
static __device__ uint2 g_avsp [T_*H_/2];
static __device__ uint2 g_h1sp [T_*H_/2];
static __device__ uint2 g_wqt  [H_*D_/2];
static __device__ uint2 g_wkt  [H_*D_/2];
static __device__ uint2 g_wvt  [H_*D_/2];
static __device__ uint2 g_wot  [D_*H_/2];
static __device__ uint2 g_w1t  [H_*D_/2];
static __device__ uint2 g_w2t  [D_*H_/2];
// fp32 scratch
static __device__ float g_pe [S_*D_];
static __device__ float g_y  [T_*D_];
static __device__ float g_s  [B_*S_*S_];
static __device__ float g_ao [T_*D_];
static __device__ float g_y1 [T_*D_];
static __device__ float g_f  [T_*D_];
static __device__ double g_part[B_*128*2];
static __device__ double g_stats[B_*2];

// ------------------------------------------------------------- helpers ------
__device__ __forceinline__ uint32_t smem_u32(const void* p) {
    uint32_t a;
    asm("{ .reg .u64 t; cvta.to.shared.u64 t, %1; cvt.u32.u64 %0, t; }" : "=r"(a) : "l"(p));
    return a;
}
#define CP16(dst, src) \
    asm volatile("cp.async.cg.shared.global [%0], [%1], 16;" :: "r"(dst), "l"(src) : "memory")
#define CP_COMMIT() asm volatile("cp.async.commit_group;" ::: "memory")
#define CP_WAIT0()  asm volatile("cp.async.wait_group 0;" ::: "memory")

__device__ __forceinline__ uint2 split_pair(float2 v) {
    __half2 h = __float22half2_rn(v);
    float2 hf = __half22float2(h);
    __half2 l = __float22half2_rn(make_float2(v.x - hf.x, v.y - hf.y));
    uint2 o;
    o.x = *reinterpret_cast<uint32_t*>(&h);
    o.y = *reinterpret_cast<uint32_t*>(&l);
    return o;
}

// f32-accumulator HMMA (main term)
__device__ __forceinline__ void mma_f16(float* c, const uint32_t* a, const uint32_t* b) {
    asm volatile(
        "mma.sync.aligned.m16n8k16.row.col.f32.f16.f16.f32 "
        "{%0,%1,%2,%3}, {%4,%5,%6,%7}, {%8,%9}, {%0,%1,%2,%3};"
        : "+f"(c[0]), "+f"(c[1]), "+f"(c[2]), "+f"(c[3])
        : "r"(a[0]), "r"(a[1]), "r"(a[2]), "r"(a[3]), "r"(b[0]), "r"(b[1]));
}
// f16-accumulator HMMA (small correction term)
__device__ __forceinline__ void mma_f16acc(uint32_t* c, const uint32_t* a, const uint32_t* b) {
    asm volatile(
        "mma.sync.aligned.m16n8k16.row.col.f16.f16.f16.f16 "
        "{%0,%1}, {%2,%3,%4,%5}, {%6,%7}, {%0,%1};"
        : "+r"(c[0]), "+r"(c[1])
        : "r"(a[0]), "r"(a[1]), "r"(a[2]), "r"(a[3]), "r"(b[0]), "r"(b[1]));
}

__device__ __forceinline__ float gelu_exact(float v) {
    return 0.5f * v * (1.0f + erff(v * 0.70710678118654752f));
}

// smem tile: 128 rows x 16 uint2 (32 elems), padded row stride 20 uint2 = 160B
#define RSTR_B   160
#define TILE_B   (128 * RSTR_B)          // 20480
#define BUF_B    (2 * TILE_B)            // 40960 (A + B)
#define SMEM_SZ  (2 * BUF_B)             // 81920

// ---------------------------------------------------------------------------
// fp16-split GEMM: C[M,N] = A[M,K]*B[N,K]^T, inputs in split-pair format.
// 128x128 tile, Kstage=32, 256 thr (warps 2m x 4n), single-sync double buffer.
// PASSES: 2 = ah*bl (f16 acc) + ah*bh (f32 acc),  1 = ah*bh only
// BIASMODE: 0 none, 1 col bias[n], 2 row bias[m]. OUTSPLIT: C split-pair else f32
// ---------------------------------------------------------------------------
template<int PASSES, int BIASMODE, int OUTSPLIT, int GELU>
__global__ void __launch_bounds__(256, 2)
hgemm(const uint2* __restrict__ A, const uint2* __restrict__ B,
      const float* __restrict__ bias, void* __restrict__ Cout,
      int N_, int K_, ll sA, ll sB, ll sC) {
    extern __shared__ char smraw[];
    A += (ll)blockIdx.z * sA;
    B += (ll)blockIdx.z * sB;
    float* Cf = (float*)Cout + (OUTSPLIT ? 0 : (ll)blockIdx.z * sC);
    uint2* Cs = (uint2*)Cout + (OUTSPLIT ? (ll)blockIdx.z * sC : 0);

    const int tid = threadIdx.x, lane = tid & 31, wid = tid >> 5;
    const int wm = wid >> 2, wn = wid & 3;
    const int bm = blockIdx.y << 7, bn = blockIdx.x << 7;
    const int Kp = K_ >> 1;
    const uint32_t sbase = smem_u32(smraw);

    float acc[4][4][4];
    uint32_t accC[4][4][2];
#pragma unroll
    for (int mt = 0; mt < 4; mt++)
#pragma unroll
        for (int nt = 0; nt < 4; nt++) {
#pragma unroll
            for (int r = 0; r < 4; r++) acc[mt][nt][r] = 0.0f;
            accC[mt][nt][0] = 0u; accC[mt][nt][1] = 0u;
        }

    // loaders: i = tid + j*256 in [0,1024): row=i>>3, chunk=i&7 (16B = 2 uint2)
    int lrow[4], lc[4];
#pragma unroll
    for (int j = 0; j < 4; j++) { int i = tid + (j << 8); lrow[j] = i >> 3; lc[j] = i & 7; }

    const int nst = K_ >> 5;

    // prologue: stage 0 into buf 0
#pragma unroll
    for (int j = 0; j < 4; j++) {
        const uint2* ga = A + (size_t)(bm + lrow[j]) * Kp + (lc[j] << 1);
        const uint2* gb = B + (size_t)(bn + lrow[j]) * Kp + (lc[j] << 1);
        uint32_t so = sbase + lrow[j] * RSTR_B + (lc[j] << 4);
        CP16(so, ga);
        CP16(so + TILE_B, gb);
    }
    CP_COMMIT();

    for (int s = 0; s < nst; s++) {
        CP_WAIT0();
        __syncthreads();

        if (s + 1 < nst) {
            const int kp0 = (s + 1) << 4;
            const uint32_t boff = ((s + 1) & 1) * BUF_B;
#pragma unroll
            for (int j = 0; j < 4; j++) {
                const uint2* ga = A + (size_t)(bm + lrow[j]) * Kp + kp0 + (lc[j] << 1);
                const uint2* gb = B + (size_t)(bn + lrow[j]) * Kp + kp0 + (lc[j] << 1);
                uint32_t so = sbase + boff + lrow[j] * RSTR_B + (lc[j] << 4);
                CP16(so, ga);
                CP16(so + TILE_B, gb);
            }
            CP_COMMIT();
        }

        const uint32_t Asm = sbase + (s & 1) * BUF_B;
        const uint32_t Bsm = Asm + TILE_B;
        const int poff = (lane & 3) << 3;

#pragma unroll
        for (int kc = 0; kc < 2; kc++) {
            const uint32_t kb = (kc << 6) + poff;
            uint32_t bh[4][2], bl[4][2];
#pragma unroll
            for (int nt = 0; nt < 4; nt++) {
                uint32_t ba = Bsm + (wn * 32 + nt * 8 + (lane >> 2)) * RSTR_B + kb;
                asm volatile("ld.shared.v2.b32 {%0,%1}, [%2];" : "=r"(bh[nt][0]), "=r"(bl[nt][0]) : "r"(ba));
                asm volatile("ld.shared.v2.b32 {%0,%1}, [%2];" : "=r"(bh[nt][1]), "=r"(bl[nt][1]) : "r"(ba + 32));
            }
#pragma unroll
            for (int mt = 0; mt < 4; mt++) {
                uint32_t aa = Asm + (wm * 64 + mt * 16 + (lane >> 2)) * RSTR_B + kb;
                uint32_t ah[4], al[4];
                asm volatile("ld.shared.v2.b32 {%0,%1}, [%2];" : "=r"(ah[0]), "=r"(al[0]) : "r"(aa));
                asm volatile("ld.shared.v2.b32 {%0,%1}, [%2];" : "=r"(ah[1]), "=r"(al[1]) : "r"(aa + 8 * RSTR_B));
                asm volatile("ld.shared.v2.b32 {%0,%1}, [%2];" : "=r"(ah[2]), "=r"(al[2]) : "r"(aa + 32));
                asm volatile("ld.shared.v2.b32 {%0,%1}, [%2];" : "=r"(ah[3]), "=r"(al[3]) : "r"(aa + 8 * RSTR_B + 32));
#pragma unroll
                for (int nt = 0; nt < 4; nt++) {
                    if (PASSES >= 2) mma_f16acc(accC[mt][nt], ah, bl[nt]);
                    mma_f16(acc[mt][nt], ah, bh[nt]);
                }
            }
        }
    }

    __syncthreads();

    // epilogue: fold f16 corrections into f32 acc, then bias/gelu/store
#pragma unroll
    for (int mt = 0; mt < 4; mt++) {
        const int m0 = bm + wm * 64 + mt * 16 + (lane >> 2);
#pragma unroll
        for (int nt = 0; nt < 4; nt++) {
            float v00 = acc[mt][nt][0], v01 = acc[mt][nt][1];
            float v10 = acc[mt][nt][2], v11 = acc[mt][nt][3];
            if (PASSES >= 2) {
                __half2 c0 = *reinterpret_cast<__half2*>(&accC[mt][nt][0]);
                __half2 c1 = *reinterpret_cast<__half2*>(&accC[mt][nt][1]);
                float2 f0 = __half22float2(c0);
                float2 f1 = __half22float2(c1);
                v00 += f0.x; v01 += f0.y; v10 += f1.x; v11 += f1.y;
            }
            const int n0 = bn + wn * 32 + nt * 8 + ((lane & 3) << 1);
            if (BIASMODE == 1) {
                float2 bb = *(const float2*)&bias[n0];
                v00 += bb.x; v01 += bb.y; v10 += bb.x; v11 += bb.y;
            } else if (BIASMODE == 2) {
                float r0 = bias[m0], r1 = bias[m0 + 8];
                v00 += r0; v01 += r0; v10 += r1; v11 += r1;
            }
            if (GELU) {
                v00 = gelu_exact(v00); v01 = gelu_exact(v01);
                v10 = gelu_exact(v10); v11 = gelu_exact(v11);
            }
            if (OUTSPLIT) {
                Cs[((size_t)m0 * N_ + n0) >> 1]       = split_pair(make_float2(v00, v01));
                Cs[((size_t)(m0 + 8) * N_ + n0) >> 1] = split_pair(make_float2(v10, v11));
            } else {
                *(float2*)&Cf[(size_t)m0 * N_ + n0]       = make_float2(v00, v01);
                *(float2*)&Cf[(size_t)(m0 + 8) * N_ + n0] = make_float2(v10, v11);
            }
        }
    }
}

// ------------------------------------------------------------- aux kernels --
__global__ void pe_kernel(float* __restrict__ pe) {
    int i = blockIdx.x * blockDim.x + threadIdx.x;
    if (i >= S_ * D_) return;
    int s = i / D_, d = i % D_;
    double ang = (double)s * exp(-9.210340371976184 * ((double)d / (double)D_));
    float a = (float)fmod(ang, 6.283185307179586);
    pe[i] = (d & 1) ? cosf(a) : sinf(a);
}

__global__ void embed_kernel(const int* __restrict__ x, const float* __restrict__ emb,
                             const float* __restrict__ pe,
                             float* __restrict__ y, uint2* __restrict__ ysp) {
    int t = blockIdx.x;
    int s = t & (S_ - 1);
    ll row = x[t];
    const float* er = emb + row * (ll)D_;
    const float* pr = pe + (ll)s * D_;
    float* yr = y + (ll)t * D_;
    uint2* yp = ysp + (ll)t * (D_ / 2);
    for (int p = threadIdx.x; p < D_ / 2; p += blockDim.x) {
        float2 e = *(const float2*)(er + 2 * p);
        float2 q = *(const float2*)(pr + 2 * p);
        float2 v = make_float2(e.x + q.x, e.y + q.y);
        *(float2*)(yr + 2 * p) = v;
        yp[p] = split_pair(v);
    }
}

// transpose [R][C] fp32 -> [C][R] split-pair
__global__ void transpose_split(const float* __restrict__ in, uint2* __restrict__ out,
                                int R, int C) {
    __shared__ float t[32][33];
    int rb = blockIdx.y * 32, cb = blockIdx.x * 32;
#pragma unroll
    for (int i = 0; i < 32; i += 8)
        t[threadIdx.y + i][threadIdx.x] = in[(size_t)(rb + threadIdx.y + i) * C + cb + threadIdx.x];
    __syncthreads();
    int tid = threadIdx.y * 32 + threadIdx.x;
#pragma unroll
    for (int j = 0; j < 2; j++) {
        int pidx = tid + j * 256;
        int c = pidx >> 4, pr = pidx & 15;
        float2 v = make_float2(t[2 * pr][c], t[2 * pr + 1][c]);
        out[(size_t)(cb + c) * (R >> 1) + (rb >> 1) + pr] = split_pair(v);
    }
}

__global__ void softmax_split(float* __restrict__ s, uint2* __restrict__ sp) {
    float* p = s + (ll)blockIdx.x * S_;
    uint2* o = sp + (ll)blockIdx.x * (S_ / 2);
    __shared__ float red[256];
    int tid = threadIdx.x;
    float m = -1e30f;
    for (int i = tid; i < S_ / 2; i += 256) {
        float2 v = *(const float2*)(p + 2 * i);
        m = fmaxf(m, fmaxf(v.x, v.y));
    }
    red[tid] = m; __syncthreads();
    for (int off = 128; off > 0; off >>= 1) { if (tid < off) red[tid] = fmaxf(red[tid], red[tid + off]); __syncthreads(); }
    m = red[0]; __syncthreads();
    float sum = 0.f;
    for (int i = tid; i < S_ / 2; i += 256) {
        float2 v = *(const float2*)(p + 2 * i);
        v.x = expf(v.x - m); v.y = expf(v.y - m);
        *(float2*)(p + 2 * i) = v;
        sum += v.x + v.y;
    }
    red[tid] = sum; __syncthreads();
    for (int off = 128; off > 0; off >>= 1) { if (tid < off) red[tid] += red[tid + off]; __syncthreads(); }
    float inv = 1.0f / red[0];
    for (int i = tid; i < S_ / 2; i += 256) {
        float2 v = *(const float2*)(p + 2 * i);
        o[i] = split_pair(make_float2(v.x * inv, v.y * inv));
    }
}

#define LN_CH (S_*D_/128)   // 6144
__global__ void ln_part(const float* __restrict__ a, const float* __restrict__ r,
                        double* __restrict__ part) {
    int b = blockIdx.y, c = blockIdx.x, tid = threadIdx.x;
    size_t base = (size_t)b * (S_*D_) + (size_t)c * LN_CH;
    double s = 0.0, s2 = 0.0;
    for (int i = tid; i < LN_CH; i += 256) {
        float v = a[base + i] + r[base + i];
        s += v; s2 += (double)v * v;
    }
    __shared__ double m1[256], m2[256];
    m1[tid] = s; m2[tid] = s2; __syncthreads();
    for (int o = 128; o > 0; o >>= 1) {
        if (tid < o) { m1[tid] += m1[tid + o]; m2[tid] += m2[tid + o]; }
        __syncthreads();
    }
    if (tid == 0) { part[(b * 128 + c) * 2] = m1[0]; part[(b * 128 + c) * 2 + 1] = m2[0]; }
}
__global__ void ln_stats(const double* __restrict__ part, double* __restrict__ stats) {
    int b = blockIdx.x, tid = threadIdx.x;
    __shared__ double m1[128], m2[128];
    m1[tid] = part[(b * 128 + tid) * 2];
    m2[tid] = part[(b * 128 + tid) * 2 + 1];
    __syncthreads();
    for (int o = 64; o > 0; o >>= 1) {
        if (tid < o) { m1[tid] += m1[tid + o]; m2[tid] += m2[tid + o]; }
        __syncthreads();
    }
    if (tid == 0) {
        double mean = m1[0] / (S_*D_);
        double var  = m2[0] / (S_*D_) - mean * mean;
        stats[b * 2] = mean;
        stats[b * 2 + 1] = 1.0 / sqrt(var + 1e-5);
    }
}
template<int SPLIT>
__global__ void ln_apply(const float* __restrict__ a, const float* __restrict__ r,
                         const float* __restrict__ w, const float* __restrict__ bb,
                         const double* __restrict__ stats,
                         float* __restrict__ out, uint2* __restrict__ osp) {
    int b = blockIdx.y, c = blockIdx.x, tid = threadIdx.x;
    size_t base = (size_t)b * (S_*D_) + (size_t)c * LN_CH;
    size_t sl = (size_t)c * LN_CH;
    float mean = (float)stats[b * 2];
    float rstd = (float)stats[b * 2 + 1];
    for (int i = tid; i < LN_CH / 2; i += 256) {
        float2 av_ = *(const float2*)(a + base + 2 * i);
        float2 rv  = *(const float2*)(r + base + 2 * i);
        float2 wv  = *(const float2*)(w + sl + 2 * i);
        float2 bv  = *(const float2*)(bb + sl + 2 * i);
        float2 v;
        v.x = (av_.x + rv.x - mean) * rstd * wv.x + bv.x;
        v.y = (av_.y + rv.y - mean) * rstd * wv.y + bv.y;
        *(float2*)(out + base + 2 * i) = v;
        if (SPLIT) osp[(base >> 1) + i] = split_pair(v);
    }
}

// ------------------------------------------------------------------ launch --
extern "C" void kernel_launch(void* const* d_in, const int* in_sizes, int n_in,
                              void* d_out, int out_size) {
    const int*   x    = (const int*)  d_in[0];
    const float* emb  = (const float*)d_in[1];
    const float* Wq   = (const float*)d_in[2];
    const float* bq   = (const float*)d_in[3];
    const float* Wk   = (const float*)d_in[4];
    const float* bk   = (const float*)d_in[5];
    const float* Wv   = (const float*)d_in[6];
    const float* bv   = (const float*)d_in[7];
    const float* Wo   = (const float*)d_in[8];
    const float* bo   = (const float*)d_in[9];
    const float* W1   = (const float*)d_in[10];
    const float* b1   = (const float*)d_in[11];
    const float* W2   = (const float*)d_in[12];
    const float* b2   = (const float*)d_in[13];
    const float* ln1w = (const float*)d_in[14];
    const float* ln1b = (const float*)d_in[15];
    const float* ln2w = (const float*)d_in[16];
    const float* ln2b = (const float*)d_in[17];
    float* out = (float*)d_out;

    float *pe, *y, *s, *ao, *y1, *f;
    uint2 *ysp, *y1sp, *qsp, *ksp, *vTsp, *ssp, *avsp, *h1sp;
    uint2 *wqt, *wkt, *wvt, *wot, *w1t, *w2t;
    double *part, *stats;
    cudaGetSymbolAddress((void**)&pe,   g_pe);
    cudaGetSymbolAddress((void**)&y,    g_y);
    cudaGetSymbolAddress((void**)&s,    g_s);
    cudaGetSymbolAddress((void**)&ao,   g_ao);
    cudaGetSymbolAddress((void**)&y1,   g_y1);
    cudaGetSymbolAddress((void**)&f,    g_f);
    cudaGetSymbolAddress((void**)&ysp,  g_ysp);
    cudaGetSymbolAddress((void**)&y1sp, g_y1sp);
    cudaGetSymbolAddress((void**)&qsp,  g_qsp);
    cudaGetSymbolAddress((void**)&ksp,  g_ksp);
    cudaGetSymbolAddress((void**)&vTsp, g_vTsp);
    cudaGetSymbolAddress((void**)&ssp,  g_ssp);
    cudaGetSymbolAddress((void**)&avsp, g_avsp);
    cudaGetSymbolAddress((void**)&h1sp, g_h1sp);
    cudaGetSymbolAddress((void**)&wqt,  g_wqt);
    cudaGetSymbolAddress((void**)&wkt,  g_wkt);
    cudaGetSymbolAddress((void**)&wvt,  g_wvt);
    cudaGetSymbolAddress((void**)&wot,  g_wot);
    cudaGetSymbolAddress((void**)&w1t,  g_w1t);
    cudaGetSymbolAddress((void**)&w2t,  g_w2t);
    cudaGetSymbolAddress((void**)&part,  g_part);
    cudaGetSymbolAddress((void**)&stats, g_stats);

    cudaFuncSetAttribute(hgemm<2,1,1,0>, cudaFuncAttributeMaxDynamicSharedMemorySize, SMEM_SZ);
    cudaFuncSetAttribute(hgemm<1,2,1,0>, cudaFuncAttributeMaxDynamicSharedMemorySize, SMEM_SZ);
    cudaFuncSetAttribute(hgemm<1,0,0,0>, cudaFuncAttributeMaxDynamicSharedMemorySize, SMEM_SZ);
    cudaFuncSetAttribute(hgemm<1,0,1,0>, cudaFuncAttributeMaxDynamicSharedMemorySize, SMEM_SZ);
    cudaFuncSetAttribute(hgemm<1,1,0,0>, cudaFuncAttributeMaxDynamicSharedMemorySize, SMEM_SZ);
    cudaFuncSetAttribute(hgemm<1,1,1,0>, cudaFuncAttributeMaxDynamicSharedMemorySize, SMEM_SZ);
    cudaFuncSetAttribute(hgemm<2,1,0,1>, cudaFuncAttributeMaxDynamicSharedMemorySize, SMEM_SZ);

    // 0. weights -> transposed split-pair
    transpose_split<<<dim3(H_/32, D_/32), dim3(32,8)>>>(Wq, wqt, D_, H_);
    transpose_split<<<dim3(H_/32, D_/32), dim3(32,8)>>>(Wk, wkt, D_, H_);
    transpose_split<<<dim3(H_/32, D_/32), dim3(32,8)>>>(Wv, wvt, D_, H_);
    transpose_split<<<dim3(D_/32, H_/32), dim3(32,8)>>>(Wo, wot, H_, D_);
    transpose_split<<<dim3(H_/32, D_/32), dim3(32,8)>>>(W1, w1t, D_, H_);
    transpose_split<<<dim3(D_/32, H_/32), dim3(32,8)>>>(W2, w2t, H_, D_);

    // 1. embedding + PE (fp32 + split)
    pe_kernel<<<(S_*D_ + 255)/256, 256>>>(pe);
    embed_kernel<<<T_, 256>>>(x, emb, pe, y, ysp);

    // 2. q,k  (M=T, N=H, K=D) 2-pass (protects attention-score path), split out
    hgemm<2,1,1,0><<<dim3(H_/128, T_/128), 256, SMEM_SZ>>>(ysp, wqt, bq, qsp, H_, D_, 0, 0, 0);
    hgemm<2,1,1,0><<<dim3(H_/128, T_/128), 256, SMEM_SZ>>>(ysp, wkt, bk, ksp, H_, D_, 0, 0, 0);

    // 3. vT_b = wvt @ y_b^T + bv(row)  (M=H, N=S, K=D) 1-pass, split out
    hgemm<1,2,1,0><<<dim3(S_/128, H_/128, B_), 256, SMEM_SZ>>>(
        wvt, ysp, bv, vTsp, S_, D_, 0, (ll)S_*D_/2, (ll)H_*S_/2);

    // 4. scores_b = q_b @ k_b^T  (M=N=S, K=H) 1-pass, f32 out
    hgemm<1,0,0,0><<<dim3(S_/128, S_/128, B_), 256, SMEM_SZ>>>(
        qsp, ksp, nullptr, s, S_, H_, (ll)S_*H_/2, (ll)S_*H_/2, (ll)S_*S_);

    // 5. softmax -> split probs
    softmax_split<<<B_*S_, 256>>>(s, ssp);

    // 6. av_b = attn_b @ vT_b^T  (M=S, N=H, K=S) 1-pass, split out
    hgemm<1,0,1,0><<<dim3(H_/128, S_/128, B_), 256, SMEM_SZ>>>(
        ssp, vTsp, nullptr, avsp, H_, S_, (ll)S_*S_/2, (ll)H_*S_/2, (ll)S_*H_/2);

    // 7. ao = av @ wot^T + bo  (M=T, N=D, K=H) 1-pass (residual-diluted), f32 out
    hgemm<1,1,0,0><<<dim3(D_/128, T_/128), 256, SMEM_SZ>>>(avsp, wot, bo, ao, D_, H_, 0, 0, 0);

    // 8. LN1: y1 = LN(y + ao)  (fp32 + split)
    ln_part <<<dim3(128, B_), 256>>>(y, ao, part);
    ln_stats<<<B_, 128>>>(part, stats);
    ln_apply<1><<<dim3(128, B_), 256>>>(y, ao, ln1w, ln1b, stats, y1, y1sp);

    // 9. FFN: h1 = y1@W1+b1 1-pass (split);  f = gelu(h1@W2+b2) 2-pass (fp32)
    hgemm<1,1,1,0><<<dim3(H_/128, T_/128), 256, SMEM_SZ>>>(y1sp, w1t, b1, h1sp, H_, D_, 0, 0, 0);
    hgemm<2,1,0,1><<<dim3(D_/128, T_/128), 256, SMEM_SZ>>>(h1sp, w2t, b2, f, D_, H_, 0, 0, 0);

    // 10. LN2 -> out (fp32 only)
    ln_part <<<dim3(128, B_), 256>>>(y1, f, part);
    ln_stats<<<B_, 128>>>(part, stats);
    ln_apply<0><<<dim3(128, B_), 256>>>(y1, f, ln2w, ln2b, stats, out, nullptr);
}

// round 9
// speedup vs baseline: 4.8512x; 1.1413x over previous
#include <cuda_runtime.h>
#include <cuda_fp16.h>
#include <math.h>
#include <cstdint>

#define B_ 8
#define S_ 1024
#define D_ 768
#define H_ 3072
#define T_ (B_*S_)

typedef long long ll;

// ---------------- scratch: split-pair (uint2 = {half2 hi, half2 lo} / 2 elems)
static __device__ uint2 g_ysp  [T_*D_/2];
static __device__ uint2 g_y1sp [T_*D_/2];
static __device__ uint2 g_qsp  [T_*H_/2];
static __device__ uint2 g_ksp  [T_*H_/2];
static __device__ uint2 g_vTsp [B_*H_*S_/2];
static __device__ uint2 g_ssp  [B_*S_*S_/2];
static __device__ uint2 g_avsp [T_*H_/2];
static __device__ uint2 g_h1sp [T_*H_/2];
static __device__ uint2 g_wqt  [H_*D_/2];
static __device__ uint2 g_wkt  [H_*D_/2];
static __device__ uint2 g_wvt  [H_*D_/2];
static __device__ uint2 g_wot  [D_*H_/2];
static __device__ uint2 g_w1t  [H_*D_/2];
static __device__ uint2 g_w2t  [D_*H_/2];
// fp32 scratch
static __device__ float g_pe [S_*D_];
static __device__ float g_y  [T_*D_];
static __device__ float g_s  [B_*S_*S_];
static __device__ float g_ao [T_*D_];
static __device__ float g_y1 [T_*D_];
static __device__ float g_f  [T_*D_];
static __device__ double g_part[B_*128*2];
static __device__ double g_stats[B_*2];

// ------------------------------------------------------------- helpers ------
__device__ __forceinline__ uint32_t smem_u32(const void* p) {
    uint32_t a;
    asm("{ .reg .u64 t; cvta.to.shared.u64 t, %1; cvt.u32.u64 %0, t; }" : "=r"(a) : "l"(p));
    return a;
}
#define CP16(dst, src) \
    asm volatile("cp.async.cg.shared.global [%0], [%1], 16;" :: "r"(dst), "l"(src) : "memory")
#define CP_COMMIT() asm volatile("cp.async.commit_group;" ::: "memory")
#define CP_WAIT0()  asm volatile("cp.async.wait_group 0;" ::: "memory")

__device__ __forceinline__ uint2 split_pair(float2 v) {
    __half2 h = __float22half2_rn(v);
    float2 hf = __half22float2(h);
    __half2 l = __float22half2_rn(make_float2(v.x - hf.x, v.y - hf.y));
    uint2 o;
    o.x = *reinterpret_cast<uint32_t*>(&h);
    o.y = *reinterpret_cast<uint32_t*>(&l);
    return o;
}

// f32-accumulator HMMA (main term)
__device__ __forceinline__ void mma_f16(float* c, const uint32_t* a, const uint32_t* b) {
    asm volatile(
        "mma.sync.aligned.m16n8k16.row.col.f32.f16.f16.f32 "
        "{%0,%1,%2,%3}, {%4,%5,%6,%7}, {%8,%9}, {%0,%1,%2,%3};"
        : "+f"(c[0]), "+f"(c[1]), "+f"(c[2]), "+f"(c[3])
        : "r"(a[0]), "r"(a[1]), "r"(a[2]), "r"(a[3]), "r"(b[0]), "r"(b[1]));
}
// f16-accumulator HMMA (small correction term)
__device__ __forceinline__ void mma_f16acc(uint32_t* c, const uint32_t* a, const uint32_t* b) {
    asm volatile(
        "mma.sync.aligned.m16n8k16.row.col.f16.f16.f16.f16 "
        "{%0,%1}, {%2,%3,%4,%5}, {%6,%7}, {%0,%1};"
        : "+r"(c[0]), "+r"(c[1])
        : "r"(a[0]), "r"(a[1]), "r"(a[2]), "r"(a[3]), "r"(b[0]), "r"(b[1]));
}

__device__ __forceinline__ float gelu_exact(float v) {
    return 0.5f * v * (1.0f + erff(v * 0.70710678118654752f));
}

// smem tile: 128 rows x 16 uint2 (32 elems), padded row stride 20 uint2 = 160B
#define RSTR_B   160
#define TILE_B   (128 * RSTR_B)          // 20480
#define BUF_B    (2 * TILE_B)            // 40960 (A + B)
#define SMEM_SZ  (2 * BUF_B)             // 81920

// ---------------------------------------------------------------------------
// fp16-split GEMM: C[M,N] = A[M,K]*B[N,K]^T, inputs in split-pair format.
// 128x128 tile, Kstage=32, 256 thr (warps 2m x 4n), single-sync double buffer.
// PASSES: 2 = ah*bl (f16 acc) + ah*bh (f32 acc),  1 = ah*bh only
// BIASMODE: 0 none, 1 col bias[n], 2 row bias[m]. OUTSPLIT: C split-pair else f32
// ---------------------------------------------------------------------------
template<int PASSES, int BIASMODE, int OUTSPLIT, int GELU>
__global__ void __launch_bounds__(256, 2)
hgemm(const uint2* __restrict__ A, const uint2* __restrict__ B,
      const float* __restrict__ bias, void* __restrict__ Cout,
      int N_, int K_, ll sA, ll sB, ll sC) {
    extern __shared__ char smraw[];
    A += (ll)blockIdx.z * sA;
    B += (ll)blockIdx.z * sB;
    float* Cf = (float*)Cout + (OUTSPLIT ? 0 : (ll)blockIdx.z * sC);
    uint2* Cs = (uint2*)Cout + (OUTSPLIT ? (ll)blockIdx.z * sC : 0);

    const int tid = threadIdx.x, lane = tid & 31, wid = tid >> 5;
    const int wm = wid >> 2, wn = wid & 3;
    const int bm = blockIdx.y << 7, bn = blockIdx.x << 7;
    const int Kp = K_ >> 1;
    const uint32_t sbase = smem_u32(smraw);

    float acc[4][4][4];
    uint32_t accC[4][4][2];
#pragma unroll
    for (int mt = 0; mt < 4; mt++)
#pragma unroll
        for (int nt = 0; nt < 4; nt++) {
#pragma unroll
            for (int r = 0; r < 4; r++) acc[mt][nt][r] = 0.0f;
            accC[mt][nt][0] = 0u; accC[mt][nt][1] = 0u;
        }

    // loaders: i = tid + j*256 in [0,1024): row=i>>3, chunk=i&7 (16B = 2 uint2)
    int lrow[4], lc[4];
#pragma unroll
    for (int j = 0; j < 4; j++) { int i = tid + (j << 8); lrow[j] = i >> 3; lc[j] = i & 7; }

    const int nst = K_ >> 5;

    // prologue: stage 0 into buf 0
#pragma unroll
    for (int j = 0; j < 4; j++) {
        const uint2* ga = A + (size_t)(bm + lrow[j]) * Kp + (lc[j] << 1);
        const uint2* gb = B + (size_t)(bn + lrow[j]) * Kp + (lc[j] << 1);
        uint32_t so = sbase + lrow[j] * RSTR_B + (lc[j] << 4);
        CP16(so, ga);
        CP16(so + TILE_B, gb);
    }
    CP_COMMIT();

    for (int s = 0; s < nst; s++) {
        CP_WAIT0();
        __syncthreads();

        if (s + 1 < nst) {
            const int kp0 = (s + 1) << 4;
            const uint32_t boff = ((s + 1) & 1) * BUF_B;
#pragma unroll
            for (int j = 0; j < 4; j++) {
                const uint2* ga = A + (size_t)(bm + lrow[j]) * Kp + kp0 + (lc[j] << 1);
                const uint2* gb = B + (size_t)(bn + lrow[j]) * Kp + kp0 + (lc[j] << 1);
                uint32_t so = sbase + boff + lrow[j] * RSTR_B + (lc[j] << 4);
                CP16(so, ga);
                CP16(so + TILE_B, gb);
            }
            CP_COMMIT();
        }

        const uint32_t Asm = sbase + (s & 1) * BUF_B;
        const uint32_t Bsm = Asm + TILE_B;
        const int poff = (lane & 3) << 3;

#pragma unroll
        for (int kc = 0; kc < 2; kc++) {
            const uint32_t kb = (kc << 6) + poff;
            uint32_t bh[4][2], bl[4][2];
#pragma unroll
            for (int nt = 0; nt < 4; nt++) {
                uint32_t ba = Bsm + (wn * 32 + nt * 8 + (lane >> 2)) * RSTR_B + kb;
                asm volatile("ld.shared.v2.b32 {%0,%1}, [%2];" : "=r"(bh[nt][0]), "=r"(bl[nt][0]) : "r"(ba));
                asm volatile("ld.shared.v2.b32 {%0,%1}, [%2];" : "=r"(bh[nt][1]), "=r"(bl[nt][1]) : "r"(ba + 32));
            }
#pragma unroll
            for (int mt = 0; mt < 4; mt++) {
                uint32_t aa = Asm + (wm * 64 + mt * 16 + (lane >> 2)) * RSTR_B + kb;
                uint32_t ah[4], al[4];
                asm volatile("ld.shared.v2.b32 {%0,%1}, [%2];" : "=r"(ah[0]), "=r"(al[0]) : "r"(aa));
                asm volatile("ld.shared.v2.b32 {%0,%1}, [%2];" : "=r"(ah[1]), "=r"(al[1]) : "r"(aa + 8 * RSTR_B));
                asm volatile("ld.shared.v2.b32 {%0,%1}, [%2];" : "=r"(ah[2]), "=r"(al[2]) : "r"(aa + 32));
                asm volatile("ld.shared.v2.b32 {%0,%1}, [%2];" : "=r"(ah[3]), "=r"(al[3]) : "r"(aa + 8 * RSTR_B + 32));
#pragma unroll
                for (int nt = 0; nt < 4; nt++) {
                    if (PASSES >= 2) mma_f16acc(accC[mt][nt], ah, bl[nt]);
                    mma_f16(acc[mt][nt], ah, bh[nt]);
                }
            }
        }
    }

    __syncthreads();

    // epilogue: fold f16 corrections into f32 acc, then bias/gelu/store
#pragma unroll
    for (int mt = 0; mt < 4; mt++) {
        const int m0 = bm + wm * 64 + mt * 16 + (lane >> 2);
#pragma unroll
        for (int nt = 0; nt < 4; nt++) {
            float v00 = acc[mt][nt][0], v01 = acc[mt][nt][1];
            float v10 = acc[mt][nt][2], v11 = acc[mt][nt][3];
            if (PASSES >= 2) {
                __half2 c0 = *reinterpret_cast<__half2*>(&accC[mt][nt][0]);
                __half2 c1 = *reinterpret_cast<__half2*>(&accC[mt][nt][1]);
                float2 f0 = __half22float2(c0);
                float2 f1 = __half22float2(c1);
                v00 += f0.x; v01 += f0.y; v10 += f1.x; v11 += f1.y;
            }
            const int n0 = bn + wn * 32 + nt * 8 + ((lane & 3) << 1);
            if (BIASMODE == 1) {
                float2 bb = *(const float2*)&bias[n0];
                v00 += bb.x; v01 += bb.y; v10 += bb.x; v11 += bb.y;
            } else if (BIASMODE == 2) {
                float r0 = bias[m0], r1 = bias[m0 + 8];
                v00 += r0; v01 += r0; v10 += r1; v11 += r1;
            }
            if (GELU) {
                v00 = gelu_exact(v00); v01 = gelu_exact(v01);
                v10 = gelu_exact(v10); v11 = gelu_exact(v11);
            }
            if (OUTSPLIT) {
                Cs[((size_t)m0 * N_ + n0) >> 1]       = split_pair(make_float2(v00, v01));
                Cs[((size_t)(m0 + 8) * N_ + n0) >> 1] = split_pair(make_float2(v10, v11));
            } else {
                *(float2*)&Cf[(size_t)m0 * N_ + n0]       = make_float2(v00, v01);
                *(float2*)&Cf[(size_t)(m0 + 8) * N_ + n0] = make_float2(v10, v11);
            }
        }
    }
}

// ------------------------------------------------------------- aux kernels --
__global__ void pe_kernel(float* __restrict__ pe) {
    int i = blockIdx.x * blockDim.x + threadIdx.x;
    if (i >= S_ * D_) return;
    int s = i / D_, d = i % D_;
    double ang = (double)s * exp(-9.210340371976184 * ((double)d / (double)D_));
    float a = (float)fmod(ang, 6.283185307179586);
    pe[i] = (d & 1) ? cosf(a) : sinf(a);
}

__global__ void embed_kernel(const int* __restrict__ x, const float* __restrict__ emb,
                             const float* __restrict__ pe,
                             float* __restrict__ y, uint2* __restrict__ ysp) {
    int t = blockIdx.x;
    int s = t & (S_ - 1);
    ll row = x[t];
    const float* er = emb + row * (ll)D_;
    const float* pr = pe + (ll)s * D_;
    float* yr = y + (ll)t * D_;
    uint2* yp = ysp + (ll)t * (D_ / 2);
    for (int p = threadIdx.x; p < D_ / 2; p += blockDim.x) {
        float2 e = *(const float2*)(er + 2 * p);
        float2 q = *(const float2*)(pr + 2 * p);
        float2 v = make_float2(e.x + q.x, e.y + q.y);
        *(float2*)(yr + 2 * p) = v;
        yp[p] = split_pair(v);
    }
}

// transpose [R][C] fp32 -> [C][R] split-pair
__global__ void transpose_split(const float* __restrict__ in, uint2* __restrict__ out,
                                int R, int C) {
    __shared__ float t[32][33];
    int rb = blockIdx.y * 32, cb = blockIdx.x * 32;
#pragma unroll
    for (int i = 0; i < 32; i += 8)
        t[threadIdx.y + i][threadIdx.x] = in[(size_t)(rb + threadIdx.y + i) * C + cb + threadIdx.x];
    __syncthreads();
    int tid = threadIdx.y * 32 + threadIdx.x;
#pragma unroll
    for (int j = 0; j < 2; j++) {
        int pidx = tid + j * 256;
        int c = pidx >> 4, pr = pidx & 15;
        float2 v = make_float2(t[2 * pr][c], t[2 * pr + 1][c]);
        out[(size_t)(cb + c) * (R >> 1) + (rb >> 1) + pr] = split_pair(v);
    }
}

__global__ void softmax_split(float* __restrict__ s, uint2* __restrict__ sp) {
    float* p = s + (ll)blockIdx.x * S_;
    uint2* o = sp + (ll)blockIdx.x * (S_ / 2);
    __shared__ float red[256];
    int tid = threadIdx.x;
    float m = -1e30f;
    for (int i = tid; i < S_ / 2; i += 256) {
        float2 v = *(const float2*)(p + 2 * i);
        m = fmaxf(m, fmaxf(v.x, v.y));
    }
    red[tid] = m; __syncthreads();
    for (int off = 128; off > 0; off >>= 1) { if (tid < off) red[tid] = fmaxf(red[tid], red[tid + off]); __syncthreads(); }
    m = red[0]; __syncthreads();
    float sum = 0.f;
    for (int i = tid; i < S_ / 2; i += 256) {
        float2 v = *(const float2*)(p + 2 * i);
        v.x = expf(v.x - m); v.y = expf(v.y - m);
        *(float2*)(p + 2 * i) = v;
        sum += v.x + v.y;
    }
    red[tid] = sum; __syncthreads();
    for (int off = 128; off > 0; off >>= 1) { if (tid < off) red[tid] += red[tid + off]; __syncthreads(); }
    float inv = 1.0f / red[0];
    for (int i = tid; i < S_ / 2; i += 256) {
        float2 v = *(const float2*)(p + 2 * i);
        o[i] = split_pair(make_float2(v.x * inv, v.y * inv));
    }
}

#define LN_CH (S_*D_/128)   // 6144
__global__ void ln_part(const float* __restrict__ a, const float* __restrict__ r,
                        double* __restrict__ part) {
    int b = blockIdx.y, c = blockIdx.x, tid = threadIdx.x;
    size_t base = (size_t)b * (S_*D_) + (size_t)c * LN_CH;
    double s = 0.0, s2 = 0.0;
    for (int i = tid; i < LN_CH; i += 256) {
        float v = a[base + i] + r[base + i];
        s += v; s2 += (double)v * v;
    }
    __shared__ double m1[256], m2[256];
    m1[tid] = s; m2[tid] = s2; __syncthreads();
    for (int o = 128; o > 0; o >>= 1) {
        if (tid < o) { m1[tid] += m1[tid + o]; m2[tid] += m2[tid + o]; }
        __syncthreads();
    }
    if (tid == 0) { part[(b * 128 + c) * 2] = m1[0]; part[(b * 128 + c) * 2 + 1] = m2[0]; }
}
__global__ void ln_stats(const double* __restrict__ part, double* __restrict__ stats) {
    int b = blockIdx.x, tid = threadIdx.x;
    __shared__ double m1[128], m2[128];
    m1[tid] = part[(b * 128 + tid) * 2];
    m2[tid] = part[(b * 128 + tid) * 2 + 1];
    __syncthreads();
    for (int o = 64; o > 0; o >>= 1) {
        if (tid < o) { m1[tid] += m1[tid + o]; m2[tid] += m2[tid + o]; }
        __syncthreads();
    }
    if (tid == 0) {
        double mean = m1[0] / (S_*D_);
        double var  = m2[0] / (S_*D_) - mean * mean;
        stats[b * 2] = mean;
        stats[b * 2 + 1] = 1.0 / sqrt(var + 1e-5);
    }
}
template<int SPLIT>
__global__ void ln_apply(const float* __restrict__ a, const float* __restrict__ r,
                         const float* __restrict__ w, const float* __restrict__ bb,
                         const double* __restrict__ stats,
                         float* __restrict__ out, uint2* __restrict__ osp) {
    int b = blockIdx.y, c = blockIdx.x, tid = threadIdx.x;
    size_t base = (size_t)b * (S_*D_) + (size_t)c * LN_CH;
    size_t sl = (size_t)c * LN_CH;
    float mean = (float)stats[b * 2];
    float rstd = (float)stats[b * 2 + 1];
    for (int i = tid; i < LN_CH / 2; i += 256) {
        float2 av_ = *(const float2*)(a + base + 2 * i);
        float2 rv  = *(const float2*)(r + base + 2 * i);
        float2 wv  = *(const float2*)(w + sl + 2 * i);
        float2 bv  = *(const float2*)(bb + sl + 2 * i);
        float2 v;
        v.x = (av_.x + rv.x - mean) * rstd * wv.x + bv.x;
        v.y = (av_.y + rv.y - mean) * rstd * wv.y + bv.y;
        *(float2*)(out + base + 2 * i) = v;
        if (SPLIT) osp[(base >> 1) + i] = split_pair(v);
    }
}

// ------------------------------------------------------------------ launch --
extern "C" void kernel_launch(void* const* d_in, const int* in_sizes, int n_in,
                              void* d_out, int out_size) {
    const int*   x    = (const int*)  d_in[0];
    const float* emb  = (const float*)d_in[1];
    const float* Wq   = (const float*)d_in[2];
    const float* bq   = (const float*)d_in[3];
    const float* Wk   = (const float*)d_in[4];
    const float* bk   = (const float*)d_in[5];
    const float* Wv   = (const float*)d_in[6];
    const float* bv   = (const float*)d_in[7];
    const float* Wo   = (const float*)d_in[8];
    const float* bo   = (const float*)d_in[9];
    const float* W1   = (const float*)d_in[10];
    const float* b1   = (const float*)d_in[11];
    const float* W2   = (const float*)d_in[12];
    const float* b2   = (const float*)d_in[13];
    const float* ln1w = (const float*)d_in[14];
    const float* ln1b = (const float*)d_in[15];
    const float* ln2w = (const float*)d_in[16];
    const float* ln2b = (const float*)d_in[17];
    float* out = (float*)d_out;

    float *pe, *y, *s, *ao, *y1, *f;
    uint2 *ysp, *y1sp, *qsp, *ksp, *vTsp, *ssp, *avsp, *h1sp;
    uint2 *wqt, *wkt, *wvt, *wot, *w1t, *w2t;
    double *part, *stats;
    cudaGetSymbolAddress((void**)&pe,   g_pe);
    cudaGetSymbolAddress((void**)&y,    g_y);
    cudaGetSymbolAddress((void**)&s,    g_s);
    cudaGetSymbolAddress((void**)&ao,   g_ao);
    cudaGetSymbolAddress((void**)&y1,   g_y1);
    cudaGetSymbolAddress((void**)&f,    g_f);
    cudaGetSymbolAddress((void**)&ysp,  g_ysp);
    cudaGetSymbolAddress((void**)&y1sp, g_y1sp);
    cudaGetSymbolAddress((void**)&qsp,  g_qsp);
    cudaGetSymbolAddress((void**)&ksp,  g_ksp);
    cudaGetSymbolAddress((void**)&vTsp, g_vTsp);
    cudaGetSymbolAddress((void**)&ssp,  g_ssp);
    cudaGetSymbolAddress((void**)&avsp, g_avsp);
    cudaGetSymbolAddress((void**)&h1sp, g_h1sp);
    cudaGetSymbolAddress((void**)&wqt,  g_wqt);
    cudaGetSymbolAddress((void**)&wkt,  g_wkt);
    cudaGetSymbolAddress((void**)&wvt,  g_wvt);
    cudaGetSymbolAddress((void**)&wot,  g_wot);
    cudaGetSymbolAddress((void**)&w1t,  g_w1t);
    cudaGetSymbolAddress((void**)&w2t,  g_w2t);
    cudaGetSymbolAddress((void**)&part,  g_part);
    cudaGetSymbolAddress((void**)&stats, g_stats);

    cudaFuncSetAttribute(hgemm<1,1,1,0>, cudaFuncAttributeMaxDynamicSharedMemorySize, SMEM_SZ);
    cudaFuncSetAttribute(hgemm<1,2,1,0>, cudaFuncAttributeMaxDynamicSharedMemorySize, SMEM_SZ);
    cudaFuncSetAttribute(hgemm<1,0,0,0>, cudaFuncAttributeMaxDynamicSharedMemorySize, SMEM_SZ);
    cudaFuncSetAttribute(hgemm<1,0,1,0>, cudaFuncAttributeMaxDynamicSharedMemorySize, SMEM_SZ);
    cudaFuncSetAttribute(hgemm<1,1,0,0>, cudaFuncAttributeMaxDynamicSharedMemorySize, SMEM_SZ);
    cudaFuncSetAttribute(hgemm<1,1,0,1>, cudaFuncAttributeMaxDynamicSharedMemorySize, SMEM_SZ);

    // 0. weights -> transposed split-pair
    transpose_split<<<dim3(H_/32, D_/32), dim3(32,8)>>>(Wq, wqt, D_, H_);
    transpose_split<<<dim3(H_/32, D_/32), dim3(32,8)>>>(Wk, wkt, D_, H_);
    transpose_split<<<dim3(H_/32, D_/32), dim3(32,8)>>>(Wv, wvt, D_, H_);
    transpose_split<<<dim3(D_/32, H_/32), dim3(32,8)>>>(Wo, wot, H_, D_);
    transpose_split<<<dim3(H_/32, D_/32), dim3(32,8)>>>(W1, w1t, D_, H_);
    transpose_split<<<dim3(D_/32, H_/32), dim3(32,8)>>>(W2, w2t, H_, D_);

    // 1. embedding + PE (fp32 + split)
    pe_kernel<<<(S_*D_ + 255)/256, 256>>>(pe);
    embed_kernel<<<T_, 256>>>(x, emb, pe, y, ysp);

    // 2. q,k  (M=T, N=H, K=D) 1-pass, split out
    hgemm<1,1,1,0><<<dim3(H_/128, T_/128), 256, SMEM_SZ>>>(ysp, wqt, bq, qsp, H_, D_, 0, 0, 0);
    hgemm<1,1,1,0><<<dim3(H_/128, T_/128), 256, SMEM_SZ>>>(ysp, wkt, bk, ksp, H_, D_, 0, 0, 0);

    // 3. vT_b = wvt @ y_b^T + bv(row)  (M=H, N=S, K=D) 1-pass, split out
    hgemm<1,2,1,0><<<dim3(S_/128, H_/128, B_), 256, SMEM_SZ>>>(
        wvt, ysp, bv, vTsp, S_, D_, 0, (ll)S_*D_/2, (ll)H_*S_/2);

    // 4. scores_b = q_b @ k_b^T  (M=N=S, K=H) 1-pass, f32 out
    hgemm<1,0,0,0><<<dim3(S_/128, S_/128, B_), 256, SMEM_SZ>>>(
        qsp, ksp, nullptr, s, S_, H_, (ll)S_*H_/2, (ll)S_*H_/2, (ll)S_*S_);

    // 5. softmax -> split probs
    softmax_split<<<B_*S_, 256>>>(s, ssp);

    // 6. av_b = attn_b @ vT_b^T  (M=S, N=H, K=S) 1-pass, split out
    hgemm<1,0,1,0><<<dim3(H_/128, S_/128, B_), 256, SMEM_SZ>>>(
        ssp, vTsp, nullptr, avsp, H_, S_, (ll)S_*S_/2, (ll)H_*S_/2, (ll)S_*H_/2);

    // 7. ao = av @ wot^T + bo  (M=T, N=D, K=H) 1-pass, f32 out
    hgemm<1,1,0,0><<<dim3(D_/128, T_/128), 256, SMEM_SZ>>>(avsp, wot, bo, ao, D_, H_, 0, 0, 0);

    // 8. LN1: y1 = LN(y + ao)  (fp32 + split)
    ln_part <<<dim3(128, B_), 256>>>(y, ao, part);
    ln_stats<<<B_, 128>>>(part, stats);
    ln_apply<1><<<dim3(128, B_), 256>>>(y, ao, ln1w, ln1b, stats, y1, y1sp);

    // 9. FFN: h1 = y1@W1+b1 1-pass (split);  f = gelu(h1@W2+b2) 1-pass (fp32)
    hgemm<1,1,1,0><<<dim3(H_/128, T_/128), 256, SMEM_SZ>>>(y1sp, w1t, b1, h1sp, H_, D_, 0, 0, 0);
    hgemm<1,1,0,1><<<dim3(D_/128, T_/128), 256, SMEM_SZ>>>(h1sp, w2t, b2, f, D_, H_, 0, 0, 0);

    // 10. LN2 -> out (fp32 only)
    ln_part <<<dim3(128, B_), 256>>>(y1, f, part);
    ln_stats<<<B_, 128>>>(part, stats);
    ln_apply<0><<<dim3(128, B_), 256>>>(y1, f, ln2w, ln2b, stats, out, nullptr);
}

// round 10
// speedup vs baseline: 7.8837x; 1.6251x over previous
#include <cuda_runtime.h>
#include <cuda_fp16.h>
#include <math.h>
#include <cstdint>

#define B_ 8
#define S_ 1024
#define D_ 768
#define H_ 3072
#define T_ (B_*S_)

typedef long long ll;

// ---------------- scratch: fp16 operands -------------------------------------
static __device__ __half g_yh  [T_*D_];
static __device__ __half g_y1h [T_*D_];
static __device__ __half g_qh  [T_*H_];
static __device__ __half g_kh  [T_*H_];
static __device__ __half g_vTh [B_*H_*S_];
static __device__ __half g_sh  [B_*S_*S_];
static __device__ __half g_avh [T_*H_];
static __device__ __half g_h1h [T_*H_];
static __device__ __half g_wqt [H_*D_];
static __device__ __half g_wkt [H_*D_];
static __device__ __half g_wvt [H_*D_];
static __device__ __half g_wot [D_*H_];
static __device__ __half g_w1t [H_*D_];
static __device__ __half g_w2t [D_*H_];
// fp32 scratch
static __device__ float g_pe [S_*D_];
static __device__ float g_y  [T_*D_];
static __device__ float g_s  [B_*S_*S_];
static __device__ float g_ao [T_*D_];
static __device__ float g_y1 [T_*D_];
static __device__ float g_f  [T_*D_];
static __device__ double g_part[B_*128*2];
static __device__ double g_stats[B_*2];

// ------------------------------------------------------------- helpers ------
__device__ __forceinline__ uint32_t smem_u32(const void* p) {
    uint32_t a;
    asm("{ .reg .u64 t; cvta.to.shared.u64 t, %1; cvt.u32.u64 %0, t; }" : "=r"(a) : "l"(p));
    return a;
}
#define CP16(dst, src) \
    asm volatile("cp.async.cg.shared.global [%0], [%1], 16;" :: "r"(dst), "l"(src) : "memory")
#define CP_COMMIT() asm volatile("cp.async.commit_group;" ::: "memory")
#define CP_WAIT0()  asm volatile("cp.async.wait_group 0;" ::: "memory")

#define LDMX4(r0, r1, r2, r3, addr) \
    asm volatile("ldmatrix.sync.aligned.m8n8.x4.shared.b16 {%0,%1,%2,%3}, [%4];" \
        : "=r"(r0), "=r"(r1), "=r"(r2), "=r"(r3) : "r"(addr))

__device__ __forceinline__ void mma_f16(float* c, const uint32_t* a, const uint32_t* b) {
    asm volatile(
        "mma.sync.aligned.m16n8k16.row.col.f32.f16.f16.f32 "
        "{%0,%1,%2,%3}, {%4,%5,%6,%7}, {%8,%9}, {%0,%1,%2,%3};"
        : "+f"(c[0]), "+f"(c[1]), "+f"(c[2]), "+f"(c[3])
        : "r"(a[0]), "r"(a[1]), "r"(a[2]), "r"(a[3]), "r"(b[0]), "r"(b[1]));
}

__device__ __forceinline__ float gelu_exact(float v) {
    return 0.5f * v * (1.0f + erff(v * 0.70710678118654752f));
}

// SW128 swizzle on byte offsets (rows are exactly 128B)
#define SWZ(o) ((o) ^ (((o) >> 3) & 0x70))

// smem tile: 128 rows x 128 B (64 fp16), SW128, K-stage = 64
#define TILE_B   16384
#define BUF_B    (2 * TILE_B)           // A + B
#define SMEM_SZ  (2 * BUF_B)            // double buffer = 65536

// ---------------------------------------------------------------------------
// fp16 GEMM (1-pass): C[M,N] = A[M,K]*B[N,K]^T, fp16 in, f32 accum.
// 128x128 tile, Kstage=64, 256 thr (warps 2m x 4n), cp.async + ldmatrix.
// BIASMODE: 0 none, 1 col bias[n], 2 row bias[m]. OUTHALF: C fp16 else fp32.
// ---------------------------------------------------------------------------
template<int BIASMODE, int OUTHALF, int GELU>
__global__ void __launch_bounds__(256, 2)
hgemm(const __half* __restrict__ A, const __half* __restrict__ B,
      const float* __restrict__ bias, void* __restrict__ Cout,
      int N_, int K_, ll sA, ll sB, ll sC) {
    extern __shared__ char smraw[];
    A += (ll)blockIdx.z * sA;
    B += (ll)blockIdx.z * sB;
    float*  Cf = (float*) Cout + (OUTHALF ? 0 : (ll)blockIdx.z * sC);
    __half* Ch = (__half*)Cout + (OUTHALF ? (ll)blockIdx.z * sC : 0);

    const int tid = threadIdx.x, lane = tid & 31, wid = tid >> 5;
    const int wm = wid >> 2, wn = wid & 3;
    const int bm = blockIdx.y << 7, bn = blockIdx.x << 7;
    const uint32_t sbase = smem_u32(smraw);

    float acc[4][4][4];
#pragma unroll
    for (int mt = 0; mt < 4; mt++)
#pragma unroll
        for (int nt = 0; nt < 4; nt++)
#pragma unroll
            for (int r = 0; r < 4; r++) acc[mt][nt][r] = 0.0f;

    // loaders: f = tid + j*256 in [0,1024): row=f>>3, 16B chunk=f&7
    int lrow[4], lcc[4];
    uint32_t swo[4];
#pragma unroll
    for (int j = 0; j < 4; j++) {
        int f = tid + (j << 8);
        lrow[j] = f >> 3; lcc[j] = f & 7;
        swo[j] = SWZ((uint32_t)(lrow[j] * 128 + lcc[j] * 16));
    }

    // ldmatrix per-thread address components
    // A frag (m16k16, x4): lanes g0:m0-7/k0-7 g1:m8-15/k0-7 g2:m0-7/k8-15 g3:m8-15/k8-15
    const int l15  = lane & 15;
    const int aklo = (lane >> 4) << 4;       // 0 or 16 bytes
    uint32_t abase[4], axorм[4];
#pragma unroll
    for (int mt = 0; mt < 4; mt++) {
        int ar = wm * 64 + mt * 16 + l15;
        abase[mt] = (uint32_t)(ar * 128);
        axorм[mt] = (uint32_t)((ar & 7) << 4);
    }
    // B frag (two n8k16 per x4): g0:nt0/k0-7 g1:nt0/k8-15 g2:nt1/k0-7 g3:nt1/k8-15
    const int bg   = lane >> 3;
    const int bsel = bg >> 1;                // which nt of the pair
    const int bklo = (bg & 1) << 4;
    uint32_t bbase[2], bxorм[2];
#pragma unroll
    for (int p = 0; p < 2; p++) {
        int br = wn * 32 + (2 * p + bsel) * 8 + (lane & 7);
        bbase[p] = (uint32_t)(br * 128);
        bxorм[p] = (uint32_t)((br & 7) << 4);
    }

    const int nst = K_ >> 6;

    // prologue: stage 0 into buf 0
#pragma unroll
    for (int j = 0; j < 4; j++) {
        const __half* ga = A + (size_t)(bm + lrow[j]) * K_ + lcc[j] * 8;
        const __half* gb = B + (size_t)(bn + lrow[j]) * K_ + lcc[j] * 8;
        CP16(sbase + swo[j], ga);
        CP16(sbase + TILE_B + swo[j], gb);
    }
    CP_COMMIT();

    for (int s = 0; s < nst; s++) {
        CP_WAIT0();
        __syncthreads();

        if (s + 1 < nst) {
            const int k0 = (s + 1) << 6;
            const uint32_t boff = ((s + 1) & 1) * BUF_B;
#pragma unroll
            for (int j = 0; j < 4; j++) {
                const __half* ga = A + (size_t)(bm + lrow[j]) * K_ + k0 + lcc[j] * 8;
                const __half* gb = B + (size_t)(bn + lrow[j]) * K_ + k0 + lcc[j] * 8;
                CP16(sbase + boff + swo[j], ga);
                CP16(sbase + boff + TILE_B + swo[j], gb);
            }
            CP_COMMIT();
        }

        const uint32_t Asm = sbase + (s & 1) * BUF_B;
        const uint32_t Bsm = Asm + TILE_B;

#pragma unroll
        for (int kc = 0; kc < 4; kc++) {
            const uint32_t kbb = (uint32_t)(kc << 5);
            uint32_t bf[4][2];
#pragma unroll
            for (int p = 0; p < 2; p++) {
                uint32_t ad = Bsm + bbase[p] + ((kbb + bklo) ^ bxorм[p]);
                LDMX4(bf[2*p][0], bf[2*p][1], bf[2*p+1][0], bf[2*p+1][1], ad);
            }
#pragma unroll
            for (int mt = 0; mt < 4; mt++) {
                uint32_t ad = Asm + abase[mt] + ((kbb + aklo) ^ axorм[mt]);
                uint32_t af[4];
                LDMX4(af[0], af[1], af[2], af[3], ad);
#pragma unroll
                for (int nt = 0; nt < 4; nt++)
                    mma_f16(acc[mt][nt], af, bf[nt]);
            }
        }
    }

    __syncthreads();

    // epilogue
#pragma unroll
    for (int mt = 0; mt < 4; mt++) {
        const int m0 = bm + wm * 64 + mt * 16 + (lane >> 2);
#pragma unroll
        for (int nt = 0; nt < 4; nt++) {
            const int n0 = bn + wn * 32 + nt * 8 + ((lane & 3) << 1);
            float v00 = acc[mt][nt][0], v01 = acc[mt][nt][1];
            float v10 = acc[mt][nt][2], v11 = acc[mt][nt][3];
            if (BIASMODE == 1) {
                float2 bb = *(const float2*)&bias[n0];
                v00 += bb.x; v01 += bb.y; v10 += bb.x; v11 += bb.y;
            } else if (BIASMODE == 2) {
                float r0 = bias[m0], r1 = bias[m0 + 8];
                v00 += r0; v01 += r0; v10 += r1; v11 += r1;
            }
            if (GELU) {
                v00 = gelu_exact(v00); v01 = gelu_exact(v01);
                v10 = gelu_exact(v10); v11 = gelu_exact(v11);
            }
            if (OUTHALF) {
                *(__half2*)&Ch[(size_t)m0 * N_ + n0] =
                    __float22half2_rn(make_float2(v00, v01));
                *(__half2*)&Ch[(size_t)(m0 + 8) * N_ + n0] =
                    __float22half2_rn(make_float2(v10, v11));
            } else {
                *(float2*)&Cf[(size_t)m0 * N_ + n0]       = make_float2(v00, v01);
                *(float2*)&Cf[(size_t)(m0 + 8) * N_ + n0] = make_float2(v10, v11);
            }
        }
    }
}

// ------------------------------------------------------------- aux kernels --
__global__ void pe_kernel(float* __restrict__ pe) {
    int i = blockIdx.x * blockDim.x + threadIdx.x;
    if (i >= S_ * D_) return;
    int s = i / D_, d = i % D_;
    double ang = (double)s * exp(-9.210340371976184 * ((double)d / (double)D_));
    float a = (float)fmod(ang, 6.283185307179586);
    pe[i] = (d & 1) ? cosf(a) : sinf(a);
}

__global__ void embed_kernel(const int* __restrict__ x, const float* __restrict__ emb,
                             const float* __restrict__ pe,
                             float* __restrict__ y, __half* __restrict__ yh) {
    int t = blockIdx.x;
    int s = t & (S_ - 1);
    ll row = x[t];
    const float* er = emb + row * (ll)D_;
    const float* pr = pe + (ll)s * D_;
    float* yr = y + (ll)t * D_;
    __half* yhr = yh + (ll)t * D_;
    for (int p = threadIdx.x; p < D_ / 2; p += blockDim.x) {
        float2 e = *(const float2*)(er + 2 * p);
        float2 q = *(const float2*)(pr + 2 * p);
        float2 v = make_float2(e.x + q.x, e.y + q.y);
        *(float2*)(yr + 2 * p) = v;
        *(__half2*)(yhr + 2 * p) = __float22half2_rn(v);
    }
}

// transpose [R][C] fp32 -> [C][R] fp16
__global__ void transpose_half(const float* __restrict__ in, __half* __restrict__ out,
                               int R, int C) {
    __shared__ float t[32][33];
    int rb = blockIdx.y * 32, cb = blockIdx.x * 32;
#pragma unroll
    for (int i = 0; i < 32; i += 8)
        t[threadIdx.y + i][threadIdx.x] = in[(size_t)(rb + threadIdx.y + i) * C + cb + threadIdx.x];
    __syncthreads();
    int tid = threadIdx.y * 32 + threadIdx.x;
#pragma unroll
    for (int j = 0; j < 2; j++) {
        int pidx = tid + j * 256;
        int c = pidx >> 4, pr = pidx & 15;
        float2 v = make_float2(t[2 * pr][c], t[2 * pr + 1][c]);
        *(__half2*)&out[(size_t)(cb + c) * R + rb + 2 * pr] = __float22half2_rn(v);
    }
}

__global__ void softmax_half(float* __restrict__ s, __half* __restrict__ sp) {
    float* p = s + (ll)blockIdx.x * S_;
    __half* o = sp + (ll)blockIdx.x * S_;
    __shared__ float red[256];
    int tid = threadIdx.x;
    float m = -1e30f;
    for (int i = tid; i < S_ / 2; i += 256) {
        float2 v = *(const float2*)(p + 2 * i);
        m = fmaxf(m, fmaxf(v.x, v.y));
    }
    red[tid] = m; __syncthreads();
    for (int off = 128; off > 0; off >>= 1) { if (tid < off) red[tid] = fmaxf(red[tid], red[tid + off]); __syncthreads(); }
    m = red[0]; __syncthreads();
    float sum = 0.f;
    for (int i = tid; i < S_ / 2; i += 256) {
        float2 v = *(const float2*)(p + 2 * i);
        v.x = expf(v.x - m); v.y = expf(v.y - m);
        *(float2*)(p + 2 * i) = v;
        sum += v.x + v.y;
    }
    red[tid] = sum; __syncthreads();
    for (int off = 128; off > 0; off >>= 1) { if (tid < off) red[tid] += red[tid + off]; __syncthreads(); }
    float inv = 1.0f / red[0];
    for (int i = tid; i < S_ / 2; i += 256) {
        float2 v = *(const float2*)(p + 2 * i);
        *(__half2*)(o + 2 * i) = __float22half2_rn(make_float2(v.x * inv, v.y * inv));
    }
}

#define LN_CH (S_*D_/128)   // 6144
__global__ void ln_part(const float* __restrict__ a, const float* __restrict__ r,
                        double* __restrict__ part) {
    int b = blockIdx.y, c = blockIdx.x, tid = threadIdx.x;
    size_t base = (size_t)b * (S_*D_) + (size_t)c * LN_CH;
    double s = 0.0, s2 = 0.0;
    for (int i = tid; i < LN_CH; i += 256) {
        float v = a[base + i] + r[base + i];
        s += v; s2 += (double)v * v;
    }
    __shared__ double m1[256], m2[256];
    m1[tid] = s; m2[tid] = s2; __syncthreads();
    for (int o = 128; o > 0; o >>= 1) {
        if (tid < o) { m1[tid] += m1[tid + o]; m2[tid] += m2[tid + o]; }
        __syncthreads();
    }
    if (tid == 0) { part[(b * 128 + c) * 2] = m1[0]; part[(b * 128 + c) * 2 + 1] = m2[0]; }
}
__global__ void ln_stats(const double* __restrict__ part, double* __restrict__ stats) {
    int b = blockIdx.x, tid = threadIdx.x;
    __shared__ double m1[128], m2[128];
    m1[tid] = part[(b * 128 + tid) * 2];
    m2[tid] = part[(b * 128 + tid) * 2 + 1];
    __syncthreads();
    for (int o = 64; o > 0; o >>= 1) {
        if (tid < o) { m1[tid] += m1[tid + o]; m2[tid] += m2[tid + o]; }
        __syncthreads();
    }
    if (tid == 0) {
        double mean = m1[0] / (S_*D_);
        double var  = m2[0] / (S_*D_) - mean * mean;
        stats[b * 2] = mean;
        stats[b * 2 + 1] = 1.0 / sqrt(var + 1e-5);
    }
}
template<int HALFOUT>
__global__ void ln_apply(const float* __restrict__ a, const float* __restrict__ r,
                         const float* __restrict__ w, const float* __restrict__ bb,
                         const double* __restrict__ stats,
                         float* __restrict__ out, __half* __restrict__ oh) {
    int b = blockIdx.y, c = blockIdx.x, tid = threadIdx.x;
    size_t base = (size_t)b * (S_*D_) + (size_t)c * LN_CH;
    size_t sl = (size_t)c * LN_CH;
    float mean = (float)stats[b * 2];
    float rstd = (float)stats[b * 2 + 1];
    for (int i = tid; i < LN_CH / 2; i += 256) {
        float2 av_ = *(const float2*)(a + base + 2 * i);
        float2 rv  = *(const float2*)(r + base + 2 * i);
        float2 wv  = *(const float2*)(w + sl + 2 * i);
        float2 bv  = *(const float2*)(bb + sl + 2 * i);
        float2 v;
        v.x = (av_.x + rv.x - mean) * rstd * wv.x + bv.x;
        v.y = (av_.y + rv.y - mean) * rstd * wv.y + bv.y;
        *(float2*)(out + base + 2 * i) = v;
        if (HALFOUT) *(__half2*)(oh + base + 2 * i) = __float22half2_rn(v);
    }
}

// ------------------------------------------------------------------ launch --
extern "C" void kernel_launch(void* const* d_in, const int* in_sizes, int n_in,
                              void* d_out, int out_size) {
    const int*   x    = (const int*)  d_in[0];
    const float* emb  = (const float*)d_in[1];
    const float* Wq   = (const float*)d_in[2];
    const float* bq   = (const float*)d_in[3];
    const float* Wk   = (const float*)d_in[4];
    const float* bk   = (const float*)d_in[5];
    const float* Wv   = (const float*)d_in[6];
    const float* bv   = (const float*)d_in[7];
    const float* Wo   = (const float*)d_in[8];
    const float* bo   = (const float*)d_in[9];
    const float* W1   = (const float*)d_in[10];
    const float* b1   = (const float*)d_in[11];
    const float* W2   = (const float*)d_in[12];
    const float* b2   = (const float*)d_in[13];
    const float* ln1w = (const float*)d_in[14];
    const float* ln1b = (const float*)d_in[15];
    const float* ln2w = (const float*)d_in[16];
    const float* ln2b = (const float*)d_in[17];
    float* out = (float*)d_out;

    float *pe, *y, *s, *ao, *y1, *f;
    __half *yh, *y1h, *qh, *kh, *vTh, *sh, *avh, *h1h;
    __half *wqt, *wkt, *wvt, *wot, *w1t, *w2t;
    double *part, *stats;
    cudaGetSymbolAddress((void**)&pe,   g_pe);
    cudaGetSymbolAddress((void**)&y,    g_y);
    cudaGetSymbolAddress((void**)&s,    g_s);
    cudaGetSymbolAddress((void**)&ao,   g_ao);
    cudaGetSymbolAddress((void**)&y1,   g_y1);
    cudaGetSymbolAddress((void**)&f,    g_f);
    cudaGetSymbolAddress((void**)&yh,   g_yh);
    cudaGetSymbolAddress((void**)&y1h,  g_y1h);
    cudaGetSymbolAddress((void**)&qh,   g_qh);
    cudaGetSymbolAddress((void**)&kh,   g_kh);
    cudaGetSymbolAddress((void**)&vTh,  g_vTh);
    cudaGetSymbolAddress((void**)&sh,   g_sh);
    cudaGetSymbolAddress((void**)&avh,  g_avh);
    cudaGetSymbolAddress((void**)&h1h,  g_h1h);
    cudaGetSymbolAddress((void**)&wqt,  g_wqt);
    cudaGetSymbolAddress((void**)&wkt,  g_wkt);
    cudaGetSymbolAddress((void**)&wvt,  g_wvt);
    cudaGetSymbolAddress((void**)&wot,  g_wot);
    cudaGetSymbolAddress((void**)&w1t,  g_w1t);
    cudaGetSymbolAddress((void**)&w2t,  g_w2t);
    cudaGetSymbolAddress((void**)&part,  g_part);
    cudaGetSymbolAddress((void**)&stats, g_stats);

    cudaFuncSetAttribute(hgemm<1,1,0>, cudaFuncAttributeMaxDynamicSharedMemorySize, SMEM_SZ);
    cudaFuncSetAttribute(hgemm<2,1,0>, cudaFuncAttributeMaxDynamicSharedMemorySize, SMEM_SZ);
    cudaFuncSetAttribute(hgemm<0,0,0>, cudaFuncAttributeMaxDynamicSharedMemorySize, SMEM_SZ);
    cudaFuncSetAttribute(hgemm<0,1,0>, cudaFuncAttributeMaxDynamicSharedMemorySize, SMEM_SZ);
    cudaFuncSetAttribute(hgemm<1,0,0>, cudaFuncAttributeMaxDynamicSharedMemorySize, SMEM_SZ);
    cudaFuncSetAttribute(hgemm<1,0,1>, cudaFuncAttributeMaxDynamicSharedMemorySize, SMEM_SZ);

    // 0. weights -> transposed fp16
    transpose_half<<<dim3(H_/32, D_/32), dim3(32,8)>>>(Wq, wqt, D_, H_);
    transpose_half<<<dim3(H_/32, D_/32), dim3(32,8)>>>(Wk, wkt, D_, H_);
    transpose_half<<<dim3(H_/32, D_/32), dim3(32,8)>>>(Wv, wvt, D_, H_);
    transpose_half<<<dim3(D_/32, H_/32), dim3(32,8)>>>(Wo, wot, H_, D_);
    transpose_half<<<dim3(H_/32, D_/32), dim3(32,8)>>>(W1, w1t, D_, H_);
    transpose_half<<<dim3(D_/32, H_/32), dim3(32,8)>>>(W2, w2t, H_, D_);

    // 1. embedding + PE (fp32 + fp16)
    pe_kernel<<<(S_*D_ + 255)/256, 256>>>(pe);
    embed_kernel<<<T_, 256>>>(x, emb, pe, y, yh);

    // 2. q,k  (M=T, N=H, K=D) fp16 out
    hgemm<1,1,0><<<dim3(H_/128, T_/128), 256, SMEM_SZ>>>(yh, wqt, bq, qh, H_, D_, 0, 0, 0);
    hgemm<1,1,0><<<dim3(H_/128, T_/128), 256, SMEM_SZ>>>(yh, wkt, bk, kh, H_, D_, 0, 0, 0);

    // 3. vT_b = wvt @ y_b^T + bv(row)  (M=H, N=S, K=D) fp16 out
    hgemm<2,1,0><<<dim3(S_/128, H_/128, B_), 256, SMEM_SZ>>>(
        wvt, yh, bv, vTh, S_, D_, 0, (ll)S_*D_, (ll)H_*S_);

    // 4. scores_b = q_b @ k_b^T  (M=N=S, K=H) fp32 out
    hgemm<0,0,0><<<dim3(S_/128, S_/128, B_), 256, SMEM_SZ>>>(
        qh, kh, nullptr, s, S_, H_, (ll)S_*H_, (ll)S_*H_, (ll)S_*S_);

    // 5. softmax -> fp16 probs
    softmax_half<<<B_*S_, 256>>>(s, sh);

    // 6. av_b = attn_b @ vT_b^T  (M=S, N=H, K=S) fp16 out
    hgemm<0,1,0><<<dim3(H_/128, S_/128, B_), 256, SMEM_SZ>>>(
        sh, vTh, nullptr, avh, H_, S_, (ll)S_*S_, (ll)H_*S_, (ll)S_*H_);

    // 7. ao = av @ wot^T + bo  (M=T, N=D, K=H) fp32 out
    hgemm<1,0,0><<<dim3(D_/128, T_/128), 256, SMEM_SZ>>>(avh, wot, bo, ao, D_, H_, 0, 0, 0);

    // 8. LN1: y1 = LN(y + ao)  (fp32 + fp16)
    ln_part <<<dim3(128, B_), 256>>>(y, ao, part);
    ln_stats<<<B_, 128>>>(part, stats);
    ln_apply<1><<<dim3(128, B_), 256>>>(y, ao, ln1w, ln1b, stats, y1, y1h);

    // 9. FFN: h1 = y1@W1+b1 (fp16);  f = gelu(h1@W2+b2) (fp32)
    hgemm<1,1,0><<<dim3(H_/128, T_/128), 256, SMEM_SZ>>>(y1h, w1t, b1, h1h, H_, D_, 0, 0, 0);
    hgemm<1,0,1><<<dim3(D_/128, T_/128), 256, SMEM_SZ>>>(h1h, w2t, b2, f, D_, H_, 0, 0, 0);

    // 10. LN2 -> out (fp32 only)
    ln_part <<<dim3(128, B_), 256>>>(y1, f, part);
    ln_stats<<<B_, 128>>>(part, stats);
    ln_apply<0><<<dim3(128, B_), 256>>>(y1, f, ln2w, ln2b, stats, out, nullptr);
}